// round 3
// baseline (speedup 1.0000x reference)
#include <cuda_runtime.h>
#include <cuda_bf16.h>
#include <math.h>

// Problem dims
#define BATCH 512
#define ZD    64
#define HD    256
#define TT    64
#define PD    10000
#define G3    768          // 3*H
#define BT    32768        // BATCH*TT

// ---------------- device scratch (no allocations allowed) ----------------
__device__ __align__(256) float g_h0  [BATCH * HD];
__device__ __align__(256) float g_hA  [BATCH * HD];
__device__ __align__(256) float g_hB  [BATCH * HD];
__device__ __align__(256) float g_out0[(size_t)BT * HD];   // layer0 outputs (b*T+t, h)
__device__ __align__(256) float g_act [(size_t)BT * HD];   // layer1 outputs -> LN/ELU in place
__device__ __align__(256) float g_gx1 [(size_t)BT * G3];   // input gates for layer1 (~100MB)
__device__ __align__(256) float g_gx0 [G3];                // constant input gates for layer0

// ---------------- helpers ----------------
__device__ __forceinline__ unsigned long long splat2(float a) {
    unsigned long long r;
    asm("mov.b64 %0,{%1,%1};" : "=l"(r) : "f"(a));
    return r;
}
__device__ __forceinline__ void fma2(unsigned long long& d, unsigned long long a, unsigned long long b) {
    asm("fma.rn.f32x2 %0,%1,%2,%0;" : "+l"(d) : "l"(a), "l"(b));
}
__device__ __forceinline__ float2 unpack2(unsigned long long v) {
    float2 f;
    asm("mov.b64 {%0,%1},%2;" : "=f"(f.x), "=f"(f.y) : "l"(v));
    return f;
}
__device__ __forceinline__ float sigmoidf_(float x) { return 1.0f / (1.0f + expf(-x)); }
__device__ __forceinline__ float eluf_(float x)     { return x > 0.f ? x : expm1f(x); }

// ---------------- init kernels ----------------
// h0 = ELU(z @ W_init^T + b_init), (512,256), K=64
__global__ __launch_bounds__(256) void k_h0(const float* __restrict__ z,
                                            const float* __restrict__ Wi,
                                            const float* __restrict__ bi)
{
    __shared__ float zs[ZD];
    int b = blockIdx.x;
    int h = threadIdx.x;
    if (threadIdx.x < ZD) zs[threadIdx.x] = z[(size_t)b * ZD + threadIdx.x];
    __syncthreads();
    float s = bi[h];
    const float* wr = Wi + (size_t)h * ZD;
    #pragma unroll 16
    for (int k = 0; k < ZD; k++) s += zs[k] * wr[k];
    g_h0[(size_t)b * HD + h] = eluf_(s);
}

// gx0 = embedding @ W_ih0^T + b_ih0, 768 outputs, K=256
__global__ __launch_bounds__(256) void k_gx0(const float* __restrict__ emb,
                                             const float* __restrict__ Wih0,
                                             const float* __restrict__ bih0)
{
    __shared__ float es[HD];
    es[threadIdx.x] = emb[threadIdx.x];
    __syncthreads();
    int j = blockIdx.x * 256 + threadIdx.x;   // grid = 3 blocks
    float s = bih0[j];
    const float* wr = Wih0 + (size_t)j * HD;
    #pragma unroll 16
    for (int k = 0; k < HD; k++) s += es[k] * wr[k];
    g_gx0[j] = s;
}

// ---------------- GRU recurrence step ----------------
// Computes gh = h_in @ Whh^T + bhh for a 32b x 32h tile (x3 gates), then gate math.
// grid = (8 h-tiles, 16 b-tiles), 128 threads/block.
template<int LAYER>
__global__ __launch_bounds__(128) void gru_step(int hin_sel, int hout_sel,
                                                const float* __restrict__ Whh,
                                                const float* __restrict__ bhh,
                                                int t)
{
    const float* __restrict__ h_in  = (hin_sel == 2) ? g_h0 : (hin_sel ? g_hB : g_hA);
    float*       __restrict__ h_out = hout_sel ? g_hB : g_hA;
    float*       __restrict__ outbuf = (LAYER == 0) ? g_out0 : g_act;

    __shared__ __align__(16) float Hs[64][36];    // [k][b], padded
    __shared__ __align__(16) float Ws[64][100];   // [k][jj] jj = gate*32 + hloc

    const int tid = threadIdx.x;
    const int h0t = blockIdx.x * 32;
    const int b0t = blockIdx.y * 32;
    const int hl  = tid & 15;          // covers h pair 2*hl, 2*hl+1
    const int b4  = (tid >> 4) * 4;    // 4 consecutive b rows

    float acc[4][3][2];
    #pragma unroll
    for (int i = 0; i < 4; i++)
        #pragma unroll
        for (int g = 0; g < 3; g++) { acc[i][g][0] = 0.f; acc[i][g][1] = 0.f; }

    for (int kc = 0; kc < HD; kc += 64) {
        __syncthreads();
        // stage h tile: 32 rows x 64 k
        #pragma unroll
        for (int q = 0; q < 4; q++) {
            int l = tid + q * 128;
            int row = l >> 4, kq = l & 15;
            float4 v = *(const float4*)(h_in + (size_t)(b0t + row) * HD + kc + kq * 4);
            Hs[kq * 4 + 0][row] = v.x; Hs[kq * 4 + 1][row] = v.y;
            Hs[kq * 4 + 2][row] = v.z; Hs[kq * 4 + 3][row] = v.w;
        }
        // stage W tile: 96 rows x 64 k
        #pragma unroll
        for (int q = 0; q < 12; q++) {
            int l = tid + q * 128;
            int jj = l >> 4, kq = l & 15;
            int g = jj >> 5, hloc = jj & 31;
            int j = g * HD + h0t + hloc;
            float4 v = *(const float4*)(Whh + (size_t)j * HD + kc + kq * 4);
            Ws[kq * 4 + 0][jj] = v.x; Ws[kq * 4 + 1][jj] = v.y;
            Ws[kq * 4 + 2][jj] = v.z; Ws[kq * 4 + 3][jj] = v.w;
        }
        __syncthreads();
        #pragma unroll 16
        for (int k = 0; k < 64; k++) {
            float4 a = *(const float4*)&Hs[k][b4];
            float av[4] = {a.x, a.y, a.z, a.w};
            float2 w0 = *(const float2*)&Ws[k][ 0 + 2 * hl];
            float2 w1 = *(const float2*)&Ws[k][32 + 2 * hl];
            float2 w2 = *(const float2*)&Ws[k][64 + 2 * hl];
            #pragma unroll
            for (int i = 0; i < 4; i++) {
                acc[i][0][0] += av[i] * w0.x; acc[i][0][1] += av[i] * w0.y;
                acc[i][1][0] += av[i] * w1.x; acc[i][1][1] += av[i] * w1.y;
                acc[i][2][0] += av[i] * w2.x; acc[i][2][1] += av[i] * w2.y;
            }
        }
    }

    // gate math + writeback
    #pragma unroll
    for (int i = 0; i < 4; i++) {
        int b = b0t + b4 + i;
        #pragma unroll
        for (int d = 0; d < 2; d++) {
            int h = h0t + 2 * hl + d;
            float ghr = acc[i][0][d] + bhh[0 * HD + h];
            float ghz = acc[i][1][d] + bhh[1 * HD + h];
            float ghn = acc[i][2][d] + bhh[2 * HD + h];
            float gxr, gxz, gxn;
            if (LAYER == 0) {
                gxr = g_gx0[0 * HD + h]; gxz = g_gx0[1 * HD + h]; gxn = g_gx0[2 * HD + h];
            } else {
                size_t base = ((size_t)b * TT + t) * G3;
                gxr = g_gx1[base + 0 * HD + h];
                gxz = g_gx1[base + 1 * HD + h];
                gxn = g_gx1[base + 2 * HD + h];
            }
            float hp = h_in[(size_t)b * HD + h];
            float r = sigmoidf_(gxr + ghr);
            float u = sigmoidf_(gxz + ghz);
            float n = tanhf(gxn + r * ghn);
            float hn = (1.f - u) * n + u * hp;
            h_out[(size_t)b * HD + h] = hn;
            outbuf[((size_t)b * TT + t) * HD + h] = hn;
        }
    }
}

// ---------------- LayerNorm + ELU (in place on g_act) ----------------
__global__ __launch_bounds__(256) void ln_elu(const float* __restrict__ gamma,
                                              const float* __restrict__ beta)
{
    int warp = threadIdx.x >> 5, lane = threadIdx.x & 31;
    size_t row = (size_t)blockIdx.x * 8 + warp;     // grid = 4096 -> 32768 rows
    float* x = g_act + row * HD;
    float v[8];
    #pragma unroll
    for (int i = 0; i < 8; i++) v[i] = x[lane + 32 * i];
    float s = 0.f;
    #pragma unroll
    for (int i = 0; i < 8; i++) s += v[i];
    #pragma unroll
    for (int o = 16; o > 0; o >>= 1) s += __shfl_xor_sync(0xffffffffu, s, o);
    float mu = s * (1.0f / 256.0f);
    float q = 0.f;
    #pragma unroll
    for (int i = 0; i < 8; i++) { float dl = v[i] - mu; q += dl * dl; }
    #pragma unroll
    for (int o = 16; o > 0; o >>= 1) q += __shfl_xor_sync(0xffffffffu, q, o);
    float inv = rsqrtf(q * (1.0f / 256.0f) + 1e-5f);
    #pragma unroll
    for (int i = 0; i < 8; i++) {
        int h = lane + 32 * i;
        float y = (v[i] - mu) * inv * gamma[h] + beta[h];
        x[h] = eluf_(y);
    }
}

// ---------------- fp32x2 GEMM: C[m][n] = sum_k A[m][k]*B[n][k] + bias[n] ----------------
// 128x128 block tile, BK=16, 256 threads, 8x8 per thread, f32x2 packed FMA.
// Asel: 0 -> g_out0, 1 -> g_act.  Cin: nullptr -> g_gx1 else external (d_out).
__global__ __launch_bounds__(256) void gemm_nt_bias(int Asel,
                                                    const float* __restrict__ Bm,
                                                    const float* __restrict__ bias,
                                                    float* __restrict__ Cin,
                                                    int M, int N, int K)
{
    const float* __restrict__ A = Asel ? g_act : g_out0;
    float* __restrict__ C = Cin ? Cin : g_gx1;

    __shared__ __align__(16) float As[16][132];
    __shared__ __align__(16) float Bs[16][132];

    const int tid = threadIdx.x;
    const int m0 = blockIdx.y * 128;
    const int n0 = blockIdx.x * 128;
    const int tm = (tid >> 4) * 8;
    const int tn = (tid & 15) * 8;

    unsigned long long acc[8][4];
    #pragma unroll
    for (int i = 0; i < 8; i++)
        #pragma unroll
        for (int j = 0; j < 4; j++) acc[i][j] = 0ull;

    for (int kc = 0; kc < K; kc += 16) {
        __syncthreads();
        #pragma unroll
        for (int q = 0; q < 2; q++) {
            int l = tid + q * 256;
            int row = l >> 2, kq = l & 3;
            float4 v = *(const float4*)(A + (size_t)(m0 + row) * K + kc + kq * 4);
            As[kq * 4 + 0][row] = v.x; As[kq * 4 + 1][row] = v.y;
            As[kq * 4 + 2][row] = v.z; As[kq * 4 + 3][row] = v.w;
        }
        #pragma unroll
        for (int q = 0; q < 2; q++) {
            int l = tid + q * 256;
            int row = l >> 2, kq = l & 3;
            int n = n0 + row;
            float4 v = make_float4(0.f, 0.f, 0.f, 0.f);
            if (n < N) v = *(const float4*)(Bm + (size_t)n * K + kc + kq * 4);
            Bs[kq * 4 + 0][row] = v.x; Bs[kq * 4 + 1][row] = v.y;
            Bs[kq * 4 + 2][row] = v.z; Bs[kq * 4 + 3][row] = v.w;
        }
        __syncthreads();
        #pragma unroll
        for (int k = 0; k < 16; k++) {
            float4 a0 = *(const float4*)&As[k][tm];
            float4 a1 = *(const float4*)&As[k][tm + 4];
            ulonglong2 bp0 = *(const ulonglong2*)&Bs[k][tn];
            ulonglong2 bp1 = *(const ulonglong2*)&Bs[k][tn + 4];
            unsigned long long bb[4] = {bp0.x, bp0.y, bp1.x, bp1.y};
            float av[8] = {a0.x, a0.y, a0.z, a0.w, a1.x, a1.y, a1.z, a1.w};
            #pragma unroll
            for (int i = 0; i < 8; i++) {
                unsigned long long as = splat2(av[i]);
                #pragma unroll
                for (int j = 0; j < 4; j++) fma2(acc[i][j], as, bb[j]);
            }
        }
    }

    int nb = n0 + tn;
    if (nb < N) {   // N % 8 == 0 for both 768 and 10000, so whole group is in/out
        float bv[8];
        #pragma unroll
        for (int j = 0; j < 8; j++) bv[j] = bias[nb + j];
        #pragma unroll
        for (int i = 0; i < 8; i++) {
            float o[8];
            #pragma unroll
            for (int j = 0; j < 4; j++) {
                float2 p = unpack2(acc[i][j]);
                o[2 * j]     = p.x + bv[2 * j];
                o[2 * j + 1] = p.y + bv[2 * j + 1];
            }
            float4* dst = (float4*)(C + (size_t)(m0 + tm + i) * N + nb);
            dst[0] = make_float4(o[0], o[1], o[2], o[3]);
            dst[1] = make_float4(o[4], o[5], o[6], o[7]);
        }
    }
}

// ---------------- launch ----------------
extern "C" void kernel_launch(void* const* d_in, const int* in_sizes, int n_in,
                              void* d_out, int out_size)
{
    const float* z         = (const float*)d_in[0];
    const float* W_init    = (const float*)d_in[1];
    const float* b_init    = (const float*)d_in[2];
    const float* embedding = (const float*)d_in[3];
    const float* W_ih0     = (const float*)d_in[4];
    const float* W_hh0     = (const float*)d_in[5];
    // b_ih0 = d_in[6] folded into gx0
    const float* b_ih0     = (const float*)d_in[6];
    const float* b_hh0     = (const float*)d_in[7];
    const float* W_ih1     = (const float*)d_in[8];
    const float* W_hh1     = (const float*)d_in[9];
    const float* b_ih1     = (const float*)d_in[10];
    const float* b_hh1     = (const float*)d_in[11];
    const float* ln_g      = (const float*)d_in[12];
    const float* ln_b      = (const float*)d_in[13];
    const float* W_out     = (const float*)d_in[14];
    const float* b_out     = (const float*)d_in[15];
    float* out = (float*)d_out;

    (void)in_sizes; (void)n_in; (void)out_size;

    k_h0<<<BATCH, 256>>>(z, W_init, b_init);
    k_gx0<<<3, 256>>>(embedding, W_ih0, b_ih0);

    // layer 0 recurrence (input gates are the constant gx0 vector)
    for (int t = 0; t < TT; t++) {
        int hin = (t == 0) ? 2 : ((t - 1) & 1);
        int hout = t & 1;
        gru_step<0><<<dim3(8, 16), 128>>>(hin, hout, W_hh0, b_hh0, t);
    }

    // gx1 = out0 @ W_ih1^T + b_ih1  (32768 x 768, K=256)
    gemm_nt_bias<<<dim3(6, 256), 256>>>(0, W_ih1, b_ih1, nullptr, BT, G3, HD);

    // layer 1 recurrence (starts again from h0)
    for (int t = 0; t < TT; t++) {
        int hin = (t == 0) ? 2 : ((t - 1) & 1);
        int hout = t & 1;
        gru_step<1><<<dim3(8, 16), 128>>>(hin, hout, W_hh1, b_hh1, t);
    }

    ln_elu<<<BT / 8, 256>>>(ln_g, ln_b);

    // logits = act @ W_out^T + b_out  (32768 x 10000, K=256)
    gemm_nt_bias<<<dim3(79, 256), 256>>>(1, W_out, b_out, out, BT, PD, HD);
}

// round 4
// speedup vs baseline: 1.3922x; 1.3922x over previous
#include <cuda_runtime.h>
#include <cuda_bf16.h>
#include <math.h>

// Problem dims
#define BATCH 512
#define ZD    64
#define HD    256
#define TT    64
#define PD    10000
#define G3    768          // 3*H
#define BT    32768        // BATCH*TT

// ---------------- device scratch (no allocations allowed) ----------------
__device__ __align__(256) float g_h0  [BATCH * HD];
__device__ __align__(256) float g_hA  [BATCH * HD];
__device__ __align__(256) float g_hB  [BATCH * HD];
__device__ __align__(256) float g_out0[(size_t)BT * HD];   // layer0 outputs (b*T+t, h)
__device__ __align__(256) float g_act [(size_t)BT * HD];   // layer1 outputs -> LN/ELU in place
__device__ __align__(256) float g_gx1 [(size_t)BT * G3];   // input gates for layer1 (~100MB)
__device__ __align__(256) float g_gx0 [G3];                // constant input gates for layer0
__device__ int g_bar[2][16];                               // per-layer, per-btile step counters

// ---------------- helpers ----------------
__device__ __forceinline__ unsigned long long splat2(float a) {
    unsigned long long r;
    asm("mov.b64 %0,{%1,%1};" : "=l"(r) : "f"(a));
    return r;
}
__device__ __forceinline__ void fma2(unsigned long long& d, unsigned long long a, unsigned long long b) {
    asm("fma.rn.f32x2 %0,%1,%2,%0;" : "+l"(d) : "l"(a), "l"(b));
}
__device__ __forceinline__ float2 unpack2(unsigned long long v) {
    float2 f;
    asm("mov.b64 {%0,%1},%2;" : "=f"(f.x), "=f"(f.y) : "l"(v));
    return f;
}
__device__ __forceinline__ int ld_acq(const int* p) {
    int v;
    asm volatile("ld.global.acquire.gpu.b32 %0,[%1];" : "=r"(v) : "l"(p));
    return v;
}
__device__ __forceinline__ float sigmoidf_(float x) { return 1.0f / (1.0f + expf(-x)); }
__device__ __forceinline__ float eluf_(float x)     { return x > 0.f ? x : expm1f(x); }

// fused GRU cell for an h-pair
__device__ __forceinline__ float2 gru_cell2(float2 ar, float2 az, float2 an,
                                            float2 gr, float2 gz, float2 gn,
                                            float2 b0, float2 b1, float2 b2, float2 hp)
{
    float r0 = sigmoidf_(gr.x + ar.x + b0.x);
    float r1 = sigmoidf_(gr.y + ar.y + b0.y);
    float u0 = sigmoidf_(gz.x + az.x + b1.x);
    float u1 = sigmoidf_(gz.y + az.y + b1.y);
    float n0 = tanhf(gn.x + r0 * (an.x + b2.x));
    float n1 = tanhf(gn.y + r1 * (an.y + b2.y));
    return make_float2((1.f - u0) * n0 + u0 * hp.x,
                       (1.f - u1) * n1 + u1 * hp.y);
}

// ---------------- init kernels ----------------
__global__ void zero_bar() {
    if (threadIdx.x < 32) ((int*)g_bar)[threadIdx.x] = 0;
}

// h0 = ELU(z @ W_init^T + b_init), (512,256), K=64
__global__ __launch_bounds__(256) void k_h0(const float* __restrict__ z,
                                            const float* __restrict__ Wi,
                                            const float* __restrict__ bi)
{
    __shared__ float zs[ZD];
    int b = blockIdx.x;
    int h = threadIdx.x;
    if (threadIdx.x < ZD) zs[threadIdx.x] = z[(size_t)b * ZD + threadIdx.x];
    __syncthreads();
    float s = bi[h];
    const float* wr = Wi + (size_t)h * ZD;
    #pragma unroll 16
    for (int k = 0; k < ZD; k++) s += zs[k] * wr[k];
    g_h0[(size_t)b * HD + h] = eluf_(s);
}

// gx0 = embedding @ W_ih0^T + b_ih0, 768 outputs, K=256
__global__ __launch_bounds__(256) void k_gx0(const float* __restrict__ emb,
                                             const float* __restrict__ Wih0,
                                             const float* __restrict__ bih0)
{
    __shared__ float es[HD];
    es[threadIdx.x] = emb[threadIdx.x];
    __syncthreads();
    int j = blockIdx.x * 256 + threadIdx.x;   // grid = 3 blocks
    float s = bih0[j];
    const float* wr = Wih0 + (size_t)j * HD;
    #pragma unroll 16
    for (int k = 0; k < HD; k++) s += es[k] * wr[k];
    g_gx0[j] = s;
}

// ---------------- persistent GRU layer ----------------
// Grid (8,16): blockIdx.x = h-tile (32 h), blockIdx.y = b-tile (32 batch).
// Whh slice (96 x 256) resident in smem for all 64 steps.
// Per b-tile 8-block barrier per step via global atomic counters.
#define WS_STRIDE 98      // row stride for Ws[k][jj], jj = g*32 + hloc
#define HS_STRIDE 260     // row stride for Hs[row][k]
#define GRU_SMEM  ((256 * WS_STRIDE + 32 * HS_STRIDE) * 4)

template<int LAYER>
__global__ __launch_bounds__(256, 1) void gru_layer(const float* __restrict__ Whh,
                                                    const float* __restrict__ bhh)
{
    extern __shared__ float sm[];
    float* Ws = sm;                       // [256][WS_STRIDE]
    float* Hs = sm + 256 * WS_STRIDE;     // [32][HS_STRIDE]

    const int tid = threadIdx.x;
    const int h0t = blockIdx.x * 32;
    const int bj  = blockIdx.y;
    const int b0t = bj * 32;
    const int hl  = tid & 15;             // h-pair 2*hl, 2*hl+1
    const int bg  = tid >> 4;             // b rows 2*bg, 2*bg+1
    const int r0  = 2 * bg, r1 = 2 * bg + 1;

    // stage weight slice, transposed to [k][jj]
    #pragma unroll
    for (int q = 0; q < 24; q++) {
        int l = tid + q * 256;
        int jj = l >> 6, kq = l & 63;
        int g = jj >> 5, hloc = jj & 31;
        float4 v = *(const float4*)(Whh + (size_t)(g * HD + h0t + hloc) * HD + 4 * kq);
        Ws[(4 * kq + 0) * WS_STRIDE + jj] = v.x;
        Ws[(4 * kq + 1) * WS_STRIDE + jj] = v.y;
        Ws[(4 * kq + 2) * WS_STRIDE + jj] = v.z;
        Ws[(4 * kq + 3) * WS_STRIDE + jj] = v.w;
    }

    // per-thread constants
    const float2 bh0 = *(const float2*)(bhh + 0 * HD + h0t + 2 * hl);
    const float2 bh1 = *(const float2*)(bhh + 1 * HD + h0t + 2 * hl);
    const float2 bh2 = *(const float2*)(bhh + 2 * HD + h0t + 2 * hl);
    float2 gx0r = make_float2(0.f, 0.f), gx0z = gx0r, gx0n = gx0r;
    if (LAYER == 0) {
        gx0r = *(const float2*)(g_gx0 + 0 * HD + h0t + 2 * hl);
        gx0z = *(const float2*)(g_gx0 + 1 * HD + h0t + 2 * hl);
        gx0n = *(const float2*)(g_gx0 + 2 * HD + h0t + 2 * hl);
    }
    __syncthreads();

    float* __restrict__ outbuf = (LAYER == 0) ? g_out0 : g_act;
    int* __restrict__ bar = &g_bar[LAYER][bj];

    for (int t = 0; t < TT; t++) {
        const float* h_in = (t == 0) ? g_h0 : ((t & 1) ? g_hA : g_hB);
        float* h_out = (t & 1) ? g_hB : g_hA;

        // stage h tile (bypass L1: buffers are rewritten within this kernel)
        #pragma unroll
        for (int q = 0; q < 8; q++) {
            int l = tid + q * 256;
            int row = l >> 6, kq = l & 63;
            float4 v = __ldcg((const float4*)(h_in + (size_t)(b0t + row) * HD + 4 * kq));
            *(float4*)&Hs[row * HS_STRIDE + 4 * kq] = v;
        }

        // prefetch layer-1 input gates for this step
        float2 gA0, gA1, gA2, gB0, gB1, gB2;
        if (LAYER == 1) {
            const float* pA = g_gx1 + ((size_t)(b0t + r0) * TT + t) * G3 + h0t + 2 * hl;
            const float* pB = g_gx1 + ((size_t)(b0t + r1) * TT + t) * G3 + h0t + 2 * hl;
            gA0 = *(const float2*)(pA);  gA1 = *(const float2*)(pA + HD);  gA2 = *(const float2*)(pA + 2 * HD);
            gB0 = *(const float2*)(pB);  gB1 = *(const float2*)(pB + HD);  gB2 = *(const float2*)(pB + 2 * HD);
        } else {
            gA0 = gB0 = gx0r; gA1 = gB1 = gx0z; gA2 = gB2 = gx0n;
        }
        __syncthreads();

        unsigned long long a00 = 0, a01 = 0, a02 = 0, a10 = 0, a11 = 0, a12 = 0;
        const float* hrow0 = &Hs[r0 * HS_STRIDE];
        const float* hrow1 = &Hs[r1 * HS_STRIDE];
        const float* wbase = &Ws[2 * hl];
        #pragma unroll 8
        for (int k = 0; k < HD; k++) {
            unsigned long long s0 = splat2(hrow0[k]);
            unsigned long long s1 = splat2(hrow1[k]);
            const float* wk = wbase + k * WS_STRIDE;
            unsigned long long w0 = *(const unsigned long long*)(wk);
            unsigned long long w1 = *(const unsigned long long*)(wk + 32);
            unsigned long long w2 = *(const unsigned long long*)(wk + 64);
            fma2(a00, s0, w0); fma2(a01, s0, w1); fma2(a02, s0, w2);
            fma2(a10, s1, w0); fma2(a11, s1, w1); fma2(a12, s1, w2);
        }

        // gate math + writeback, row r0
        {
            int b = b0t + r0;
            float2 hp = *(const float2*)&Hs[r0 * HS_STRIDE + h0t + 2 * hl];
            float2 o = gru_cell2(unpack2(a00), unpack2(a01), unpack2(a02),
                                 gA0, gA1, gA2, bh0, bh1, bh2, hp);
            *(float2*)(h_out + (size_t)b * HD + h0t + 2 * hl) = o;
            *(float2*)(outbuf + ((size_t)b * TT + t) * HD + h0t + 2 * hl) = o;
        }
        // row r1
        {
            int b = b0t + r1;
            float2 hp = *(const float2*)&Hs[r1 * HS_STRIDE + h0t + 2 * hl];
            float2 o = gru_cell2(unpack2(a10), unpack2(a11), unpack2(a12),
                                 gB0, gB1, gB2, bh0, bh1, bh2, hp);
            *(float2*)(h_out + (size_t)b * HD + h0t + 2 * hl) = o;
            *(float2*)(outbuf + ((size_t)b * TT + t) * HD + h0t + 2 * hl) = o;
        }

        // per-btile barrier (skip after last step)
        if (t < TT - 1) {
            __threadfence();
            __syncthreads();
            if (tid == 0) {
                atomicAdd(bar, 1);
                int target = 8 * (t + 1);
                while (ld_acq(bar) < target) { }
            }
            __syncthreads();
        }
    }
}

// ---------------- LayerNorm + ELU (in place on g_act) ----------------
__global__ __launch_bounds__(256) void ln_elu(const float* __restrict__ gamma,
                                              const float* __restrict__ beta)
{
    int warp = threadIdx.x >> 5, lane = threadIdx.x & 31;
    size_t row = (size_t)blockIdx.x * 8 + warp;     // grid = 4096 -> 32768 rows
    float* x = g_act + row * HD;
    float v[8];
    #pragma unroll
    for (int i = 0; i < 8; i++) v[i] = x[lane + 32 * i];
    float s = 0.f;
    #pragma unroll
    for (int i = 0; i < 8; i++) s += v[i];
    #pragma unroll
    for (int o = 16; o > 0; o >>= 1) s += __shfl_xor_sync(0xffffffffu, s, o);
    float mu = s * (1.0f / 256.0f);
    float q = 0.f;
    #pragma unroll
    for (int i = 0; i < 8; i++) { float dl = v[i] - mu; q += dl * dl; }
    #pragma unroll
    for (int o = 16; o > 0; o >>= 1) q += __shfl_xor_sync(0xffffffffu, q, o);
    float inv = rsqrtf(q * (1.0f / 256.0f) + 1e-5f);
    #pragma unroll
    for (int i = 0; i < 8; i++) {
        int h = lane + 32 * i;
        float y = (v[i] - mu) * inv * gamma[h] + beta[h];
        x[h] = eluf_(y);
    }
}

// ---------------- fp32x2 GEMM: C[m][n] = sum_k A[m][k]*B[n][k] + bias[n] ----------------
// 128x128 tile, BK=16, 256 threads, 8x8 per thread, duplicated-A smem (no splat MOVs).
__global__ __launch_bounds__(256) void gemm_nt_bias(int Asel,
                                                    const float* __restrict__ Bm,
                                                    const float* __restrict__ bias,
                                                    float* __restrict__ Cin,
                                                    int M, int N, int K)
{
    const float* __restrict__ A = Asel ? g_act : g_out0;
    float* __restrict__ C = Cin ? Cin : g_gx1;

    __shared__ __align__(16) float As[16 * 264];   // duplicated: [k][2m]
    __shared__ __align__(16) float Bs[16 * 132];

    const int tid = threadIdx.x;
    const int m0 = blockIdx.y * 128;
    const int n0 = blockIdx.x * 128;
    const int tm = (tid >> 4) * 8;
    const int tn = (tid & 15) * 8;

    unsigned long long acc[8][4];
    #pragma unroll
    for (int i = 0; i < 8; i++)
        #pragma unroll
        for (int j = 0; j < 4; j++) acc[i][j] = 0ull;

    for (int kc = 0; kc < K; kc += 16) {
        __syncthreads();
        #pragma unroll
        for (int q = 0; q < 2; q++) {
            int l = tid + q * 256;
            int row = l >> 2, kq = l & 3;
            float4 v = *(const float4*)(A + (size_t)(m0 + row) * K + kc + 4 * kq);
            *(unsigned long long*)&As[(4 * kq + 0) * 264 + 2 * row] = splat2(v.x);
            *(unsigned long long*)&As[(4 * kq + 1) * 264 + 2 * row] = splat2(v.y);
            *(unsigned long long*)&As[(4 * kq + 2) * 264 + 2 * row] = splat2(v.z);
            *(unsigned long long*)&As[(4 * kq + 3) * 264 + 2 * row] = splat2(v.w);
        }
        #pragma unroll
        for (int q = 0; q < 2; q++) {
            int l = tid + q * 256;
            int row = l >> 2, kq = l & 3;
            int n = n0 + row;
            float4 v = make_float4(0.f, 0.f, 0.f, 0.f);
            if (n < N) v = *(const float4*)(Bm + (size_t)n * K + kc + 4 * kq);
            Bs[(4 * kq + 0) * 132 + row] = v.x;
            Bs[(4 * kq + 1) * 132 + row] = v.y;
            Bs[(4 * kq + 2) * 132 + row] = v.z;
            Bs[(4 * kq + 3) * 132 + row] = v.w;
        }
        __syncthreads();
        #pragma unroll
        for (int k = 0; k < 16; k++) {
            ulonglong2 A0 = *(const ulonglong2*)&As[k * 264 + 2 * tm];
            ulonglong2 A1 = *(const ulonglong2*)&As[k * 264 + 2 * tm + 4];
            ulonglong2 A2 = *(const ulonglong2*)&As[k * 264 + 2 * tm + 8];
            ulonglong2 A3 = *(const ulonglong2*)&As[k * 264 + 2 * tm + 12];
            ulonglong2 bp0 = *(const ulonglong2*)&Bs[k * 132 + tn];
            ulonglong2 bp1 = *(const ulonglong2*)&Bs[k * 132 + tn + 4];
            unsigned long long aa[8] = {A0.x, A0.y, A1.x, A1.y, A2.x, A2.y, A3.x, A3.y};
            unsigned long long bb[4] = {bp0.x, bp0.y, bp1.x, bp1.y};
            #pragma unroll
            for (int i = 0; i < 8; i++)
                #pragma unroll
                for (int j = 0; j < 4; j++)
                    fma2(acc[i][j], aa[i], bb[j]);
        }
    }

    int nb = n0 + tn;
    if (nb < N) {
        float bv[8];
        #pragma unroll
        for (int j = 0; j < 8; j++) bv[j] = bias[nb + j];
        #pragma unroll
        for (int i = 0; i < 8; i++) {
            float o[8];
            #pragma unroll
            for (int j = 0; j < 4; j++) {
                float2 p = unpack2(acc[i][j]);
                o[2 * j]     = p.x + bv[2 * j];
                o[2 * j + 1] = p.y + bv[2 * j + 1];
            }
            float4* dst = (float4*)(C + (size_t)(m0 + tm + i) * N + nb);
            dst[0] = make_float4(o[0], o[1], o[2], o[3]);
            dst[1] = make_float4(o[4], o[5], o[6], o[7]);
        }
    }
}

// ---------------- launch ----------------
extern "C" void kernel_launch(void* const* d_in, const int* in_sizes, int n_in,
                              void* d_out, int out_size)
{
    const float* z         = (const float*)d_in[0];
    const float* W_init    = (const float*)d_in[1];
    const float* b_init    = (const float*)d_in[2];
    const float* embedding = (const float*)d_in[3];
    const float* W_ih0     = (const float*)d_in[4];
    const float* W_hh0     = (const float*)d_in[5];
    const float* b_ih0     = (const float*)d_in[6];
    const float* b_hh0     = (const float*)d_in[7];
    const float* W_ih1     = (const float*)d_in[8];
    const float* W_hh1     = (const float*)d_in[9];
    const float* b_ih1     = (const float*)d_in[10];
    const float* b_hh1     = (const float*)d_in[11];
    const float* ln_g      = (const float*)d_in[12];
    const float* ln_b      = (const float*)d_in[13];
    const float* W_out     = (const float*)d_in[14];
    const float* b_out     = (const float*)d_in[15];
    float* out = (float*)d_out;

    (void)in_sizes; (void)n_in; (void)out_size;

    static bool attr_done = false;
    if (!attr_done) {
        cudaFuncSetAttribute(gru_layer<0>, cudaFuncAttributeMaxDynamicSharedMemorySize, GRU_SMEM);
        cudaFuncSetAttribute(gru_layer<1>, cudaFuncAttributeMaxDynamicSharedMemorySize, GRU_SMEM);
        attr_done = true;
    }

    zero_bar<<<1, 32>>>();
    k_h0<<<BATCH, 256>>>(z, W_init, b_init);
    k_gx0<<<3, 256>>>(embedding, W_ih0, b_ih0);

    // layer 0 recurrence (constant input gates gx0), persistent kernel
    gru_layer<0><<<dim3(8, 16), 256, GRU_SMEM>>>(W_hh0, b_hh0);

    // gx1 = out0 @ W_ih1^T + b_ih1  (32768 x 768, K=256)
    gemm_nt_bias<<<dim3(6, 256), 256>>>(0, W_ih1, b_ih1, nullptr, BT, G3, HD);

    // layer 1 recurrence, persistent kernel
    gru_layer<1><<<dim3(8, 16), 256, GRU_SMEM>>>(W_hh1, b_hh1);

    ln_elu<<<BT / 8, 256>>>(ln_g, ln_b);

    // logits = act @ W_out^T + b_out  (32768 x 10000, K=256)
    gemm_nt_bias<<<dim3(79, 256), 256>>>(1, W_out, b_out, out, BT, PD, HD);
}

// round 9
// speedup vs baseline: 2.3764x; 1.7070x over previous
#include <cuda_runtime.h>
#include <cuda_bf16.h>
#include <math.h>
#include <stdint.h>

// Problem dims
#define BATCH 512
#define ZD    64
#define HD    256
#define TT    64
#define PD    10000
#define G3    768
#define BT    32768

// ---------------- device scratch ----------------
__device__ __align__(256) float g_h0[BATCH * HD];
__device__ __align__(256) float g_hA[BATCH * HD];
__device__ __align__(256) float g_hB[BATCH * HD];
__device__ __align__(256) __nv_bfloat16 g_out0_hi[(size_t)BT * HD];
__device__ __align__(256) __nv_bfloat16 g_out0_lo[(size_t)BT * HD];
__device__ __align__(256) float g_act[(size_t)BT * HD];
__device__ __align__(256) __nv_bfloat16 g_act_hi[(size_t)BT * HD];
__device__ __align__(256) __nv_bfloat16 g_act_lo[(size_t)BT * HD];
__device__ __align__(256) float g_gx1[(size_t)BT * G3];
__device__ __align__(256) float g_gx0[G3];
__device__ __align__(256) __nv_bfloat16 g_wih1_hi[G3 * HD];
__device__ __align__(256) __nv_bfloat16 g_wih1_lo[G3 * HD];
__device__ __align__(256) __nv_bfloat16 g_wout_hi[PD * HD];
__device__ __align__(256) __nv_bfloat16 g_wout_lo[PD * HD];
__device__ int g_bar[2][16];

// ---------------- generic helpers ----------------
__device__ __forceinline__ unsigned long long splat2(float a) {
    unsigned long long r;
    asm("mov.b64 %0,{%1,%1};" : "=l"(r) : "f"(a));
    return r;
}
__device__ __forceinline__ void fma2(unsigned long long& d, unsigned long long a, unsigned long long b) {
    asm("fma.rn.f32x2 %0,%1,%2,%0;" : "+l"(d) : "l"(a), "l"(b));
}
__device__ __forceinline__ float2 unpack2(unsigned long long v) {
    float2 f;
    asm("mov.b64 {%0,%1},%2;" : "=f"(f.x), "=f"(f.y) : "l"(v));
    return f;
}
__device__ __forceinline__ int ld_acq(const int* p) {
    int v;
    asm volatile("ld.global.acquire.gpu.b32 %0,[%1];" : "=r"(v) : "l"(p));
    return v;
}
__device__ __forceinline__ float sigmoidf_(float x) { return 1.0f / (1.0f + expf(-x)); }
__device__ __forceinline__ float eluf_(float x)     { return x > 0.f ? x : expm1f(x); }

// hi/lo split
__device__ __forceinline__ void split_hl(float x, __nv_bfloat16& h, __nv_bfloat16& l) {
    h = __float2bfloat16(x);
    l = __float2bfloat16(x - __bfloat162float(h));
}

__device__ __forceinline__ uint32_t s2u(const void* p) {
    uint32_t a;
    asm("{ .reg .u64 t; cvta.to.shared.u64 t, %1; cvt.u32.u64 %0, t; }" : "=r"(a) : "l"(p));
    return a;
}

// ---------------- mma.sync building blocks (sm_80-baseline, works on sm_103) ----------------
__device__ __forceinline__ void cp16(uint32_t dst, const void* src, int srcbytes) {
    asm volatile("cp.async.cg.shared.global [%0], [%1], 16, %2;"
                 :: "r"(dst), "l"(src), "r"(srcbytes) : "memory");
}
__device__ __forceinline__ void cp_commit() {
    asm volatile("cp.async.commit_group;" ::: "memory");
}
__device__ __forceinline__ void ldm_x4(uint32_t* r, uint32_t addr) {
    asm volatile("ldmatrix.sync.aligned.m8n8.x4.shared.b16 {%0,%1,%2,%3}, [%4];"
                 : "=r"(r[0]), "=r"(r[1]), "=r"(r[2]), "=r"(r[3]) : "r"(addr));
}
__device__ __forceinline__ void mma16816(float* d, const uint32_t* a, const uint32_t* b) {
    asm volatile("mma.sync.aligned.m16n8k16.row.col.f32.bf16.bf16.f32 "
                 "{%0,%1,%2,%3}, {%4,%5,%6,%7}, {%8,%9}, {%0,%1,%2,%3};"
                 : "+f"(d[0]), "+f"(d[1]), "+f"(d[2]), "+f"(d[3])
                 : "r"(a[0]), "r"(a[1]), "r"(a[2]), "r"(a[3]), "r"(b[0]), "r"(b[1]));
}

// fused GRU cell for an h-pair
__device__ __forceinline__ float2 gru_cell2(float2 ar, float2 az, float2 an,
                                            float2 gr, float2 gz, float2 gn,
                                            float2 b0, float2 b1, float2 b2, float2 hp)
{
    float r0 = sigmoidf_(gr.x + ar.x + b0.x);
    float r1 = sigmoidf_(gr.y + ar.y + b0.y);
    float u0 = sigmoidf_(gz.x + az.x + b1.x);
    float u1 = sigmoidf_(gz.y + az.y + b1.y);
    float n0 = tanhf(gn.x + r0 * (an.x + b2.x));
    float n1 = tanhf(gn.y + r1 * (an.y + b2.y));
    return make_float2((1.f - u0) * n0 + u0 * hp.x,
                       (1.f - u1) * n1 + u1 * hp.y);
}

// ---------------- init kernels ----------------
__global__ void zero_bar() {
    if (threadIdx.x < 32) ((int*)g_bar)[threadIdx.x] = 0;
}

__global__ __launch_bounds__(256) void k_h0(const float* __restrict__ z,
                                            const float* __restrict__ Wi,
                                            const float* __restrict__ bi)
{
    __shared__ float zs[ZD];
    int b = blockIdx.x;
    int h = threadIdx.x;
    if (threadIdx.x < ZD) zs[threadIdx.x] = z[(size_t)b * ZD + threadIdx.x];
    __syncthreads();
    float s = bi[h];
    const float* wr = Wi + (size_t)h * ZD;
    #pragma unroll 16
    for (int k = 0; k < ZD; k++) s += zs[k] * wr[k];
    g_h0[(size_t)b * HD + h] = eluf_(s);
}

__global__ __launch_bounds__(256) void k_gx0(const float* __restrict__ emb,
                                             const float* __restrict__ Wih0,
                                             const float* __restrict__ bih0)
{
    __shared__ float es[HD];
    es[threadIdx.x] = emb[threadIdx.x];
    __syncthreads();
    int j = blockIdx.x * 256 + threadIdx.x;
    float s = bih0[j];
    const float* wr = Wih0 + (size_t)j * HD;
    #pragma unroll 16
    for (int k = 0; k < HD; k++) s += es[k] * wr[k];
    g_gx0[j] = s;
}

// weight hi/lo splitter. dsel: 0 -> wih1, 1 -> wout. n4 = elems/4.
__global__ __launch_bounds__(256) void cvt_split(const float* __restrict__ src, int dsel, int n4)
{
    __nv_bfloat16* hi = dsel ? g_wout_hi : g_wih1_hi;
    __nv_bfloat16* lo = dsel ? g_wout_lo : g_wih1_lo;
    int i = blockIdx.x * 256 + threadIdx.x;
    if (i < n4) {
        float4 v = ((const float4*)src)[i];
        __nv_bfloat16 h0, h1, h2, h3, l0, l1, l2, l3;
        split_hl(v.x, h0, l0); split_hl(v.y, h1, l1);
        split_hl(v.z, h2, l2); split_hl(v.w, h3, l3);
        __nv_bfloat162 ha, hb, la, lb;
        ha.x = h0; ha.y = h1; hb.x = h2; hb.y = h3;
        la.x = l0; la.y = l1; lb.x = l2; lb.y = l3;
        ((__nv_bfloat162*)hi)[2 * i]     = ha;
        ((__nv_bfloat162*)hi)[2 * i + 1] = hb;
        ((__nv_bfloat162*)lo)[2 * i]     = la;
        ((__nv_bfloat162*)lo)[2 * i + 1] = lb;
    }
}

// ---------------- persistent GRU layer ----------------
#define WS_STRIDE 98
#define HS_STRIDE 260
#define GRU_SMEM  ((256 * WS_STRIDE + 32 * HS_STRIDE) * 4)

template<int LAYER>
__global__ __launch_bounds__(256, 1) void gru_layer(const float* __restrict__ Whh,
                                                    const float* __restrict__ bhh)
{
    extern __shared__ float sm[];
    float* Ws = sm;
    float* Hs = sm + 256 * WS_STRIDE;

    const int tid = threadIdx.x;
    const int h0t = blockIdx.x * 32;
    const int bj  = blockIdx.y;
    const int b0t = bj * 32;
    const int hl  = tid & 15;
    const int bg  = tid >> 4;
    const int r0  = 2 * bg, r1 = 2 * bg + 1;

    #pragma unroll
    for (int q = 0; q < 24; q++) {
        int l = tid + q * 256;
        int jj = l >> 6, kq = l & 63;
        int g = jj >> 5, hloc = jj & 31;
        float4 v = *(const float4*)(Whh + (size_t)(g * HD + h0t + hloc) * HD + 4 * kq);
        Ws[(4 * kq + 0) * WS_STRIDE + jj] = v.x;
        Ws[(4 * kq + 1) * WS_STRIDE + jj] = v.y;
        Ws[(4 * kq + 2) * WS_STRIDE + jj] = v.z;
        Ws[(4 * kq + 3) * WS_STRIDE + jj] = v.w;
    }

    const float2 bh0 = *(const float2*)(bhh + 0 * HD + h0t + 2 * hl);
    const float2 bh1 = *(const float2*)(bhh + 1 * HD + h0t + 2 * hl);
    const float2 bh2 = *(const float2*)(bhh + 2 * HD + h0t + 2 * hl);
    float2 gx0r = make_float2(0.f, 0.f), gx0z = gx0r, gx0n = gx0r;
    if (LAYER == 0) {
        gx0r = *(const float2*)(g_gx0 + 0 * HD + h0t + 2 * hl);
        gx0z = *(const float2*)(g_gx0 + 1 * HD + h0t + 2 * hl);
        gx0n = *(const float2*)(g_gx0 + 2 * HD + h0t + 2 * hl);
    }
    __syncthreads();

    int* __restrict__ bar = &g_bar[LAYER][bj];

    for (int t = 0; t < TT; t++) {
        const float* h_in = (t == 0) ? g_h0 : ((t & 1) ? g_hA : g_hB);
        float* h_out = (t & 1) ? g_hB : g_hA;

        #pragma unroll
        for (int q = 0; q < 8; q++) {
            int l = tid + q * 256;
            int row = l >> 6, kq = l & 63;
            float4 v = __ldcg((const float4*)(h_in + (size_t)(b0t + row) * HD + 4 * kq));
            *(float4*)&Hs[row * HS_STRIDE + 4 * kq] = v;
        }

        float2 gA0, gA1, gA2, gB0, gB1, gB2;
        if (LAYER == 1) {
            const float* pA = g_gx1 + ((size_t)(b0t + r0) * TT + t) * G3 + h0t + 2 * hl;
            const float* pB = g_gx1 + ((size_t)(b0t + r1) * TT + t) * G3 + h0t + 2 * hl;
            gA0 = *(const float2*)(pA);  gA1 = *(const float2*)(pA + HD);  gA2 = *(const float2*)(pA + 2 * HD);
            gB0 = *(const float2*)(pB);  gB1 = *(const float2*)(pB + HD);  gB2 = *(const float2*)(pB + 2 * HD);
        } else {
            gA0 = gB0 = gx0r; gA1 = gB1 = gx0z; gA2 = gB2 = gx0n;
        }
        __syncthreads();

        unsigned long long a00 = 0, a01 = 0, a02 = 0, a10 = 0, a11 = 0, a12 = 0;
        const float* hrow0 = &Hs[r0 * HS_STRIDE];
        const float* hrow1 = &Hs[r1 * HS_STRIDE];
        const float* wbase = &Ws[2 * hl];
        #pragma unroll 8
        for (int k = 0; k < HD; k++) {
            unsigned long long s0 = splat2(hrow0[k]);
            unsigned long long s1 = splat2(hrow1[k]);
            const float* wk = wbase + k * WS_STRIDE;
            unsigned long long w0 = *(const unsigned long long*)(wk);
            unsigned long long w1 = *(const unsigned long long*)(wk + 32);
            unsigned long long w2 = *(const unsigned long long*)(wk + 64);
            fma2(a00, s0, w0); fma2(a01, s0, w1); fma2(a02, s0, w2);
            fma2(a10, s1, w0); fma2(a11, s1, w1); fma2(a12, s1, w2);
        }

        #pragma unroll
        for (int half = 0; half < 2; half++) {
            int rr = half ? r1 : r0;
            int b = b0t + rr;
            float2 hp = *(const float2*)&Hs[rr * HS_STRIDE + h0t + 2 * hl];
            float2 o = half
                ? gru_cell2(unpack2(a10), unpack2(a11), unpack2(a12), gB0, gB1, gB2, bh0, bh1, bh2, hp)
                : gru_cell2(unpack2(a00), unpack2(a01), unpack2(a02), gA0, gA1, gA2, bh0, bh1, bh2, hp);
            *(float2*)(h_out + (size_t)b * HD + h0t + 2 * hl) = o;
            size_t p = ((size_t)b * TT + t) * HD + h0t + 2 * hl;
            if (LAYER == 0) {
                __nv_bfloat162 h2, l2;
                split_hl(o.x, h2.x, l2.x);
                split_hl(o.y, h2.y, l2.y);
                *(__nv_bfloat162*)(g_out0_hi + p) = h2;
                *(__nv_bfloat162*)(g_out0_lo + p) = l2;
            } else {
                *(float2*)(g_act + p) = o;
            }
        }

        if (t < TT - 1) {
            __threadfence();
            __syncthreads();
            if (tid == 0) {
                atomicAdd(bar, 1);
                int target = 8 * (t + 1);
                while (ld_acq(bar) < target) { }
            }
            __syncthreads();
        }
    }
}

// ---------------- LayerNorm + ELU -> bf16 hi/lo ----------------
__global__ __launch_bounds__(256) void ln_elu(const float* __restrict__ gamma,
                                              const float* __restrict__ beta)
{
    int warp = threadIdx.x >> 5, lane = threadIdx.x & 31;
    size_t row = (size_t)blockIdx.x * 8 + warp;
    const float* x = g_act + row * HD;
    float v[8];
    #pragma unroll
    for (int i = 0; i < 8; i++) v[i] = x[lane + 32 * i];
    float s = 0.f;
    #pragma unroll
    for (int i = 0; i < 8; i++) s += v[i];
    #pragma unroll
    for (int o = 16; o > 0; o >>= 1) s += __shfl_xor_sync(0xffffffffu, s, o);
    float mu = s * (1.0f / 256.0f);
    float q = 0.f;
    #pragma unroll
    for (int i = 0; i < 8; i++) { float dl = v[i] - mu; q += dl * dl; }
    #pragma unroll
    for (int o = 16; o > 0; o >>= 1) q += __shfl_xor_sync(0xffffffffu, q, o);
    float inv = rsqrtf(q * (1.0f / 256.0f) + 1e-5f);
    #pragma unroll
    for (int i = 0; i < 8; i++) {
        int h = lane + 32 * i;
        float y = eluf_((v[i] - mu) * inv * gamma[h] + beta[h]);
        __nv_bfloat16 hb, lb;
        split_hl(y, hb, lb);
        g_act_hi[row * HD + h] = hb;
        g_act_lo[row * HD + h] = lb;
    }
}

// ---------------- mma.sync bf16x3 GEMM ----------------
// C[m][n] = sum_k A[m][k]*B[n][k] + bias[n], logical K = 768 (3 phases x 256):
//   phase 0: Ahi x Bhi, phase 1: Alo x Bhi, phase 2: Ahi x Blo
// CTA tile 128x128, 8 warps (2m x 4n), each 64x32 via m16n8k16.
// 4-stage cp.async pipeline, K-chunk 32, padded 40-elem rows (conflict-free ldmatrix).
#define NCHUNK 24
#define ROWP 40                      // padded row stride (elems)
#define ASTG_B 0
#define BSTG_B (128 * ROWP * 2)      // 10240 bytes
#define STG_BYTES (2 * 128 * ROWP * 2)  // 20480
#define GEMM_SMEM (4 * STG_BYTES)       // 81920

__device__ __forceinline__ void ld_chunk(uint32_t smbase, int stage,
                                         const __nv_bfloat16* __restrict__ Ahi,
                                         const __nv_bfloat16* __restrict__ Alo,
                                         const __nv_bfloat16* __restrict__ Bhi,
                                         const __nv_bfloat16* __restrict__ Blo,
                                         int m0, int n0, int N, int c, int tid)
{
    if (c < NCHUNK) {
        int p = c >> 3, k0 = (c & 7) * 32;
        const __nv_bfloat16* A = (p == 1) ? Alo : Ahi;
        const __nv_bfloat16* B = (p == 2) ? Blo : Bhi;
        uint32_t stg = smbase + stage * STG_BYTES;
        #pragma unroll
        for (int q = 0; q < 2; q++) {
            int i = tid * 2 + q;             // 0..511
            int row = i >> 2, seg = i & 3;   // 128 rows x 4 segs of 8 elems
            uint32_t soff = (uint32_t)(row * ROWP + seg * 8) * 2;
            cp16(stg + ASTG_B + soff, A + (size_t)(m0 + row) * HD + k0 + seg * 8, 16);
            int n = n0 + row;
            const __nv_bfloat16* bsrc = B + (size_t)(n < N ? n : 0) * HD + k0 + seg * 8;
            cp16(stg + BSTG_B + soff, bsrc, n < N ? 16 : 0);
        }
    }
    cp_commit();   // always commit (possibly empty) to keep group counting uniform
}

// Asel: 0 -> g_out0 hi/lo, 1 -> g_act hi/lo. Bsel: 0 -> wih1, 1 -> wout.
// Cext: nullptr -> g_gx1.
__global__ __launch_bounds__(256, 1) void gemm_mma(int Asel, int Bsel,
                                                   const float* __restrict__ bias,
                                                   float* __restrict__ Cext, int N)
{
    extern __shared__ char smraw[];
    const uint32_t smb = s2u(smraw);

    const int tid = threadIdx.x, wid = tid >> 5, lane = tid & 31;
    const int n0 = blockIdx.x * 128;
    const int m0 = blockIdx.y * 128;
    const int mwarp = (wid & 1) * 64;
    const int nwarp = (wid >> 1) * 32;

    const __nv_bfloat16* Ahi = Asel ? g_act_hi : g_out0_hi;
    const __nv_bfloat16* Alo = Asel ? g_act_lo : g_out0_lo;
    const __nv_bfloat16* Bhi = Bsel ? g_wout_hi : g_wih1_hi;
    const __nv_bfloat16* Blo = Bsel ? g_wout_lo : g_wih1_lo;
    float* C = Cext ? Cext : g_gx1;

    // ldmatrix lane offsets (bytes, relative to stage base)
    uint32_t aoff[4], boff[2];
    {
        int arow = (lane & 15);
        int akc  = (lane >> 4) * 8;
        #pragma unroll
        for (int mf = 0; mf < 4; mf++)
            aoff[mf] = (uint32_t)(((mwarp + mf * 16 + arow) * ROWP + akc) * 2);
        int brow = (lane & 7) + ((lane >> 4) & 1) * 8;
        int bkc  = ((lane >> 3) & 1) * 8;
        #pragma unroll
        for (int nf2 = 0; nf2 < 2; nf2++)
            boff[nf2] = (uint32_t)(BSTG_B + ((nwarp + nf2 * 16 + brow) * ROWP + bkc) * 2);
    }

    // accumulators initialized with bias
    const int dr = lane >> 2;            // d-frag row within 16
    const int dc = (lane & 3) * 2;       // d-frag col pair
    float acc[4][4][4];
    #pragma unroll
    for (int nf = 0; nf < 4; nf++) {
        int n = n0 + nwarp + nf * 8 + dc;
        float b0 = (n < N) ? bias[n] : 0.f;
        float b1 = (n + 1 < N) ? bias[n + 1] : 0.f;
        #pragma unroll
        for (int mf = 0; mf < 4; mf++) {
            acc[mf][nf][0] = b0; acc[mf][nf][1] = b1;
            acc[mf][nf][2] = b0; acc[mf][nf][3] = b1;
        }
    }

    // prologue: chunks 0..2 into stages 0..2
    #pragma unroll
    for (int c = 0; c < 3; c++)
        ld_chunk(smb, c, Ahi, Alo, Bhi, Blo, m0, n0, N, c, tid);

    for (int c = 0; c < NCHUNK; c++) {
        asm volatile("cp.async.wait_group 2;" ::: "memory");
        __syncthreads();
        ld_chunk(smb, (c + 3) & 3, Ahi, Alo, Bhi, Blo, m0, n0, N, c + 3, tid);

        uint32_t stg = smb + (c & 3) * STG_BYTES;
        #pragma unroll
        for (int kk = 0; kk < 2; kk++) {
            uint32_t af[4][4], bf[2][4];
            #pragma unroll
            for (int mf = 0; mf < 4; mf++) ldm_x4(af[mf], stg + aoff[mf] + kk * 32);
            #pragma unroll
            for (int nf2 = 0; nf2 < 2; nf2++) ldm_x4(bf[nf2], stg + boff[nf2] + kk * 32);
            #pragma unroll
            for (int mf = 0; mf < 4; mf++)
                #pragma unroll
                for (int nf = 0; nf < 4; nf++)
                    mma16816(acc[mf][nf], af[mf], &bf[nf >> 1][(nf & 1) * 2]);
        }
        __syncthreads();
    }

    // epilogue: direct stores (float2 per d-pair)
    #pragma unroll
    for (int mf = 0; mf < 4; mf++) {
        int m = m0 + mwarp + mf * 16 + dr;
        #pragma unroll
        for (int nf = 0; nf < 4; nf++) {
            int n = n0 + nwarp + nf * 8 + dc;
            if (n < N) {
                *(float2*)(C + (size_t)m * N + n)       = make_float2(acc[mf][nf][0], acc[mf][nf][1]);
                *(float2*)(C + (size_t)(m + 8) * N + n) = make_float2(acc[mf][nf][2], acc[mf][nf][3]);
            }
        }
    }
}

// ---------------- launch ----------------
extern "C" void kernel_launch(void* const* d_in, const int* in_sizes, int n_in,
                              void* d_out, int out_size)
{
    const float* z         = (const float*)d_in[0];
    const float* W_init    = (const float*)d_in[1];
    const float* b_init    = (const float*)d_in[2];
    const float* embedding = (const float*)d_in[3];
    const float* W_ih0     = (const float*)d_in[4];
    const float* W_hh0     = (const float*)d_in[5];
    const float* b_ih0     = (const float*)d_in[6];
    const float* b_hh0     = (const float*)d_in[7];
    const float* W_ih1     = (const float*)d_in[8];
    const float* W_hh1     = (const float*)d_in[9];
    const float* b_ih1     = (const float*)d_in[10];
    const float* b_hh1     = (const float*)d_in[11];
    const float* ln_g      = (const float*)d_in[12];
    const float* ln_b      = (const float*)d_in[13];
    const float* W_out     = (const float*)d_in[14];
    const float* b_out     = (const float*)d_in[15];
    float* out = (float*)d_out;

    (void)in_sizes; (void)n_in; (void)out_size;

    static bool attr_done = false;
    if (!attr_done) {
        cudaFuncSetAttribute(gru_layer<0>, cudaFuncAttributeMaxDynamicSharedMemorySize, GRU_SMEM);
        cudaFuncSetAttribute(gru_layer<1>, cudaFuncAttributeMaxDynamicSharedMemorySize, GRU_SMEM);
        cudaFuncSetAttribute(gemm_mma, cudaFuncAttributeMaxDynamicSharedMemorySize, GEMM_SMEM);
        attr_done = true;
    }

    zero_bar<<<1, 32>>>();
    k_h0<<<BATCH, 256>>>(z, W_init, b_init);
    k_gx0<<<3, 256>>>(embedding, W_ih0, b_ih0);
    // split weights into bf16 hi/lo
    cvt_split<<<(G3 * HD / 4 + 255) / 256, 256>>>(W_ih1, 0, G3 * HD / 4);
    cvt_split<<<(PD * HD / 4 + 255) / 256, 256>>>(W_out, 1, PD * HD / 4);

    // layer 0 recurrence (writes bf16 hi/lo outputs)
    gru_layer<0><<<dim3(8, 16), 256, GRU_SMEM>>>(W_hh0, b_hh0);

    // gx1 = out0 @ W_ih1^T + b_ih1  (32768 x 768)
    gemm_mma<<<dim3(G3 / 128, BT / 128), 256, GEMM_SMEM>>>(0, 0, b_ih1, nullptr, G3);

    // layer 1 recurrence (writes g_act fp32)
    gru_layer<1><<<dim3(8, 16), 256, GRU_SMEM>>>(W_hh1, b_hh1);

    // LN + ELU -> bf16 hi/lo
    ln_elu<<<BT / 8, 256>>>(ln_g, ln_b);

    // logits = act @ W_out^T + b_out  (32768 x 10000)
    gemm_mma<<<dim3((PD + 127) / 128, BT / 128), 256, GEMM_SMEM>>>(1, 1, b_out, out, PD);
}

// round 11
// speedup vs baseline: 3.7635x; 1.5837x over previous
#include <cuda_runtime.h>
#include <cuda_bf16.h>
#include <cuda_fp16.h>
#include <math.h>
#include <stdint.h>

// Problem dims
#define BATCH 512
#define ZD    64
#define HD    256
#define TT    64
#define PD    10000
#define G3    768
#define BT    32768

// ---------------- device scratch ----------------
__device__ __align__(256) float g_h0[BATCH * HD];
__device__ __align__(256) float g_hA[BATCH * HD];
__device__ __align__(256) float g_hB[BATCH * HD];
__device__ __align__(256) __nv_bfloat16 g_out0_hi[(size_t)BT * HD];
__device__ __align__(256) __nv_bfloat16 g_out0_lo[(size_t)BT * HD];
__device__ __align__(256) float g_act[(size_t)BT * HD];
__device__ __align__(256) __half g_act_hi[(size_t)BT * HD];
__device__ __align__(256) __half g_act_lo[(size_t)BT * HD];
__device__ __align__(256) float g_gx1[(size_t)BT * G3];
__device__ __align__(256) float g_gx0[G3];
__device__ __align__(256) __nv_bfloat16 g_wih1_hi[G3 * HD];
__device__ __align__(256) __nv_bfloat16 g_wih1_lo[G3 * HD];
__device__ __align__(256) __half g_wout_h[(size_t)PD * HD];
__device__ int g_bar[2][16];

// ---------------- generic helpers ----------------
__device__ __forceinline__ int ld_acq(const int* p) {
    int v;
    asm volatile("ld.global.acquire.gpu.b32 %0,[%1];" : "=r"(v) : "l"(p));
    return v;
}
__device__ __forceinline__ float sigmoidf_(float x) { return 1.0f / (1.0f + expf(-x)); }
__device__ __forceinline__ float eluf_(float x)     { return x > 0.f ? x : expm1f(x); }

__device__ __forceinline__ void split_hl(float x, __nv_bfloat16& h, __nv_bfloat16& l) {
    h = __float2bfloat16(x);
    l = __float2bfloat16(x - __bfloat162float(h));
}
__device__ __forceinline__ void split_hlh(float x, __half& h, __half& l) {
    h = __float2half_rn(x);
    l = __float2half_rn(x - __half2float(h));
}

__device__ __forceinline__ uint32_t s2u(const void* p) {
    uint32_t a;
    asm("{ .reg .u64 t; cvta.to.shared.u64 t, %1; cvt.u32.u64 %0, t; }" : "=r"(a) : "l"(p));
    return a;
}

// ---------------- mma.sync building blocks (sm_80-baseline) ----------------
__device__ __forceinline__ void cp16(uint32_t dst, const void* src, int srcbytes) {
    asm volatile("cp.async.cg.shared.global [%0], [%1], 16, %2;"
                 :: "r"(dst), "l"(src), "r"(srcbytes) : "memory");
}
__device__ __forceinline__ void cp_commit() {
    asm volatile("cp.async.commit_group;" ::: "memory");
}
__device__ __forceinline__ void ldm_x4(uint32_t* r, uint32_t addr) {
    asm volatile("ldmatrix.sync.aligned.m8n8.x4.shared.b16 {%0,%1,%2,%3}, [%4];"
                 : "=r"(r[0]), "=r"(r[1]), "=r"(r[2]), "=r"(r[3]) : "r"(addr));
}
__device__ __forceinline__ void ldm_x2(uint32_t* r, uint32_t addr) {
    asm volatile("ldmatrix.sync.aligned.m8n8.x2.shared.b16 {%0,%1}, [%2];"
                 : "=r"(r[0]), "=r"(r[1]) : "r"(addr));
}
__device__ __forceinline__ void mma_bf16(float* d, const uint32_t* a, const uint32_t* b) {
    asm volatile("mma.sync.aligned.m16n8k16.row.col.f32.bf16.bf16.f32 "
                 "{%0,%1,%2,%3}, {%4,%5,%6,%7}, {%8,%9}, {%0,%1,%2,%3};"
                 : "+f"(d[0]), "+f"(d[1]), "+f"(d[2]), "+f"(d[3])
                 : "r"(a[0]), "r"(a[1]), "r"(a[2]), "r"(a[3]), "r"(b[0]), "r"(b[1]));
}
__device__ __forceinline__ void mma_f16(float* d, const uint32_t* a, const uint32_t* b) {
    asm volatile("mma.sync.aligned.m16n8k16.row.col.f32.f16.f16.f32 "
                 "{%0,%1,%2,%3}, {%4,%5,%6,%7}, {%8,%9}, {%0,%1,%2,%3};"
                 : "+f"(d[0]), "+f"(d[1]), "+f"(d[2]), "+f"(d[3])
                 : "r"(a[0]), "r"(a[1]), "r"(a[2]), "r"(a[3]), "r"(b[0]), "r"(b[1]));
}

// ---------------- init kernels ----------------
__global__ void zero_bar() {
    if (threadIdx.x < 32) ((int*)g_bar)[threadIdx.x] = 0;
}

__global__ __launch_bounds__(256) void k_h0(const float* __restrict__ z,
                                            const float* __restrict__ Wi,
                                            const float* __restrict__ bi)
{
    __shared__ float zs[ZD];
    int b = blockIdx.x;
    int h = threadIdx.x;
    if (threadIdx.x < ZD) zs[threadIdx.x] = z[(size_t)b * ZD + threadIdx.x];
    __syncthreads();
    float s = bi[h];
    const float* wr = Wi + (size_t)h * ZD;
    #pragma unroll 16
    for (int k = 0; k < ZD; k++) s += zs[k] * wr[k];
    g_h0[(size_t)b * HD + h] = eluf_(s);
}

__global__ __launch_bounds__(256) void k_gx0(const float* __restrict__ emb,
                                             const float* __restrict__ Wih0,
                                             const float* __restrict__ bih0)
{
    __shared__ float es[HD];
    es[threadIdx.x] = emb[threadIdx.x];
    __syncthreads();
    int j = blockIdx.x * 256 + threadIdx.x;
    float s = bih0[j];
    const float* wr = Wih0 + (size_t)j * HD;
    #pragma unroll 16
    for (int k = 0; k < HD; k++) s += es[k] * wr[k];
    g_gx0[j] = s;
}

// bf16 hi/lo splitter for W_ih1
__global__ __launch_bounds__(256) void cvt_split(const float* __restrict__ src, int n4)
{
    int i = blockIdx.x * 256 + threadIdx.x;
    if (i < n4) {
        float4 v = ((const float4*)src)[i];
        __nv_bfloat16 h0, h1, h2, h3, l0, l1, l2, l3;
        split_hl(v.x, h0, l0); split_hl(v.y, h1, l1);
        split_hl(v.z, h2, l2); split_hl(v.w, h3, l3);
        ((__nv_bfloat162*)g_wih1_hi)[2 * i]     = __halves2bfloat162(h0, h1);
        ((__nv_bfloat162*)g_wih1_hi)[2 * i + 1] = __halves2bfloat162(h2, h3);
        ((__nv_bfloat162*)g_wih1_lo)[2 * i]     = __halves2bfloat162(l0, l1);
        ((__nv_bfloat162*)g_wih1_lo)[2 * i + 1] = __halves2bfloat162(l2, l3);
    }
}

// fp16 single-round converter for W_out
__global__ __launch_bounds__(256) void cvt_half(const float* __restrict__ src, int n4)
{
    int i = blockIdx.x * 256 + threadIdx.x;
    if (i < n4) {
        float4 v = ((const float4*)src)[i];
        ((__half2*)g_wout_h)[2 * i]     = __halves2half2(__float2half_rn(v.x), __float2half_rn(v.y));
        ((__half2*)g_wout_h)[2 * i + 1] = __halves2half2(__float2half_rn(v.z), __float2half_rn(v.w));
    }
}

// ---------------- persistent GRU layer (tensor-core) ----------------
// Grid (8,16): blockIdx.x = h-tile (32 h), blockIdx.y = b-tile (32 b).
// Whh slice (96 x 256) resident in smem as bf16 hi/lo for all 64 steps.
// Per step: stage h (32x256 fp32 -> bf16 hi/lo), 8 warps do 16b x (3 gates x 8h)
// via 3-term bf16 m16n8k16, then gate math on d-fragments.
#define ROWPA 264   // bf16 elems per smem row (264*2=528 B; 528/16=33, 33%8=1 -> ldsm conflict-free)
#define GRUSM_WHI 0
#define GRUSM_WLO (96 * ROWPA * 2)
#define GRUSM_AHI (2 * 96 * ROWPA * 2)
#define GRUSM_ALO (2 * 96 * ROWPA * 2 + 32 * ROWPA * 2)
#define GRU_SMEM  (2 * 96 * ROWPA * 2 + 2 * 32 * ROWPA * 2)   // 135168 B

template<int LAYER>
__global__ __launch_bounds__(256, 1) void gru_layer(const float* __restrict__ Whh,
                                                    const float* __restrict__ bhh)
{
    extern __shared__ char smraw[];
    const uint32_t smb = s2u(smraw);

    const int tid = threadIdx.x, wid = tid >> 5, lane = tid & 31;
    const int h0t = blockIdx.x * 32;
    const int bj  = blockIdx.y;
    const int b0t = bj * 32;

    // ---- stage Whh slice as bf16 hi/lo, layout [j=g*32+hloc][k], padded rows ----
    #pragma unroll
    for (int q = 0; q < 24; q++) {
        int l = tid + q * 256;           // 0..6143 = 96 j * 64 float4
        int j = l >> 6, kq = l & 63;
        int g = j >> 5, hloc = j & 31;
        float4 v = *(const float4*)(Whh + (size_t)(g * HD + h0t + hloc) * HD + 4 * kq);
        __nv_bfloat16 h0, h1, h2, h3, l0, l1, l2, l3;
        split_hl(v.x, h0, l0); split_hl(v.y, h1, l1);
        split_hl(v.z, h2, l2); split_hl(v.w, h3, l3);
        char* dh = smraw + GRUSM_WHI + ((size_t)j * ROWPA + 4 * kq) * 2;
        char* dl = smraw + GRUSM_WLO + ((size_t)j * ROWPA + 4 * kq) * 2;
        ((__nv_bfloat162*)dh)[0] = __halves2bfloat162(h0, h1);
        ((__nv_bfloat162*)dh)[1] = __halves2bfloat162(h2, h3);
        ((__nv_bfloat162*)dl)[0] = __halves2bfloat162(l0, l1);
        ((__nv_bfloat162*)dl)[1] = __halves2bfloat162(l2, l3);
    }

    // ---- per-warp fragment addressing ----
    const int mh = wid & 1;              // b-half (16 rows)
    const int hw = (wid >> 1) * 8;       // 8-h chunk within 32-h tile
    const int arow = lane & 15, akc = (lane >> 4) * 8;
    const uint32_t aoff_hi = smb + GRUSM_AHI + (uint32_t)(((mh * 16 + arow) * ROWPA + akc) * 2);
    const uint32_t aoff_lo = smb + GRUSM_ALO + (uint32_t)(((mh * 16 + arow) * ROWPA + akc) * 2);
    const int brow8 = lane & 7;
    const int bg01  = (lane >> 4) & 1;   // 0->gate r, 1->gate z
    const int bkc   = ((lane >> 3) & 1) * 8;
    const int bj01  = bg01 * 32 + hw + brow8;
    const uint32_t b01_hi = smb + GRUSM_WHI + (uint32_t)((bj01 * ROWPA + bkc) * 2);
    const uint32_t b01_lo = smb + GRUSM_WLO + (uint32_t)((bj01 * ROWPA + bkc) * 2);
    const int l15 = lane & 15;
    const int bj2 = 64 + hw + (l15 & 7);
    const int bkc2 = ((l15 >> 3) & 1) * 8;
    const uint32_t b2_hi = smb + GRUSM_WHI + (uint32_t)((bj2 * ROWPA + bkc2) * 2);
    const uint32_t b2_lo = smb + GRUSM_WLO + (uint32_t)((bj2 * ROWPA + bkc2) * 2);

    // d-fragment coordinates
    const int dr = lane >> 2;            // row within 8
    const int dc = (lane & 3) * 2;       // col pair
    const int hcol = h0t + hw + dc;      // 2 h's: hcol, hcol+1

    // per-lane constants
    const float2 bh_r = *(const float2*)(bhh + 0 * HD + hcol);
    const float2 bh_z = *(const float2*)(bhh + 1 * HD + hcol);
    const float2 bh_n = *(const float2*)(bhh + 2 * HD + hcol);
    float2 gx0r = make_float2(0.f, 0.f), gx0z = gx0r, gx0n = gx0r;
    if (LAYER == 0) {
        gx0r = *(const float2*)(g_gx0 + 0 * HD + hcol);
        gx0z = *(const float2*)(g_gx0 + 1 * HD + hcol);
        gx0n = *(const float2*)(g_gx0 + 2 * HD + hcol);
    }
    __syncthreads();

    int* __restrict__ bar = &g_bar[LAYER][bj];

    for (int t = 0; t < TT; t++) {
        const float* h_in = (t == 0) ? g_h0 : ((t & 1) ? g_hA : g_hB);
        float* h_out = (t & 1) ? g_hB : g_hA;

        // ---- stage h tile: 32 rows x 256 k fp32 -> bf16 hi/lo smem ----
        #pragma unroll
        for (int q = 0; q < 8; q++) {
            int l = tid + q * 256;       // 32 rows x 64 float4
            int row = l >> 6, kq = l & 63;
            float4 v = __ldcg((const float4*)(h_in + (size_t)(b0t + row) * HD + 4 * kq));
            __nv_bfloat16 h0, h1, h2, h3, l0, l1, l2, l3;
            split_hl(v.x, h0, l0); split_hl(v.y, h1, l1);
            split_hl(v.z, h2, l2); split_hl(v.w, h3, l3);
            char* dh = smraw + GRUSM_AHI + ((size_t)row * ROWPA + 4 * kq) * 2;
            char* dl = smraw + GRUSM_ALO + ((size_t)row * ROWPA + 4 * kq) * 2;
            ((__nv_bfloat162*)dh)[0] = __halves2bfloat162(h0, h1);
            ((__nv_bfloat162*)dh)[1] = __halves2bfloat162(h2, h3);
            ((__nv_bfloat162*)dl)[0] = __halves2bfloat162(l0, l1);
            ((__nv_bfloat162*)dl)[1] = __halves2bfloat162(l2, l3);
        }

        // ---- preload per-lane gate inputs + h_prev (overlap with sync/mma) ----
        const int bA = b0t + mh * 16 + dr;       // rowhalf 0
        const int bB = bA + 8;                   // rowhalf 1
        float2 hpA, hpB;
        {
            hpA = __ldcg((const float2*)(h_in + (size_t)bA * HD + hcol));
            hpB = __ldcg((const float2*)(h_in + (size_t)bB * HD + hcol));
        }
        float2 gAr, gAz, gAn, gBr, gBz, gBn;
        if (LAYER == 1) {
            const float* pA = g_gx1 + ((size_t)bA * TT + t) * G3 + hcol;
            const float* pB = g_gx1 + ((size_t)bB * TT + t) * G3 + hcol;
            gAr = *(const float2*)(pA);  gAz = *(const float2*)(pA + HD);  gAn = *(const float2*)(pA + 2 * HD);
            gBr = *(const float2*)(pB);  gBz = *(const float2*)(pB + HD);  gBn = *(const float2*)(pB + 2 * HD);
        } else {
            gAr = gBr = gx0r; gAz = gBz = gx0z; gAn = gBn = gx0n;
        }
        __syncthreads();

        // ---- 3-term bf16 MMA over K=256 ----
        float acc0[4] = {0.f, 0.f, 0.f, 0.f};
        float acc1[4] = {0.f, 0.f, 0.f, 0.f};
        float acc2[4] = {0.f, 0.f, 0.f, 0.f};
        #pragma unroll
        for (int ks = 0; ks < 16; ks++) {
            uint32_t ah[4], al[4], w01h[4], w01l[4], w2h[2], w2l[2];
            ldm_x4(ah, aoff_hi + ks * 32);
            ldm_x4(al, aoff_lo + ks * 32);
            ldm_x4(w01h, b01_hi + ks * 32);
            ldm_x4(w01l, b01_lo + ks * 32);
            ldm_x2(w2h, b2_hi + ks * 32);
            ldm_x2(w2l, b2_lo + ks * 32);
            // gate r (cols j = hw..hw+7)
            mma_bf16(acc0, ah, w01h);
            mma_bf16(acc0, al, w01h);
            mma_bf16(acc0, ah, w01l);
            // gate z (cols j = 32+hw..)
            mma_bf16(acc1, ah, w01h + 2);
            mma_bf16(acc1, al, w01h + 2);
            mma_bf16(acc1, ah, w01l + 2);
            // gate n (cols j = 64+hw..)
            mma_bf16(acc2, ah, w2h);
            mma_bf16(acc2, al, w2h);
            mma_bf16(acc2, ah, w2l);
        }

        // ---- gate math + writeback (2 row-halves, 2 h's each) ----
        #pragma unroll
        for (int rh = 0; rh < 2; rh++) {
            int b = rh ? bB : bA;
            float2 hp = rh ? hpB : hpA;
            float2 gr = rh ? gBr : gAr;
            float2 gz = rh ? gBz : gAz;
            float2 gn = rh ? gBn : gAn;
            float ar0 = rh ? acc0[2] : acc0[0], ar1 = rh ? acc0[3] : acc0[1];
            float az0 = rh ? acc1[2] : acc1[0], az1 = rh ? acc1[3] : acc1[1];
            float an0 = rh ? acc2[2] : acc2[0], an1 = rh ? acc2[3] : acc2[1];
            float r0 = sigmoidf_(gr.x + ar0 + bh_r.x);
            float r1 = sigmoidf_(gr.y + ar1 + bh_r.y);
            float u0 = sigmoidf_(gz.x + az0 + bh_z.x);
            float u1 = sigmoidf_(gz.y + az1 + bh_z.y);
            float n0 = tanhf(gn.x + r0 * (an0 + bh_n.x));
            float n1 = tanhf(gn.y + r1 * (an1 + bh_n.y));
            float hn0 = (1.f - u0) * n0 + u0 * hp.x;
            float hn1 = (1.f - u1) * n1 + u1 * hp.y;
            *(float2*)(h_out + (size_t)b * HD + hcol) = make_float2(hn0, hn1);
            size_t p = ((size_t)b * TT + t) * HD + hcol;
            if (LAYER == 0) {
                __nv_bfloat16 hh0, ll0, hh1, ll1;
                split_hl(hn0, hh0, ll0);
                split_hl(hn1, hh1, ll1);
                *(__nv_bfloat162*)(g_out0_hi + p) = __halves2bfloat162(hh0, hh1);
                *(__nv_bfloat162*)(g_out0_lo + p) = __halves2bfloat162(ll0, ll1);
            } else {
                *(float2*)(g_act + p) = make_float2(hn0, hn1);
            }
        }

        // ---- per-btile 8-block barrier ----
        if (t < TT - 1) {
            __threadfence();
            __syncthreads();
            if (tid == 0) {
                atomicAdd(bar, 1);
                int target = 8 * (t + 1);
                while (ld_acq(bar) < target) { }
            }
            __syncthreads();
        }
    }
}

// ---------------- LayerNorm + ELU -> fp16 hi/lo ----------------
__global__ __launch_bounds__(256) void ln_elu(const float* __restrict__ gamma,
                                              const float* __restrict__ beta)
{
    int warp = threadIdx.x >> 5, lane = threadIdx.x & 31;
    size_t row = (size_t)blockIdx.x * 8 + warp;
    const float* x = g_act + row * HD;
    float v[8];
    #pragma unroll
    for (int i = 0; i < 8; i++) v[i] = x[lane + 32 * i];
    float s = 0.f;
    #pragma unroll
    for (int i = 0; i < 8; i++) s += v[i];
    #pragma unroll
    for (int o = 16; o > 0; o >>= 1) s += __shfl_xor_sync(0xffffffffu, s, o);
    float mu = s * (1.0f / 256.0f);
    float q = 0.f;
    #pragma unroll
    for (int i = 0; i < 8; i++) { float dl = v[i] - mu; q += dl * dl; }
    #pragma unroll
    for (int o = 16; o > 0; o >>= 1) q += __shfl_xor_sync(0xffffffffu, q, o);
    float inv = rsqrtf(q * (1.0f / 256.0f) + 1e-5f);
    #pragma unroll
    for (int i = 0; i < 8; i++) {
        int h = lane + 32 * i;
        float y = eluf_((v[i] - mu) * inv * gamma[h] + beta[h]);
        __half hb, lb;
        split_hlh(y, hb, lb);
        g_act_hi[row * HD + h] = hb;
        g_act_lo[row * HD + h] = lb;
    }
}

// ---------------- mma.sync GEMM (templated precision mode) ----------------
// MODE 0: bf16 3-term (gx1): K phases Ahi*Bhi, Alo*Bhi, Ahi*Blo, NCH=24
// MODE 1: fp16 2-term (logits): Ahi*W, Alo*W, NCH=16
// CTA tile 128x128, 8 warps (2m x 4n) of 64x32, 4-stage cp.async, K-chunk 32.
#define ROWP 40
#define ASTG_B 0
#define BSTG_B (128 * ROWP * 2)
#define STG_BYTES (2 * 128 * ROWP * 2)
#define GEMM_SMEM (4 * STG_BYTES)

__device__ __forceinline__ void ld_chunk2(uint32_t smbase, int stage,
                                          const uint16_t* __restrict__ A0,
                                          const uint16_t* __restrict__ A1,
                                          const uint16_t* __restrict__ A2,
                                          const uint16_t* __restrict__ B0,
                                          const uint16_t* __restrict__ B2,
                                          int m0, int n0, int N, int c, int tid, int nch)
{
    if (c < nch) {
        int p = c >> 3, k0 = (c & 7) * 32;
        const uint16_t* A = (p == 1) ? A1 : ((p == 2) ? A2 : A0);
        const uint16_t* B = (p == 2) ? B2 : B0;
        uint32_t stg = smbase + stage * STG_BYTES;
        #pragma unroll
        for (int q = 0; q < 2; q++) {
            int i = tid * 2 + q;
            int row = i >> 2, seg = i & 3;
            uint32_t soff = (uint32_t)(row * ROWP + seg * 8) * 2;
            cp16(stg + ASTG_B + soff, A + (size_t)(m0 + row) * HD + k0 + seg * 8, 16);
            int n = n0 + row;
            const uint16_t* bsrc = B + (size_t)(n < N ? n : 0) * HD + k0 + seg * 8;
            cp16(stg + BSTG_B + soff, bsrc, n < N ? 16 : 0);
        }
    }
    cp_commit();
}

template<int MODE>
__global__ __launch_bounds__(256, 1) void gemm_mma(const float* __restrict__ bias,
                                                   float* __restrict__ Cext, int N)
{
    extern __shared__ char smraw[];
    const uint32_t smb = s2u(smraw);

    const int tid = threadIdx.x, wid = tid >> 5, lane = tid & 31;
    const int n0 = blockIdx.x * 128;
    const int m0 = blockIdx.y * 128;
    const int mwarp = (wid & 1) * 64;
    const int nwarp = (wid >> 1) * 32;
    const int NCH = MODE ? 16 : 24;

    const uint16_t *A0, *A1, *A2, *B0, *B2;
    if (MODE == 0) {
        A0 = (const uint16_t*)g_out0_hi; A1 = (const uint16_t*)g_out0_lo; A2 = A0;
        B0 = (const uint16_t*)g_wih1_hi; B2 = (const uint16_t*)g_wih1_lo;
    } else {
        A0 = (const uint16_t*)g_act_hi;  A1 = (const uint16_t*)g_act_lo;  A2 = A0;
        B0 = (const uint16_t*)g_wout_h;  B2 = B0;
    }
    float* C = Cext ? Cext : g_gx1;

    uint32_t aoff[4], boff[2];
    {
        int arow = (lane & 15);
        int akc  = (lane >> 4) * 8;
        #pragma unroll
        for (int mf = 0; mf < 4; mf++)
            aoff[mf] = (uint32_t)(((mwarp + mf * 16 + arow) * ROWP + akc) * 2);
        int brow = (lane & 7) + ((lane >> 4) & 1) * 8;
        int bkc  = ((lane >> 3) & 1) * 8;
        #pragma unroll
        for (int nf2 = 0; nf2 < 2; nf2++)
            boff[nf2] = (uint32_t)(BSTG_B + ((nwarp + nf2 * 16 + brow) * ROWP + bkc) * 2);
    }

    const int dr = lane >> 2;
    const int dc = (lane & 3) * 2;
    float acc[4][4][4];
    #pragma unroll
    for (int nf = 0; nf < 4; nf++) {
        int n = n0 + nwarp + nf * 8 + dc;
        float b0 = (n < N) ? bias[n] : 0.f;
        float b1 = (n + 1 < N) ? bias[n + 1] : 0.f;
        #pragma unroll
        for (int mf = 0; mf < 4; mf++) {
            acc[mf][nf][0] = b0; acc[mf][nf][1] = b1;
            acc[mf][nf][2] = b0; acc[mf][nf][3] = b1;
        }
    }

    #pragma unroll
    for (int c = 0; c < 3; c++)
        ld_chunk2(smb, c, A0, A1, A2, B0, B2, m0, n0, N, c, tid, NCH);

    for (int c = 0; c < NCH; c++) {
        asm volatile("cp.async.wait_group 2;" ::: "memory");
        __syncthreads();
        ld_chunk2(smb, (c + 3) & 3, A0, A1, A2, B0, B2, m0, n0, N, c + 3, tid, NCH);

        uint32_t stg = smb + (c & 3) * STG_BYTES;
        #pragma unroll
        for (int kk = 0; kk < 2; kk++) {
            uint32_t af[4][4], bf[2][4];
            #pragma unroll
            for (int mf = 0; mf < 4; mf++) ldm_x4(af[mf], stg + aoff[mf] + kk * 32);
            #pragma unroll
            for (int nf2 = 0; nf2 < 2; nf2++) ldm_x4(bf[nf2], stg + boff[nf2] + kk * 32);
            #pragma unroll
            for (int mf = 0; mf < 4; mf++)
                #pragma unroll
                for (int nf = 0; nf < 4; nf++) {
                    if (MODE == 0) mma_bf16(acc[mf][nf], af[mf], &bf[nf >> 1][(nf & 1) * 2]);
                    else           mma_f16 (acc[mf][nf], af[mf], &bf[nf >> 1][(nf & 1) * 2]);
                }
        }
        __syncthreads();
    }

    #pragma unroll
    for (int mf = 0; mf < 4; mf++) {
        int m = m0 + mwarp + mf * 16 + dr;
        #pragma unroll
        for (int nf = 0; nf < 4; nf++) {
            int n = n0 + nwarp + nf * 8 + dc;
            if (n < N) {
                *(float2*)(C + (size_t)m * N + n)       = make_float2(acc[mf][nf][0], acc[mf][nf][1]);
                *(float2*)(C + (size_t)(m + 8) * N + n) = make_float2(acc[mf][nf][2], acc[mf][nf][3]);
            }
        }
    }
}

// ---------------- launch ----------------
extern "C" void kernel_launch(void* const* d_in, const int* in_sizes, int n_in,
                              void* d_out, int out_size)
{
    const float* z         = (const float*)d_in[0];
    const float* W_init    = (const float*)d_in[1];
    const float* b_init    = (const float*)d_in[2];
    const float* embedding = (const float*)d_in[3];
    const float* W_ih0     = (const float*)d_in[4];
    const float* W_hh0     = (const float*)d_in[5];
    const float* b_ih0     = (const float*)d_in[6];
    const float* b_hh0     = (const float*)d_in[7];
    const float* W_ih1     = (const float*)d_in[8];
    const float* W_hh1     = (const float*)d_in[9];
    const float* b_ih1     = (const float*)d_in[10];
    const float* b_hh1     = (const float*)d_in[11];
    const float* ln_g      = (const float*)d_in[12];
    const float* ln_b      = (const float*)d_in[13];
    const float* W_out     = (const float*)d_in[14];
    const float* b_out     = (const float*)d_in[15];
    float* out = (float*)d_out;

    (void)in_sizes; (void)n_in; (void)out_size;

    static bool attr_done = false;
    if (!attr_done) {
        cudaFuncSetAttribute(gru_layer<0>, cudaFuncAttributeMaxDynamicSharedMemorySize, GRU_SMEM);
        cudaFuncSetAttribute(gru_layer<1>, cudaFuncAttributeMaxDynamicSharedMemorySize, GRU_SMEM);
        cudaFuncSetAttribute(gemm_mma<0>, cudaFuncAttributeMaxDynamicSharedMemorySize, GEMM_SMEM);
        cudaFuncSetAttribute(gemm_mma<1>, cudaFuncAttributeMaxDynamicSharedMemorySize, GEMM_SMEM);
        attr_done = true;
    }

    zero_bar<<<1, 32>>>();
    k_h0<<<BATCH, 256>>>(z, W_init, b_init);
    k_gx0<<<3, 256>>>(embedding, W_ih0, b_ih0);
    cvt_split<<<(G3 * HD / 4 + 255) / 256, 256>>>(W_ih1, G3 * HD / 4);
    cvt_half<<<(PD * HD / 4 + 255) / 256, 256>>>(W_out, PD * HD / 4);

    // layer 0 recurrence (tensor-core GRU, writes bf16 hi/lo outputs)
    gru_layer<0><<<dim3(8, 16), 256, GRU_SMEM>>>(W_hh0, b_hh0);

    // gx1 = out0 @ W_ih1^T + b_ih1  (32768 x 768), bf16 3-term
    gemm_mma<0><<<dim3(G3 / 128, BT / 128), 256, GEMM_SMEM>>>(b_ih1, nullptr, G3);

    // layer 1 recurrence (writes g_act fp32)
    gru_layer<1><<<dim3(8, 16), 256, GRU_SMEM>>>(W_hh1, b_hh1);

    // LN + ELU -> fp16 hi/lo
    ln_elu<<<BT / 8, 256>>>(ln_g, ln_b);

    // logits = act @ W_out^T + b_out  (32768 x 10000), fp16 2-term
    gemm_mma<1><<<dim3((PD + 127) / 128, BT / 128), 256, GEMM_SMEM>>>(b_out, out, PD);
}

// round 12
// speedup vs baseline: 4.4446x; 1.1810x over previous
#include <cuda_runtime.h>
#include <cuda_bf16.h>
#include <cuda_fp16.h>
#include <math.h>
#include <stdint.h>

// Problem dims
#define BATCH 512
#define ZD    64
#define HD    256
#define TT    64
#define PD    10000
#define G3    768
#define BT    32768

// ---------------- device scratch ----------------
__device__ __align__(256) float g_h0[BATCH * HD];
__device__ __align__(256) float g_hA[BATCH * HD];
__device__ __align__(256) float g_hB[BATCH * HD];
__device__ __align__(256) __nv_bfloat16 g_out0_hi[(size_t)BT * HD];
__device__ __align__(256) __nv_bfloat16 g_out0_lo[(size_t)BT * HD];
__device__ __align__(256) float g_act[(size_t)BT * HD];
__device__ __align__(256) __half g_act_hi[(size_t)BT * HD];
__device__ __align__(256) __half g_act_lo[(size_t)BT * HD];
__device__ __align__(256) float g_gx1[(size_t)BT * G3];
__device__ __align__(256) float g_gx0[G3];
__device__ __align__(256) __nv_bfloat16 g_wih1_hi[G3 * HD];
__device__ __align__(256) __nv_bfloat16 g_wih1_lo[G3 * HD];
__device__ __align__(256) __half g_wout_h[(size_t)PD * HD];
__device__ int g_bar[2][16];

// ---------------- generic helpers ----------------
__device__ __forceinline__ int ld_acq(const int* p) {
    int v;
    asm volatile("ld.global.acquire.gpu.b32 %0,[%1];" : "=r"(v) : "l"(p));
    return v;
}
__device__ __forceinline__ float sigmoidf_(float x) { return 1.0f / (1.0f + expf(-x)); }
__device__ __forceinline__ float eluf_(float x)     { return x > 0.f ? x : expm1f(x); }

__device__ __forceinline__ void split_hl(float x, __nv_bfloat16& h, __nv_bfloat16& l) {
    h = __float2bfloat16(x);
    l = __float2bfloat16(x - __bfloat162float(h));
}
__device__ __forceinline__ void split_hlh(float x, __half& h, __half& l) {
    h = __float2half_rn(x);
    l = __float2half_rn(x - __half2float(h));
}

__device__ __forceinline__ uint32_t s2u(const void* p) {
    uint32_t a;
    asm("{ .reg .u64 t; cvta.to.shared.u64 t, %1; cvt.u32.u64 %0, t; }" : "=r"(a) : "l"(p));
    return a;
}

// ---------------- mma.sync building blocks (sm_80-baseline) ----------------
__device__ __forceinline__ void cp16(uint32_t dst, const void* src, int srcbytes) {
    asm volatile("cp.async.cg.shared.global [%0], [%1], 16, %2;"
                 :: "r"(dst), "l"(src), "r"(srcbytes) : "memory");
}
__device__ __forceinline__ void cp_commit() {
    asm volatile("cp.async.commit_group;" ::: "memory");
}
__device__ __forceinline__ void ldm_x4(uint32_t* r, uint32_t addr) {
    asm volatile("ldmatrix.sync.aligned.m8n8.x4.shared.b16 {%0,%1,%2,%3}, [%4];"
                 : "=r"(r[0]), "=r"(r[1]), "=r"(r[2]), "=r"(r[3]) : "r"(addr));
}
__device__ __forceinline__ void ldm_x2(uint32_t* r, uint32_t addr) {
    asm volatile("ldmatrix.sync.aligned.m8n8.x2.shared.b16 {%0,%1}, [%2];"
                 : "=r"(r[0]), "=r"(r[1]) : "r"(addr));
}
__device__ __forceinline__ void mma_bf16(float* d, const uint32_t* a, const uint32_t* b) {
    asm volatile("mma.sync.aligned.m16n8k16.row.col.f32.bf16.bf16.f32 "
                 "{%0,%1,%2,%3}, {%4,%5,%6,%7}, {%8,%9}, {%0,%1,%2,%3};"
                 : "+f"(d[0]), "+f"(d[1]), "+f"(d[2]), "+f"(d[3])
                 : "r"(a[0]), "r"(a[1]), "r"(a[2]), "r"(a[3]), "r"(b[0]), "r"(b[1]));
}
__device__ __forceinline__ void mma_f16(float* d, const uint32_t* a, const uint32_t* b) {
    asm volatile("mma.sync.aligned.m16n8k16.row.col.f32.f16.f16.f32 "
                 "{%0,%1,%2,%3}, {%4,%5,%6,%7}, {%8,%9}, {%0,%1,%2,%3};"
                 : "+f"(d[0]), "+f"(d[1]), "+f"(d[2]), "+f"(d[3])
                 : "r"(a[0]), "r"(a[1]), "r"(a[2]), "r"(a[3]), "r"(b[0]), "r"(b[1]));
}

// ---------------- init kernels ----------------
__global__ void zero_bar() {
    if (threadIdx.x < 32) ((int*)g_bar)[threadIdx.x] = 0;
}

__global__ __launch_bounds__(256) void k_h0(const float* __restrict__ z,
                                            const float* __restrict__ Wi,
                                            const float* __restrict__ bi)
{
    __shared__ float zs[ZD];
    int b = blockIdx.x;
    int h = threadIdx.x;
    if (threadIdx.x < ZD) zs[threadIdx.x] = z[(size_t)b * ZD + threadIdx.x];
    __syncthreads();
    float s = bi[h];
    const float* wr = Wi + (size_t)h * ZD;
    #pragma unroll 16
    for (int k = 0; k < ZD; k++) s += zs[k] * wr[k];
    g_h0[(size_t)b * HD + h] = eluf_(s);
}

__global__ __launch_bounds__(256) void k_gx0(const float* __restrict__ emb,
                                             const float* __restrict__ Wih0,
                                             const float* __restrict__ bih0)
{
    __shared__ float es[HD];
    es[threadIdx.x] = emb[threadIdx.x];
    __syncthreads();
    int j = blockIdx.x * 256 + threadIdx.x;
    float s = bih0[j];
    const float* wr = Wih0 + (size_t)j * HD;
    #pragma unroll 16
    for (int k = 0; k < HD; k++) s += es[k] * wr[k];
    g_gx0[j] = s;
}

// bf16 hi/lo splitter for W_ih1
__global__ __launch_bounds__(256) void cvt_split(const float* __restrict__ src, int n4)
{
    int i = blockIdx.x * 256 + threadIdx.x;
    if (i < n4) {
        float4 v = ((const float4*)src)[i];
        __nv_bfloat16 h0, h1, h2, h3, l0, l1, l2, l3;
        split_hl(v.x, h0, l0); split_hl(v.y, h1, l1);
        split_hl(v.z, h2, l2); split_hl(v.w, h3, l3);
        ((__nv_bfloat162*)g_wih1_hi)[2 * i]     = __halves2bfloat162(h0, h1);
        ((__nv_bfloat162*)g_wih1_hi)[2 * i + 1] = __halves2bfloat162(h2, h3);
        ((__nv_bfloat162*)g_wih1_lo)[2 * i]     = __halves2bfloat162(l0, l1);
        ((__nv_bfloat162*)g_wih1_lo)[2 * i + 1] = __halves2bfloat162(l2, l3);
    }
}

// fp16 single-round converter for W_out
__global__ __launch_bounds__(256) void cvt_half(const float* __restrict__ src, int n4)
{
    int i = blockIdx.x * 256 + threadIdx.x;
    if (i < n4) {
        float4 v = ((const float4*)src)[i];
        ((__half2*)g_wout_h)[2 * i]     = __halves2half2(__float2half_rn(v.x), __float2half_rn(v.y));
        ((__half2*)g_wout_h)[2 * i + 1] = __halves2half2(__float2half_rn(v.z), __float2half_rn(v.w));
    }
}

// ---------------- persistent GRU layer (tensor-core) ----------------
#define ROWPA 264
#define GRUSM_WHI 0
#define GRUSM_WLO (96 * ROWPA * 2)
#define GRUSM_AHI (2 * 96 * ROWPA * 2)
#define GRUSM_ALO (2 * 96 * ROWPA * 2 + 32 * ROWPA * 2)
#define GRU_SMEM  (2 * 96 * ROWPA * 2 + 2 * 32 * ROWPA * 2)   // 135168 B

template<int LAYER>
__global__ __launch_bounds__(256, 1) void gru_layer(const float* __restrict__ Whh,
                                                    const float* __restrict__ bhh)
{
    extern __shared__ char smraw[];
    const uint32_t smb = s2u(smraw);

    const int tid = threadIdx.x, wid = tid >> 5, lane = tid & 31;
    const int h0t = blockIdx.x * 32;
    const int bj  = blockIdx.y;
    const int b0t = bj * 32;

    // stage Whh slice as bf16 hi/lo, layout [j=g*32+hloc][k]
    #pragma unroll
    for (int q = 0; q < 24; q++) {
        int l = tid + q * 256;
        int j = l >> 6, kq = l & 63;
        int g = j >> 5, hloc = j & 31;
        float4 v = *(const float4*)(Whh + (size_t)(g * HD + h0t + hloc) * HD + 4 * kq);
        __nv_bfloat16 h0, h1, h2, h3, l0, l1, l2, l3;
        split_hl(v.x, h0, l0); split_hl(v.y, h1, l1);
        split_hl(v.z, h2, l2); split_hl(v.w, h3, l3);
        char* dh = smraw + GRUSM_WHI + ((size_t)j * ROWPA + 4 * kq) * 2;
        char* dl = smraw + GRUSM_WLO + ((size_t)j * ROWPA + 4 * kq) * 2;
        ((__nv_bfloat162*)dh)[0] = __halves2bfloat162(h0, h1);
        ((__nv_bfloat162*)dh)[1] = __halves2bfloat162(h2, h3);
        ((__nv_bfloat162*)dl)[0] = __halves2bfloat162(l0, l1);
        ((__nv_bfloat162*)dl)[1] = __halves2bfloat162(l2, l3);
    }

    const int mh = wid & 1;
    const int hw = (wid >> 1) * 8;
    const int arow = lane & 15, akc = (lane >> 4) * 8;
    const uint32_t aoff_hi = smb + GRUSM_AHI + (uint32_t)(((mh * 16 + arow) * ROWPA + akc) * 2);
    const uint32_t aoff_lo = smb + GRUSM_ALO + (uint32_t)(((mh * 16 + arow) * ROWPA + akc) * 2);
    const int brow8 = lane & 7;
    const int bg01  = (lane >> 4) & 1;
    const int bkc   = ((lane >> 3) & 1) * 8;
    const int bj01  = bg01 * 32 + hw + brow8;
    const uint32_t b01_hi = smb + GRUSM_WHI + (uint32_t)((bj01 * ROWPA + bkc) * 2);
    const uint32_t b01_lo = smb + GRUSM_WLO + (uint32_t)((bj01 * ROWPA + bkc) * 2);
    const int l15 = lane & 15;
    const int bj2 = 64 + hw + (l15 & 7);
    const int bkc2 = ((l15 >> 3) & 1) * 8;
    const uint32_t b2_hi = smb + GRUSM_WHI + (uint32_t)((bj2 * ROWPA + bkc2) * 2);
    const uint32_t b2_lo = smb + GRUSM_WLO + (uint32_t)((bj2 * ROWPA + bkc2) * 2);

    const int dr = lane >> 2;
    const int dc = (lane & 3) * 2;
    const int hcol = h0t + hw + dc;

    const float2 bh_r = *(const float2*)(bhh + 0 * HD + hcol);
    const float2 bh_z = *(const float2*)(bhh + 1 * HD + hcol);
    const float2 bh_n = *(const float2*)(bhh + 2 * HD + hcol);
    float2 gx0r = make_float2(0.f, 0.f), gx0z = gx0r, gx0n = gx0r;
    if (LAYER == 0) {
        gx0r = *(const float2*)(g_gx0 + 0 * HD + hcol);
        gx0z = *(const float2*)(g_gx0 + 1 * HD + hcol);
        gx0n = *(const float2*)(g_gx0 + 2 * HD + hcol);
    }
    __syncthreads();

    int* __restrict__ bar = &g_bar[LAYER][bj];

    for (int t = 0; t < TT; t++) {
        const float* h_in = (t == 0) ? g_h0 : ((t & 1) ? g_hA : g_hB);
        float* h_out = (t & 1) ? g_hB : g_hA;

        #pragma unroll
        for (int q = 0; q < 8; q++) {
            int l = tid + q * 256;
            int row = l >> 6, kq = l & 63;
            float4 v = __ldcg((const float4*)(h_in + (size_t)(b0t + row) * HD + 4 * kq));
            __nv_bfloat16 h0, h1, h2, h3, l0, l1, l2, l3;
            split_hl(v.x, h0, l0); split_hl(v.y, h1, l1);
            split_hl(v.z, h2, l2); split_hl(v.w, h3, l3);
            char* dh = smraw + GRUSM_AHI + ((size_t)row * ROWPA + 4 * kq) * 2;
            char* dl = smraw + GRUSM_ALO + ((size_t)row * ROWPA + 4 * kq) * 2;
            ((__nv_bfloat162*)dh)[0] = __halves2bfloat162(h0, h1);
            ((__nv_bfloat162*)dh)[1] = __halves2bfloat162(h2, h3);
            ((__nv_bfloat162*)dl)[0] = __halves2bfloat162(l0, l1);
            ((__nv_bfloat162*)dl)[1] = __halves2bfloat162(l2, l3);
        }

        const int bA = b0t + mh * 16 + dr;
        const int bB = bA + 8;
        float2 hpA, hpB;
        {
            hpA = __ldcg((const float2*)(h_in + (size_t)bA * HD + hcol));
            hpB = __ldcg((const float2*)(h_in + (size_t)bB * HD + hcol));
        }
        float2 gAr, gAz, gAn, gBr, gBz, gBn;
        if (LAYER == 1) {
            const float* pA = g_gx1 + ((size_t)bA * TT + t) * G3 + hcol;
            const float* pB = g_gx1 + ((size_t)bB * TT + t) * G3 + hcol;
            gAr = *(const float2*)(pA);  gAz = *(const float2*)(pA + HD);  gAn = *(const float2*)(pA + 2 * HD);
            gBr = *(const float2*)(pB);  gBz = *(const float2*)(pB + HD);  gBn = *(const float2*)(pB + 2 * HD);
        } else {
            gAr = gBr = gx0r; gAz = gBz = gx0z; gAn = gBn = gx0n;
        }
        __syncthreads();

        float acc0[4] = {0.f, 0.f, 0.f, 0.f};
        float acc1[4] = {0.f, 0.f, 0.f, 0.f};
        float acc2[4] = {0.f, 0.f, 0.f, 0.f};
        #pragma unroll
        for (int ks = 0; ks < 16; ks++) {
            uint32_t ah[4], al[4], w01h[4], w01l[4], w2h[2], w2l[2];
            ldm_x4(ah, aoff_hi + ks * 32);
            ldm_x4(al, aoff_lo + ks * 32);
            ldm_x4(w01h, b01_hi + ks * 32);
            ldm_x4(w01l, b01_lo + ks * 32);
            ldm_x2(w2h, b2_hi + ks * 32);
            ldm_x2(w2l, b2_lo + ks * 32);
            mma_bf16(acc0, ah, w01h);
            mma_bf16(acc0, al, w01h);
            mma_bf16(acc0, ah, w01l);
            mma_bf16(acc1, ah, w01h + 2);
            mma_bf16(acc1, al, w01h + 2);
            mma_bf16(acc1, ah, w01l + 2);
            mma_bf16(acc2, ah, w2h);
            mma_bf16(acc2, al, w2h);
            mma_bf16(acc2, ah, w2l);
        }

        #pragma unroll
        for (int rh = 0; rh < 2; rh++) {
            int b = rh ? bB : bA;
            float2 hp = rh ? hpB : hpA;
            float2 gr = rh ? gBr : gAr;
            float2 gz = rh ? gBz : gAz;
            float2 gn = rh ? gBn : gAn;
            float ar0 = rh ? acc0[2] : acc0[0], ar1 = rh ? acc0[3] : acc0[1];
            float az0 = rh ? acc1[2] : acc1[0], az1 = rh ? acc1[3] : acc1[1];
            float an0 = rh ? acc2[2] : acc2[0], an1 = rh ? acc2[3] : acc2[1];
            float r0 = sigmoidf_(gr.x + ar0 + bh_r.x);
            float r1 = sigmoidf_(gr.y + ar1 + bh_r.y);
            float u0 = sigmoidf_(gz.x + az0 + bh_z.x);
            float u1 = sigmoidf_(gz.y + az1 + bh_z.y);
            float n0 = tanhf(gn.x + r0 * (an0 + bh_n.x));
            float n1 = tanhf(gn.y + r1 * (an1 + bh_n.y));
            float hn0 = (1.f - u0) * n0 + u0 * hp.x;
            float hn1 = (1.f - u1) * n1 + u1 * hp.y;
            *(float2*)(h_out + (size_t)b * HD + hcol) = make_float2(hn0, hn1);
            size_t p = ((size_t)b * TT + t) * HD + hcol;
            if (LAYER == 0) {
                __nv_bfloat16 hh0, ll0, hh1, ll1;
                split_hl(hn0, hh0, ll0);
                split_hl(hn1, hh1, ll1);
                *(__nv_bfloat162*)(g_out0_hi + p) = __halves2bfloat162(hh0, hh1);
                *(__nv_bfloat162*)(g_out0_lo + p) = __halves2bfloat162(ll0, ll1);
            } else {
                *(float2*)(g_act + p) = make_float2(hn0, hn1);
            }
        }

        if (t < TT - 1) {
            __threadfence();
            __syncthreads();
            if (tid == 0) {
                atomicAdd(bar, 1);
                int target = 8 * (t + 1);
                while (ld_acq(bar) < target) { }
            }
            __syncthreads();
        }
    }
}

// ---------------- LayerNorm + ELU -> fp16 hi/lo ----------------
__global__ __launch_bounds__(256) void ln_elu(const float* __restrict__ gamma,
                                              const float* __restrict__ beta)
{
    int warp = threadIdx.x >> 5, lane = threadIdx.x & 31;
    size_t row = (size_t)blockIdx.x * 8 + warp;
    const float* x = g_act + row * HD;
    float v[8];
    #pragma unroll
    for (int i = 0; i < 8; i++) v[i] = x[lane + 32 * i];
    float s = 0.f;
    #pragma unroll
    for (int i = 0; i < 8; i++) s += v[i];
    #pragma unroll
    for (int o = 16; o > 0; o >>= 1) s += __shfl_xor_sync(0xffffffffu, s, o);
    float mu = s * (1.0f / 256.0f);
    float q = 0.f;
    #pragma unroll
    for (int i = 0; i < 8; i++) { float dl = v[i] - mu; q += dl * dl; }
    #pragma unroll
    for (int o = 16; o > 0; o >>= 1) q += __shfl_xor_sync(0xffffffffu, q, o);
    float inv = rsqrtf(q * (1.0f / 256.0f) + 1e-5f);
    #pragma unroll
    for (int i = 0; i < 8; i++) {
        int h = lane + 32 * i;
        float y = eluf_((v[i] - mu) * inv * gamma[h] + beta[h]);
        __half hb, lb;
        split_hlh(y, hb, lb);
        g_act_hi[row * HD + h] = hb;
        g_act_lo[row * HD + h] = lb;
    }
}

// ---------------- mma.sync GEMM, CTA 128x256, warp 64x64 ----------------
// MODE 0: bf16 3-term (gx1): phases Ahi*Bhi, Alo*Bhi, Ahi*Blo, NCH=24
// MODE 1: fp16 2-term (logits): Ahi*W, Alo*W, NCH=16
// 8 warps (2m x 4n) of 64x64, 4-stage cp.async, K-chunk 32.
#define ROWP 40
#define ASTG_B 0
#define BSTG_B (128 * ROWP * 2)            // 10240
#define STG_BYTES (BSTG_B + 256 * ROWP * 2) // 30720
#define GEMM_SMEM (4 * STG_BYTES)           // 122880

__device__ __forceinline__ void ld_chunk2(uint32_t smbase, int stage,
                                          const uint16_t* __restrict__ A0,
                                          const uint16_t* __restrict__ A1,
                                          const uint16_t* __restrict__ B0,
                                          const uint16_t* __restrict__ B2,
                                          int m0, int n0, int N, int c, int tid, int nch)
{
    if (c < nch) {
        int p = c >> 3, k0 = (c & 7) * 32;
        const uint16_t* A = (p == 1) ? A1 : A0;
        const uint16_t* B = (p == 2) ? B2 : B0;
        uint32_t stg = smbase + stage * STG_BYTES;
        #pragma unroll
        for (int q = 0; q < 2; q++) {
            int i = tid + q * 256;           // 512 = 128 rows x 4 segs
            int row = i >> 2, seg = i & 3;
            uint32_t soff = (uint32_t)(row * ROWP + seg * 8) * 2;
            cp16(stg + ASTG_B + soff, A + (size_t)(m0 + row) * HD + k0 + seg * 8, 16);
        }
        #pragma unroll
        for (int q = 0; q < 4; q++) {
            int i = tid + q * 256;           // 1024 = 256 rows x 4 segs
            int row = i >> 2, seg = i & 3;
            uint32_t soff = (uint32_t)(row * ROWP + seg * 8) * 2;
            int n = n0 + row;
            const uint16_t* bsrc = B + (size_t)(n < N ? n : 0) * HD + k0 + seg * 8;
            cp16(stg + BSTG_B + soff, bsrc, n < N ? 16 : 0);
        }
    }
    cp_commit();
}

template<int MODE>
__global__ __launch_bounds__(256, 1) void gemm_mma(const float* __restrict__ bias,
                                                   float* __restrict__ Cext, int N)
{
    extern __shared__ char smraw[];
    const uint32_t smb = s2u(smraw);

    const int tid = threadIdx.x, wid = tid >> 5, lane = tid & 31;
    const int n0 = blockIdx.x * 256;
    const int m0 = blockIdx.y * 128;
    const int mwarp = (wid & 1) * 64;
    const int nwarp = (wid >> 1) * 64;
    const int NCH = MODE ? 16 : 24;

    const uint16_t *A0, *A1, *B0, *B2;
    if (MODE == 0) {
        A0 = (const uint16_t*)g_out0_hi; A1 = (const uint16_t*)g_out0_lo;
        B0 = (const uint16_t*)g_wih1_hi; B2 = (const uint16_t*)g_wih1_lo;
    } else {
        A0 = (const uint16_t*)g_act_hi;  A1 = (const uint16_t*)g_act_lo;
        B0 = (const uint16_t*)g_wout_h;  B2 = B0;
    }
    float* C = Cext ? Cext : g_gx1;

    uint32_t aoff[4], boff[4];
    {
        int arow = (lane & 15);
        int akc  = (lane >> 4) * 8;
        #pragma unroll
        for (int mf = 0; mf < 4; mf++)
            aoff[mf] = (uint32_t)(((mwarp + mf * 16 + arow) * ROWP + akc) * 2);
        int brow = (lane & 7) + ((lane >> 4) & 1) * 8;
        int bkc  = ((lane >> 3) & 1) * 8;
        #pragma unroll
        for (int nf2 = 0; nf2 < 4; nf2++)
            boff[nf2] = (uint32_t)(BSTG_B + ((nwarp + nf2 * 16 + brow) * ROWP + bkc) * 2);
    }

    const int dr = lane >> 2;
    const int dc = (lane & 3) * 2;
    float acc[4][8][4];
    #pragma unroll
    for (int nf = 0; nf < 8; nf++) {
        int n = n0 + nwarp + nf * 8 + dc;
        float b0 = (n < N) ? bias[n] : 0.f;
        float b1 = (n + 1 < N) ? bias[n + 1] : 0.f;
        #pragma unroll
        for (int mf = 0; mf < 4; mf++) {
            acc[mf][nf][0] = b0; acc[mf][nf][1] = b1;
            acc[mf][nf][2] = b0; acc[mf][nf][3] = b1;
        }
    }

    #pragma unroll
    for (int c = 0; c < 3; c++)
        ld_chunk2(smb, c, A0, A1, B0, B2, m0, n0, N, c, tid, NCH);

    for (int c = 0; c < NCH; c++) {
        asm volatile("cp.async.wait_group 2;" ::: "memory");
        __syncthreads();
        ld_chunk2(smb, (c + 3) & 3, A0, A1, B0, B2, m0, n0, N, c + 3, tid, NCH);

        uint32_t stg = smb + (c & 3) * STG_BYTES;
        #pragma unroll
        for (int kk = 0; kk < 2; kk++) {
            uint32_t af[4][4], bf[4][4];
            #pragma unroll
            for (int mf = 0; mf < 4; mf++) ldm_x4(af[mf], stg + aoff[mf] + kk * 32);
            #pragma unroll
            for (int nf2 = 0; nf2 < 4; nf2++) ldm_x4(bf[nf2], stg + boff[nf2] + kk * 32);
            #pragma unroll
            for (int mf = 0; mf < 4; mf++)
                #pragma unroll
                for (int nf = 0; nf < 8; nf++) {
                    if (MODE == 0) mma_bf16(acc[mf][nf], af[mf], &bf[nf >> 1][(nf & 1) * 2]);
                    else           mma_f16 (acc[mf][nf], af[mf], &bf[nf >> 1][(nf & 1) * 2]);
                }
        }
        __syncthreads();
    }

    #pragma unroll
    for (int mf = 0; mf < 4; mf++) {
        int m = m0 + mwarp + mf * 16 + dr;
        #pragma unroll
        for (int nf = 0; nf < 8; nf++) {
            int n = n0 + nwarp + nf * 8 + dc;
            if (n < N) {
                *(float2*)(C + (size_t)m * N + n)       = make_float2(acc[mf][nf][0], acc[mf][nf][1]);
                *(float2*)(C + (size_t)(m + 8) * N + n) = make_float2(acc[mf][nf][2], acc[mf][nf][3]);
            }
        }
    }
}

// ---------------- launch ----------------
extern "C" void kernel_launch(void* const* d_in, const int* in_sizes, int n_in,
                              void* d_out, int out_size)
{
    const float* z         = (const float*)d_in[0];
    const float* W_init    = (const float*)d_in[1];
    const float* b_init    = (const float*)d_in[2];
    const float* embedding = (const float*)d_in[3];
    const float* W_ih0     = (const float*)d_in[4];
    const float* W_hh0     = (const float*)d_in[5];
    const float* b_ih0     = (const float*)d_in[6];
    const float* b_hh0     = (const float*)d_in[7];
    const float* W_ih1     = (const float*)d_in[8];
    const float* W_hh1     = (const float*)d_in[9];
    const float* b_ih1     = (const float*)d_in[10];
    const float* b_hh1     = (const float*)d_in[11];
    const float* ln_g      = (const float*)d_in[12];
    const float* ln_b      = (const float*)d_in[13];
    const float* W_out     = (const float*)d_in[14];
    const float* b_out     = (const float*)d_in[15];
    float* out = (float*)d_out;

    (void)in_sizes; (void)n_in; (void)out_size;

    static bool attr_done = false;
    if (!attr_done) {
        cudaFuncSetAttribute(gru_layer<0>, cudaFuncAttributeMaxDynamicSharedMemorySize, GRU_SMEM);
        cudaFuncSetAttribute(gru_layer<1>, cudaFuncAttributeMaxDynamicSharedMemorySize, GRU_SMEM);
        cudaFuncSetAttribute(gemm_mma<0>, cudaFuncAttributeMaxDynamicSharedMemorySize, GEMM_SMEM);
        cudaFuncSetAttribute(gemm_mma<1>, cudaFuncAttributeMaxDynamicSharedMemorySize, GEMM_SMEM);
        attr_done = true;
    }

    zero_bar<<<1, 32>>>();
    k_h0<<<BATCH, 256>>>(z, W_init, b_init);
    k_gx0<<<3, 256>>>(embedding, W_ih0, b_ih0);
    cvt_split<<<(G3 * HD / 4 + 255) / 256, 256>>>(W_ih1, G3 * HD / 4);
    cvt_half<<<(PD * HD / 4 + 255) / 256, 256>>>(W_out, PD * HD / 4);

    // layer 0 recurrence (tensor-core GRU, writes bf16 hi/lo outputs)
    gru_layer<0><<<dim3(8, 16), 256, GRU_SMEM>>>(W_hh0, b_hh0);

    // gx1 = out0 @ W_ih1^T + b_ih1  (32768 x 768), bf16 3-term
    gemm_mma<0><<<dim3(G3 / 256, BT / 128), 256, GEMM_SMEM>>>(b_ih1, nullptr, G3);

    // layer 1 recurrence (writes g_act fp32)
    gru_layer<1><<<dim3(8, 16), 256, GRU_SMEM>>>(W_hh1, b_hh1);

    // LN + ELU -> fp16 hi/lo
    ln_elu<<<BT / 8, 256>>>(ln_g, ln_b);

    // logits = act @ W_out^T + b_out  (32768 x 10000), fp16 2-term
    gemm_mma<1><<<dim3((PD + 255) / 256, BT / 128), 256, GEMM_SMEM>>>(b_out, out, PD);
}

// round 13
// speedup vs baseline: 5.9713x; 1.3435x over previous
#include <cuda_runtime.h>
#include <cuda_bf16.h>
#include <cuda_fp16.h>
#include <math.h>
#include <stdint.h>

// Problem dims
#define BATCH 512
#define ZD    64
#define HD    256
#define TT    64
#define PD    10000
#define G3    768
#define BT    32768

// ---------------- device scratch ----------------
__device__ __align__(256) float g_h0[BATCH * HD];
__device__ __align__(256) float g_hA[BATCH * HD];
__device__ __align__(256) float g_hB[BATCH * HD];
__device__ __align__(256) __nv_bfloat16 g_out0_hi[(size_t)BT * HD];
__device__ __align__(256) __nv_bfloat16 g_out0_lo[(size_t)BT * HD];
__device__ __align__(256) float g_act[(size_t)BT * HD];
__device__ __align__(256) __half g_act_hi[(size_t)BT * HD];
__device__ __align__(256) float g_gx1[(size_t)BT * G3];
__device__ __align__(256) float g_gx0[G3];
__device__ __align__(256) __nv_bfloat16 g_wih1_hi[G3 * HD];
__device__ __align__(256) __nv_bfloat16 g_wih1_lo[G3 * HD];
__device__ __align__(256) __half g_wout_h[(size_t)PD * HD];
__device__ int g_bar[2][16];

// ---------------- generic helpers ----------------
__device__ __forceinline__ int ld_acq(const int* p) {
    int v;
    asm volatile("ld.global.acquire.gpu.b32 %0,[%1];" : "=r"(v) : "l"(p));
    return v;
}
__device__ __forceinline__ float sigmoidf_(float x) { return 1.0f / (1.0f + expf(-x)); }
__device__ __forceinline__ float eluf_(float x)     { return x > 0.f ? x : expm1f(x); }

__device__ __forceinline__ void split_hl(float x, __nv_bfloat16& h, __nv_bfloat16& l) {
    h = __float2bfloat16(x);
    l = __float2bfloat16(x - __bfloat162float(h));
}

__device__ __forceinline__ uint32_t s2u(const void* p) {
    uint32_t a;
    asm("{ .reg .u64 t; cvta.to.shared.u64 t, %1; cvt.u32.u64 %0, t; }" : "=r"(a) : "l"(p));
    return a;
}

// ---------------- mma.sync building blocks (sm_80-baseline) ----------------
__device__ __forceinline__ void cp16(uint32_t dst, const void* src, int srcbytes) {
    asm volatile("cp.async.cg.shared.global [%0], [%1], 16, %2;"
                 :: "r"(dst), "l"(src), "r"(srcbytes) : "memory");
}
__device__ __forceinline__ void cp_commit() {
    asm volatile("cp.async.commit_group;" ::: "memory");
}
__device__ __forceinline__ void ldm_x4(uint32_t* r, uint32_t addr) {
    asm volatile("ldmatrix.sync.aligned.m8n8.x4.shared.b16 {%0,%1,%2,%3}, [%4];"
                 : "=r"(r[0]), "=r"(r[1]), "=r"(r[2]), "=r"(r[3]) : "r"(addr));
}
__device__ __forceinline__ void ldm_x2(uint32_t* r, uint32_t addr) {
    asm volatile("ldmatrix.sync.aligned.m8n8.x2.shared.b16 {%0,%1}, [%2];"
                 : "=r"(r[0]), "=r"(r[1]) : "r"(addr));
}
__device__ __forceinline__ void mma_bf16(float* d, const uint32_t* a, const uint32_t* b) {
    asm volatile("mma.sync.aligned.m16n8k16.row.col.f32.bf16.bf16.f32 "
                 "{%0,%1,%2,%3}, {%4,%5,%6,%7}, {%8,%9}, {%0,%1,%2,%3};"
                 : "+f"(d[0]), "+f"(d[1]), "+f"(d[2]), "+f"(d[3])
                 : "r"(a[0]), "r"(a[1]), "r"(a[2]), "r"(a[3]), "r"(b[0]), "r"(b[1]));
}
__device__ __forceinline__ void mma_f16(float* d, const uint32_t* a, const uint32_t* b) {
    asm volatile("mma.sync.aligned.m16n8k16.row.col.f32.f16.f16.f32 "
                 "{%0,%1,%2,%3}, {%4,%5,%6,%7}, {%8,%9}, {%0,%1,%2,%3};"
                 : "+f"(d[0]), "+f"(d[1]), "+f"(d[2]), "+f"(d[3])
                 : "r"(a[0]), "r"(a[1]), "r"(a[2]), "r"(a[3]), "r"(b[0]), "r"(b[1]));
}

// ---------------- init kernels ----------------
__global__ void zero_bar() {
    if (threadIdx.x < 32) ((int*)g_bar)[threadIdx.x] = 0;
}

__global__ __launch_bounds__(256) void k_h0(const float* __restrict__ z,
                                            const float* __restrict__ Wi,
                                            const float* __restrict__ bi)
{
    __shared__ float zs[ZD];
    int b = blockIdx.x;
    int h = threadIdx.x;
    if (threadIdx.x < ZD) zs[threadIdx.x] = z[(size_t)b * ZD + threadIdx.x];
    __syncthreads();
    float s = bi[h];
    const float* wr = Wi + (size_t)h * ZD;
    #pragma unroll 16
    for (int k = 0; k < ZD; k++) s += zs[k] * wr[k];
    g_h0[(size_t)b * HD + h] = eluf_(s);
}

__global__ __launch_bounds__(256) void k_gx0(const float* __restrict__ emb,
                                             const float* __restrict__ Wih0,
                                             const float* __restrict__ bih0)
{
    __shared__ float es[HD];
    es[threadIdx.x] = emb[threadIdx.x];
    __syncthreads();
    int j = blockIdx.x * 256 + threadIdx.x;
    float s = bih0[j];
    const float* wr = Wih0 + (size_t)j * HD;
    #pragma unroll 16
    for (int k = 0; k < HD; k++) s += es[k] * wr[k];
    g_gx0[j] = s;
}

// bf16 hi/lo splitter for W_ih1
__global__ __launch_bounds__(256) void cvt_split(const float* __restrict__ src, int n4)
{
    int i = blockIdx.x * 256 + threadIdx.x;
    if (i < n4) {
        float4 v = ((const float4*)src)[i];
        __nv_bfloat16 h0, h1, h2, h3, l0, l1, l2, l3;
        split_hl(v.x, h0, l0); split_hl(v.y, h1, l1);
        split_hl(v.z, h2, l2); split_hl(v.w, h3, l3);
        ((__nv_bfloat162*)g_wih1_hi)[2 * i]     = __halves2bfloat162(h0, h1);
        ((__nv_bfloat162*)g_wih1_hi)[2 * i + 1] = __halves2bfloat162(h2, h3);
        ((__nv_bfloat162*)g_wih1_lo)[2 * i]     = __halves2bfloat162(l0, l1);
        ((__nv_bfloat162*)g_wih1_lo)[2 * i + 1] = __halves2bfloat162(l2, l3);
    }
}

// fp16 single-round converter for W_out
__global__ __launch_bounds__(256) void cvt_half(const float* __restrict__ src, int n4)
{
    int i = blockIdx.x * 256 + threadIdx.x;
    if (i < n4) {
        float4 v = ((const float4*)src)[i];
        ((__half2*)g_wout_h)[2 * i]     = __halves2half2(__float2half_rn(v.x), __float2half_rn(v.y));
        ((__half2*)g_wout_h)[2 * i + 1] = __halves2half2(__float2half_rn(v.z), __float2half_rn(v.w));
    }
}

// ---------------- persistent GRU layer (tensor-core) ----------------
#define ROWPA 264
#define GRUSM_WHI 0
#define GRUSM_WLO (96 * ROWPA * 2)
#define GRUSM_AHI (2 * 96 * ROWPA * 2)
#define GRUSM_ALO (2 * 96 * ROWPA * 2 + 32 * ROWPA * 2)
#define GRU_SMEM  (2 * 96 * ROWPA * 2 + 2 * 32 * ROWPA * 2)   // 135168 B

template<int LAYER>
__global__ __launch_bounds__(256, 1) void gru_layer(const float* __restrict__ Whh,
                                                    const float* __restrict__ bhh)
{
    extern __shared__ char smraw[];
    const uint32_t smb = s2u(smraw);

    const int tid = threadIdx.x, wid = tid >> 5, lane = tid & 31;
    const int h0t = blockIdx.x * 32;
    const int bj  = blockIdx.y;
    const int b0t = bj * 32;

    // stage Whh slice as bf16 hi/lo, layout [j=g*32+hloc][k]
    #pragma unroll
    for (int q = 0; q < 24; q++) {
        int l = tid + q * 256;
        int j = l >> 6, kq = l & 63;
        int g = j >> 5, hloc = j & 31;
        float4 v = *(const float4*)(Whh + (size_t)(g * HD + h0t + hloc) * HD + 4 * kq);
        __nv_bfloat16 h0, h1, h2, h3, l0, l1, l2, l3;
        split_hl(v.x, h0, l0); split_hl(v.y, h1, l1);
        split_hl(v.z, h2, l2); split_hl(v.w, h3, l3);
        char* dh = smraw + GRUSM_WHI + ((size_t)j * ROWPA + 4 * kq) * 2;
        char* dl = smraw + GRUSM_WLO + ((size_t)j * ROWPA + 4 * kq) * 2;
        ((__nv_bfloat162*)dh)[0] = __halves2bfloat162(h0, h1);
        ((__nv_bfloat162*)dh)[1] = __halves2bfloat162(h2, h3);
        ((__nv_bfloat162*)dl)[0] = __halves2bfloat162(l0, l1);
        ((__nv_bfloat162*)dl)[1] = __halves2bfloat162(l2, l3);
    }

    const int mh = wid & 1;
    const int hw = (wid >> 1) * 8;
    const int arow = lane & 15, akc = (lane >> 4) * 8;
    const uint32_t aoff_hi = smb + GRUSM_AHI + (uint32_t)(((mh * 16 + arow) * ROWPA + akc) * 2);
    const uint32_t aoff_lo = smb + GRUSM_ALO + (uint32_t)(((mh * 16 + arow) * ROWPA + akc) * 2);
    const int brow8 = lane & 7;
    const int bg01  = (lane >> 4) & 1;
    const int bkc   = ((lane >> 3) & 1) * 8;
    const int bj01  = bg01 * 32 + hw + brow8;
    const uint32_t b01_hi = smb + GRUSM_WHI + (uint32_t)((bj01 * ROWPA + bkc) * 2);
    const uint32_t b01_lo = smb + GRUSM_WLO + (uint32_t)((bj01 * ROWPA + bkc) * 2);
    const int l15 = lane & 15;
    const int bj2 = 64 + hw + (l15 & 7);
    const int bkc2 = ((l15 >> 3) & 1) * 8;
    const uint32_t b2_hi = smb + GRUSM_WHI + (uint32_t)((bj2 * ROWPA + bkc2) * 2);
    const uint32_t b2_lo = smb + GRUSM_WLO + (uint32_t)((bj2 * ROWPA + bkc2) * 2);

    const int dr = lane >> 2;
    const int dc = (lane & 3) * 2;
    const int hcol = h0t + hw + dc;

    const float2 bh_r = *(const float2*)(bhh + 0 * HD + hcol);
    const float2 bh_z = *(const float2*)(bhh + 1 * HD + hcol);
    const float2 bh_n = *(const float2*)(bhh + 2 * HD + hcol);
    float2 gx0r = make_float2(0.f, 0.f), gx0z = gx0r, gx0n = gx0r;
    if (LAYER == 0) {
        gx0r = *(const float2*)(g_gx0 + 0 * HD + hcol);
        gx0z = *(const float2*)(g_gx0 + 1 * HD + hcol);
        gx0n = *(const float2*)(g_gx0 + 2 * HD + hcol);
    }
    __syncthreads();

    int* __restrict__ bar = &g_bar[LAYER][bj];

    for (int t = 0; t < TT; t++) {
        const float* h_in = (t == 0) ? g_h0 : ((t & 1) ? g_hA : g_hB);
        float* h_out = (t & 1) ? g_hB : g_hA;

        #pragma unroll
        for (int q = 0; q < 8; q++) {
            int l = tid + q * 256;
            int row = l >> 6, kq = l & 63;
            float4 v = __ldcg((const float4*)(h_in + (size_t)(b0t + row) * HD + 4 * kq));
            __nv_bfloat16 h0, h1, h2, h3, l0, l1, l2, l3;
            split_hl(v.x, h0, l0); split_hl(v.y, h1, l1);
            split_hl(v.z, h2, l2); split_hl(v.w, h3, l3);
            char* dh = smraw + GRUSM_AHI + ((size_t)row * ROWPA + 4 * kq) * 2;
            char* dl = smraw + GRUSM_ALO + ((size_t)row * ROWPA + 4 * kq) * 2;
            ((__nv_bfloat162*)dh)[0] = __halves2bfloat162(h0, h1);
            ((__nv_bfloat162*)dh)[1] = __halves2bfloat162(h2, h3);
            ((__nv_bfloat162*)dl)[0] = __halves2bfloat162(l0, l1);
            ((__nv_bfloat162*)dl)[1] = __halves2bfloat162(l2, l3);
        }

        const int bA = b0t + mh * 16 + dr;
        const int bB = bA + 8;
        float2 hpA, hpB;
        {
            hpA = __ldcg((const float2*)(h_in + (size_t)bA * HD + hcol));
            hpB = __ldcg((const float2*)(h_in + (size_t)bB * HD + hcol));
        }
        float2 gAr, gAz, gAn, gBr, gBz, gBn;
        if (LAYER == 1) {
            const float* pA = g_gx1 + ((size_t)bA * TT + t) * G3 + hcol;
            const float* pB = g_gx1 + ((size_t)bB * TT + t) * G3 + hcol;
            gAr = *(const float2*)(pA);  gAz = *(const float2*)(pA + HD);  gAn = *(const float2*)(pA + 2 * HD);
            gBr = *(const float2*)(pB);  gBz = *(const float2*)(pB + HD);  gBn = *(const float2*)(pB + 2 * HD);
        } else {
            gAr = gBr = gx0r; gAz = gBz = gx0z; gAn = gBn = gx0n;
        }
        __syncthreads();

        float acc0[4] = {0.f, 0.f, 0.f, 0.f};
        float acc1[4] = {0.f, 0.f, 0.f, 0.f};
        float acc2[4] = {0.f, 0.f, 0.f, 0.f};
        #pragma unroll
        for (int ks = 0; ks < 16; ks++) {
            uint32_t ah[4], al[4], w01h[4], w01l[4], w2h[2], w2l[2];
            ldm_x4(ah, aoff_hi + ks * 32);
            ldm_x4(al, aoff_lo + ks * 32);
            ldm_x4(w01h, b01_hi + ks * 32);
            ldm_x4(w01l, b01_lo + ks * 32);
            ldm_x2(w2h, b2_hi + ks * 32);
            ldm_x2(w2l, b2_lo + ks * 32);
            mma_bf16(acc0, ah, w01h);
            mma_bf16(acc0, al, w01h);
            mma_bf16(acc0, ah, w01l);
            mma_bf16(acc1, ah, w01h + 2);
            mma_bf16(acc1, al, w01h + 2);
            mma_bf16(acc1, ah, w01l + 2);
            mma_bf16(acc2, ah, w2h);
            mma_bf16(acc2, al, w2h);
            mma_bf16(acc2, ah, w2l);
        }

        #pragma unroll
        for (int rh = 0; rh < 2; rh++) {
            int b = rh ? bB : bA;
            float2 hp = rh ? hpB : hpA;
            float2 gr = rh ? gBr : gAr;
            float2 gz = rh ? gBz : gAz;
            float2 gn = rh ? gBn : gAn;
            float ar0 = rh ? acc0[2] : acc0[0], ar1 = rh ? acc0[3] : acc0[1];
            float az0 = rh ? acc1[2] : acc1[0], az1 = rh ? acc1[3] : acc1[1];
            float an0 = rh ? acc2[2] : acc2[0], an1 = rh ? acc2[3] : acc2[1];
            float r0 = sigmoidf_(gr.x + ar0 + bh_r.x);
            float r1 = sigmoidf_(gr.y + ar1 + bh_r.y);
            float u0 = sigmoidf_(gz.x + az0 + bh_z.x);
            float u1 = sigmoidf_(gz.y + az1 + bh_z.y);
            float n0 = tanhf(gn.x + r0 * (an0 + bh_n.x));
            float n1 = tanhf(gn.y + r1 * (an1 + bh_n.y));
            float hn0 = (1.f - u0) * n0 + u0 * hp.x;
            float hn1 = (1.f - u1) * n1 + u1 * hp.y;
            *(float2*)(h_out + (size_t)b * HD + hcol) = make_float2(hn0, hn1);
            size_t p = ((size_t)b * TT + t) * HD + hcol;
            if (LAYER == 0) {
                __nv_bfloat16 hh0, ll0, hh1, ll1;
                split_hl(hn0, hh0, ll0);
                split_hl(hn1, hh1, ll1);
                *(__nv_bfloat162*)(g_out0_hi + p) = __halves2bfloat162(hh0, hh1);
                *(__nv_bfloat162*)(g_out0_lo + p) = __halves2bfloat162(ll0, ll1);
            } else {
                *(float2*)(g_act + p) = make_float2(hn0, hn1);
            }
        }

        if (t < TT - 1) {
            __threadfence();
            __syncthreads();
            if (tid == 0) {
                atomicAdd(bar, 1);
                int target = 8 * (t + 1);
                while (ld_acq(bar) < target) { }
            }
            __syncthreads();
        }
    }
}

// ---------------- LayerNorm + ELU -> fp16 (single plane) ----------------
__global__ __launch_bounds__(256) void ln_elu(const float* __restrict__ gamma,
                                              const float* __restrict__ beta)
{
    int warp = threadIdx.x >> 5, lane = threadIdx.x & 31;
    size_t row = (size_t)blockIdx.x * 8 + warp;
    const float* x = g_act + row * HD;
    float v[8];
    #pragma unroll
    for (int i = 0; i < 8; i++) v[i] = x[lane + 32 * i];
    float s = 0.f;
    #pragma unroll
    for (int i = 0; i < 8; i++) s += v[i];
    #pragma unroll
    for (int o = 16; o > 0; o >>= 1) s += __shfl_xor_sync(0xffffffffu, s, o);
    float mu = s * (1.0f / 256.0f);
    float q = 0.f;
    #pragma unroll
    for (int i = 0; i < 8; i++) { float dl = v[i] - mu; q += dl * dl; }
    #pragma unroll
    for (int o = 16; o > 0; o >>= 1) q += __shfl_xor_sync(0xffffffffu, q, o);
    float inv = rsqrtf(q * (1.0f / 256.0f) + 1e-5f);
    #pragma unroll
    for (int i = 0; i < 8; i++) {
        int h = lane + 32 * i;
        float y = eluf_((v[i] - mu) * inv * gamma[h] + beta[h]);
        g_act_hi[row * HD + h] = __float2half_rn(y);
    }
}

// ---------------- mma.sync GEMM, CTA 128x256, warp 64x64 ----------------
// MODE 0: bf16 3-term (gx1): phases Ahi*Bhi, Alo*Bhi, Ahi*Blo, NCH=24
// MODE 1: fp16 1-term (logits): A*W, NCH=8
// 8 warps (2m x 4n) of 64x64, 4-stage cp.async, K-chunk 32.
#define ROWP 40
#define ASTG_B 0
#define BSTG_B (128 * ROWP * 2)             // 10240
#define STG_BYTES (BSTG_B + 256 * ROWP * 2) // 30720
#define GEMM_SMEM (4 * STG_BYTES)           // 122880

__device__ __forceinline__ void ld_chunk2(uint32_t smbase, int stage,
                                          const uint16_t* __restrict__ A0,
                                          const uint16_t* __restrict__ A1,
                                          const uint16_t* __restrict__ B0,
                                          const uint16_t* __restrict__ B2,
                                          int m0, int n0, int N, int c, int tid, int nch)
{
    if (c < nch) {
        int p = c >> 3, k0 = (c & 7) * 32;
        const uint16_t* A = (p == 1) ? A1 : A0;
        const uint16_t* B = (p == 2) ? B2 : B0;
        uint32_t stg = smbase + stage * STG_BYTES;
        #pragma unroll
        for (int q = 0; q < 2; q++) {
            int i = tid + q * 256;
            int row = i >> 2, seg = i & 3;
            uint32_t soff = (uint32_t)(row * ROWP + seg * 8) * 2;
            cp16(stg + ASTG_B + soff, A + (size_t)(m0 + row) * HD + k0 + seg * 8, 16);
        }
        #pragma unroll
        for (int q = 0; q < 4; q++) {
            int i = tid + q * 256;
            int row = i >> 2, seg = i & 3;
            uint32_t soff = (uint32_t)(row * ROWP + seg * 8) * 2;
            int n = n0 + row;
            const uint16_t* bsrc = B + (size_t)(n < N ? n : 0) * HD + k0 + seg * 8;
            cp16(stg + BSTG_B + soff, bsrc, n < N ? 16 : 0);
        }
    }
    cp_commit();
}

template<int MODE>
__global__ __launch_bounds__(256, 1) void gemm_mma(const float* __restrict__ bias,
                                                   float* __restrict__ Cext, int N)
{
    extern __shared__ char smraw[];
    const uint32_t smb = s2u(smraw);

    const int tid = threadIdx.x, wid = tid >> 5, lane = tid & 31;
    const int n0 = blockIdx.x * 256;
    const int m0 = blockIdx.y * 128;
    const int mwarp = (wid & 1) * 64;
    const int nwarp = (wid >> 1) * 64;
    const int NCH = MODE ? 8 : 24;

    const uint16_t *A0, *A1, *B0, *B2;
    if (MODE == 0) {
        A0 = (const uint16_t*)g_out0_hi; A1 = (const uint16_t*)g_out0_lo;
        B0 = (const uint16_t*)g_wih1_hi; B2 = (const uint16_t*)g_wih1_lo;
    } else {
        A0 = (const uint16_t*)g_act_hi;  A1 = A0;
        B0 = (const uint16_t*)g_wout_h;  B2 = B0;
    }
    float* C = Cext ? Cext : g_gx1;

    uint32_t aoff[4], boff[4];
    {
        int arow = (lane & 15);
        int akc  = (lane >> 4) * 8;
        #pragma unroll
        for (int mf = 0; mf < 4; mf++)
            aoff[mf] = (uint32_t)(((mwarp + mf * 16 + arow) * ROWP + akc) * 2);
        int brow = (lane & 7) + ((lane >> 4) & 1) * 8;
        int bkc  = ((lane >> 3) & 1) * 8;
        #pragma unroll
        for (int nf2 = 0; nf2 < 4; nf2++)
            boff[nf2] = (uint32_t)(BSTG_B + ((nwarp + nf2 * 16 + brow) * ROWP + bkc) * 2);
    }

    const int dr = lane >> 2;
    const int dc = (lane & 3) * 2;
    float acc[4][8][4];
    #pragma unroll
    for (int nf = 0; nf < 8; nf++) {
        int n = n0 + nwarp + nf * 8 + dc;
        float b0 = (n < N) ? bias[n] : 0.f;
        float b1 = (n + 1 < N) ? bias[n + 1] : 0.f;
        #pragma unroll
        for (int mf = 0; mf < 4; mf++) {
            acc[mf][nf][0] = b0; acc[mf][nf][1] = b1;
            acc[mf][nf][2] = b0; acc[mf][nf][3] = b1;
        }
    }

    #pragma unroll
    for (int c = 0; c < 3; c++)
        ld_chunk2(smb, c, A0, A1, B0, B2, m0, n0, N, c, tid, NCH);

    for (int c = 0; c < NCH; c++) {
        asm volatile("cp.async.wait_group 2;" ::: "memory");
        __syncthreads();
        ld_chunk2(smb, (c + 3) & 3, A0, A1, B0, B2, m0, n0, N, c + 3, tid, NCH);

        uint32_t stg = smb + (c & 3) * STG_BYTES;
        #pragma unroll
        for (int kk = 0; kk < 2; kk++) {
            uint32_t af[4][4], bf[4][4];
            #pragma unroll
            for (int mf = 0; mf < 4; mf++) ldm_x4(af[mf], stg + aoff[mf] + kk * 32);
            #pragma unroll
            for (int nf2 = 0; nf2 < 4; nf2++) ldm_x4(bf[nf2], stg + boff[nf2] + kk * 32);
            #pragma unroll
            for (int mf = 0; mf < 4; mf++)
                #pragma unroll
                for (int nf = 0; nf < 8; nf++) {
                    if (MODE == 0) mma_bf16(acc[mf][nf], af[mf], &bf[nf >> 1][(nf & 1) * 2]);
                    else           mma_f16 (acc[mf][nf], af[mf], &bf[nf >> 1][(nf & 1) * 2]);
                }
        }
        __syncthreads();
    }

    #pragma unroll
    for (int mf = 0; mf < 4; mf++) {
        int m = m0 + mwarp + mf * 16 + dr;
        #pragma unroll
        for (int nf = 0; nf < 8; nf++) {
            int n = n0 + nwarp + nf * 8 + dc;
            if (n < N) {
                *(float2*)(C + (size_t)m * N + n)       = make_float2(acc[mf][nf][0], acc[mf][nf][1]);
                *(float2*)(C + (size_t)(m + 8) * N + n) = make_float2(acc[mf][nf][2], acc[mf][nf][3]);
            }
        }
    }
}

// ---------------- launch ----------------
extern "C" void kernel_launch(void* const* d_in, const int* in_sizes, int n_in,
                              void* d_out, int out_size)
{
    const float* z         = (const float*)d_in[0];
    const float* W_init    = (const float*)d_in[1];
    const float* b_init    = (const float*)d_in[2];
    const float* embedding = (const float*)d_in[3];
    const float* W_ih0     = (const float*)d_in[4];
    const float* W_hh0     = (const float*)d_in[5];
    const float* b_ih0     = (const float*)d_in[6];
    const float* b_hh0     = (const float*)d_in[7];
    const float* W_ih1     = (const float*)d_in[8];
    const float* W_hh1     = (const float*)d_in[9];
    const float* b_ih1     = (const float*)d_in[10];
    const float* b_hh1     = (const float*)d_in[11];
    const float* ln_g      = (const float*)d_in[12];
    const float* ln_b      = (const float*)d_in[13];
    const float* W_out     = (const float*)d_in[14];
    const float* b_out     = (const float*)d_in[15];
    float* out = (float*)d_out;

    (void)in_sizes; (void)n_in; (void)out_size;

    static bool attr_done = false;
    if (!attr_done) {
        cudaFuncSetAttribute(gru_layer<0>, cudaFuncAttributeMaxDynamicSharedMemorySize, GRU_SMEM);
        cudaFuncSetAttribute(gru_layer<1>, cudaFuncAttributeMaxDynamicSharedMemorySize, GRU_SMEM);
        cudaFuncSetAttribute(gemm_mma<0>, cudaFuncAttributeMaxDynamicSharedMemorySize, GEMM_SMEM);
        cudaFuncSetAttribute(gemm_mma<1>, cudaFuncAttributeMaxDynamicSharedMemorySize, GEMM_SMEM);
        attr_done = true;
    }

    zero_bar<<<1, 32>>>();
    k_h0<<<BATCH, 256>>>(z, W_init, b_init);
    k_gx0<<<3, 256>>>(embedding, W_ih0, b_ih0);
    cvt_split<<<(G3 * HD / 4 + 255) / 256, 256>>>(W_ih1, G3 * HD / 4);
    cvt_half<<<(PD * HD / 4 + 255) / 256, 256>>>(W_out, PD * HD / 4);

    // layer 0 recurrence (tensor-core GRU, writes bf16 hi/lo outputs)
    gru_layer<0><<<dim3(8, 16), 256, GRU_SMEM>>>(W_hh0, b_hh0);

    // gx1 = out0 @ W_ih1^T + b_ih1  (32768 x 768), bf16 3-term
    gemm_mma<0><<<dim3(G3 / 256, BT / 128), 256, GEMM_SMEM>>>(b_ih1, nullptr, G3);

    // layer 1 recurrence (writes g_act fp32)
    gru_layer<1><<<dim3(8, 16), 256, GRU_SMEM>>>(W_hh1, b_hh1);

    // LN + ELU -> fp16
    ln_elu<<<BT / 8, 256>>>(ln_g, ln_b);

    // logits = act @ W_out^T + b_out  (32768 x 10000), fp16 1-term
    gemm_mma<1><<<dim3((PD + 255) / 256, BT / 128), 256, GEMM_SMEM>>>(b_out, out, PD);
}

// round 15
// speedup vs baseline: 6.2491x; 1.0465x over previous
#include <cuda_runtime.h>
#include <cuda_bf16.h>
#include <cuda_fp16.h>
#include <math.h>
#include <stdint.h>

// Problem dims
#define BATCH 512
#define ZD    64
#define HD    256
#define TT    64
#define PD    10000
#define G3    768
#define BT    32768

// ---------------- device scratch ----------------
__device__ __align__(256) float g_h0[BATCH * HD];
__device__ __align__(256) float g_hA[BATCH * HD];
__device__ __align__(256) float g_hB[BATCH * HD];
__device__ __align__(256) __half g_out0_h[(size_t)BT * HD];     // layer0 outputs, fp16 (gx1 A)
__device__ __align__(256) float g_act[(size_t)BT * HD];
__device__ __align__(256) __half g_act_hi[(size_t)BT * HD];     // LN+ELU outputs, fp16 (logits A)
__device__ __align__(256) float g_gx1[(size_t)BT * G3];
__device__ __align__(256) float g_gx0[G3];
__device__ __align__(256) __half g_wih1_h[G3 * HD];
__device__ __align__(256) __half g_wout_h[(size_t)PD * HD];
// h planes: slots 0/1 = step ping-pong, slot 2 = h0 seed (never overwritten)
__device__ __align__(256) __nv_bfloat16 g_hbf_hi[3][BATCH * HD];
__device__ __align__(256) __nv_bfloat16 g_hbf_lo[3][BATCH * HD];
__device__ int g_bar[2][16];

// ---------------- generic helpers ----------------
__device__ __forceinline__ int ld_acq(const int* p) {
    int v;
    asm volatile("ld.global.acquire.gpu.b32 %0,[%1];" : "=r"(v) : "l"(p));
    return v;
}
__device__ __forceinline__ float sigmoidf_(float x) { return 1.0f / (1.0f + expf(-x)); }
__device__ __forceinline__ float eluf_(float x)     { return x > 0.f ? x : expm1f(x); }

__device__ __forceinline__ void split_hl(float x, __nv_bfloat16& h, __nv_bfloat16& l) {
    h = __float2bfloat16(x);
    l = __float2bfloat16(x - __bfloat162float(h));
}

__device__ __forceinline__ uint32_t s2u(const void* p) {
    uint32_t a;
    asm("{ .reg .u64 t; cvta.to.shared.u64 t, %1; cvt.u32.u64 %0, t; }" : "=r"(a) : "l"(p));
    return a;
}

// ---------------- mma.sync building blocks (sm_80-baseline) ----------------
__device__ __forceinline__ void cp16(uint32_t dst, const void* src, int srcbytes) {
    asm volatile("cp.async.cg.shared.global [%0], [%1], 16, %2;"
                 :: "r"(dst), "l"(src), "r"(srcbytes) : "memory");
}
__device__ __forceinline__ void cp_commit() {
    asm volatile("cp.async.commit_group;" ::: "memory");
}
__device__ __forceinline__ void ldm_x4(uint32_t* r, uint32_t addr) {
    asm volatile("ldmatrix.sync.aligned.m8n8.x4.shared.b16 {%0,%1,%2,%3}, [%4];"
                 : "=r"(r[0]), "=r"(r[1]), "=r"(r[2]), "=r"(r[3]) : "r"(addr));
}
__device__ __forceinline__ void ldm_x2(uint32_t* r, uint32_t addr) {
    asm volatile("ldmatrix.sync.aligned.m8n8.x2.shared.b16 {%0,%1}, [%2];"
                 : "=r"(r[0]), "=r"(r[1]) : "r"(addr));
}
__device__ __forceinline__ void mma_bf16(float* d, const uint32_t* a, const uint32_t* b) {
    asm volatile("mma.sync.aligned.m16n8k16.row.col.f32.bf16.bf16.f32 "
                 "{%0,%1,%2,%3}, {%4,%5,%6,%7}, {%8,%9}, {%0,%1,%2,%3};"
                 : "+f"(d[0]), "+f"(d[1]), "+f"(d[2]), "+f"(d[3])
                 : "r"(a[0]), "r"(a[1]), "r"(a[2]), "r"(a[3]), "r"(b[0]), "r"(b[1]));
}
__device__ __forceinline__ void mma_f16(float* d, const uint32_t* a, const uint32_t* b) {
    asm volatile("mma.sync.aligned.m16n8k16.row.col.f32.f16.f16.f32 "
                 "{%0,%1,%2,%3}, {%4,%5,%6,%7}, {%8,%9}, {%0,%1,%2,%3};"
                 : "+f"(d[0]), "+f"(d[1]), "+f"(d[2]), "+f"(d[3])
                 : "r"(a[0]), "r"(a[1]), "r"(a[2]), "r"(a[3]), "r"(b[0]), "r"(b[1]));
}

// ---------------- init kernels ----------------
__global__ void zero_bar() {
    if (threadIdx.x < 32) ((int*)g_bar)[threadIdx.x] = 0;
}

// h0 = ELU(z @ W_init^T + b_init); seeds the h0 plane slot 2 (read by both layers at t=0)
__global__ __launch_bounds__(256) void k_h0(const float* __restrict__ z,
                                            const float* __restrict__ Wi,
                                            const float* __restrict__ bi)
{
    __shared__ float zs[ZD];
    int b = blockIdx.x;
    int h = threadIdx.x;
    if (threadIdx.x < ZD) zs[threadIdx.x] = z[(size_t)b * ZD + threadIdx.x];
    __syncthreads();
    float s = bi[h];
    const float* wr = Wi + (size_t)h * ZD;
    #pragma unroll 16
    for (int k = 0; k < ZD; k++) s += zs[k] * wr[k];
    float hv = eluf_(s);
    g_h0[(size_t)b * HD + h] = hv;
    __nv_bfloat16 hh, ll;
    split_hl(hv, hh, ll);
    g_hbf_hi[2][(size_t)b * HD + h] = hh;
    g_hbf_lo[2][(size_t)b * HD + h] = ll;
}

__global__ __launch_bounds__(256) void k_gx0(const float* __restrict__ emb,
                                             const float* __restrict__ Wih0,
                                             const float* __restrict__ bih0)
{
    __shared__ float es[HD];
    es[threadIdx.x] = emb[threadIdx.x];
    __syncthreads();
    int j = blockIdx.x * 256 + threadIdx.x;
    float s = bih0[j];
    const float* wr = Wih0 + (size_t)j * HD;
    #pragma unroll 16
    for (int k = 0; k < HD; k++) s += es[k] * wr[k];
    g_gx0[j] = s;
}

// fp16 converter. dsel: 0 -> wih1, 1 -> wout
__global__ __launch_bounds__(256) void cvt_half(const float* __restrict__ src, int dsel, int n4)
{
    __half* dst = dsel ? g_wout_h : g_wih1_h;
    int i = blockIdx.x * 256 + threadIdx.x;
    if (i < n4) {
        float4 v = ((const float4*)src)[i];
        ((__half2*)dst)[2 * i]     = __halves2half2(__float2half_rn(v.x), __float2half_rn(v.y));
        ((__half2*)dst)[2 * i + 1] = __halves2half2(__float2half_rn(v.z), __float2half_rn(v.w));
    }
}

// ---------------- persistent GRU layer (tensor-core) ----------------
#define ROWPA 264
#define GRUSM_WHI 0
#define GRUSM_WLO (96 * ROWPA * 2)
#define GRUSM_AHI (2 * 96 * ROWPA * 2)
#define GRUSM_ALO (2 * 96 * ROWPA * 2 + 32 * ROWPA * 2)
#define GRU_SMEM  (2 * 96 * ROWPA * 2 + 2 * 32 * ROWPA * 2)   // 135168 B

template<int LAYER>
__global__ __launch_bounds__(256, 1) void gru_layer(const float* __restrict__ Whh,
                                                    const float* __restrict__ bhh)
{
    extern __shared__ char smraw[];
    const uint32_t smb = s2u(smraw);

    const int tid = threadIdx.x, wid = tid >> 5, lane = tid & 31;
    const int h0t = blockIdx.x * 32;
    const int bj  = blockIdx.y;
    const int b0t = bj * 32;

    // stage Whh slice as bf16 hi/lo, layout [j=g*32+hloc][k]
    #pragma unroll
    for (int q = 0; q < 24; q++) {
        int l = tid + q * 256;
        int j = l >> 6, kq = l & 63;
        int g = j >> 5, hloc = j & 31;
        float4 v = *(const float4*)(Whh + (size_t)(g * HD + h0t + hloc) * HD + 4 * kq);
        __nv_bfloat16 h0, h1, h2, h3, l0, l1, l2, l3;
        split_hl(v.x, h0, l0); split_hl(v.y, h1, l1);
        split_hl(v.z, h2, l2); split_hl(v.w, h3, l3);
        char* dh = smraw + GRUSM_WHI + ((size_t)j * ROWPA + 4 * kq) * 2;
        char* dl = smraw + GRUSM_WLO + ((size_t)j * ROWPA + 4 * kq) * 2;
        ((__nv_bfloat162*)dh)[0] = __halves2bfloat162(h0, h1);
        ((__nv_bfloat162*)dh)[1] = __halves2bfloat162(h2, h3);
        ((__nv_bfloat162*)dl)[0] = __halves2bfloat162(l0, l1);
        ((__nv_bfloat162*)dl)[1] = __halves2bfloat162(l2, l3);
    }

    const int mh = wid & 1;
    const int hw = (wid >> 1) * 8;
    const int arow = lane & 15, akc = (lane >> 4) * 8;
    const uint32_t aoff_hi = smb + GRUSM_AHI + (uint32_t)(((mh * 16 + arow) * ROWPA + akc) * 2);
    const uint32_t aoff_lo = smb + GRUSM_ALO + (uint32_t)(((mh * 16 + arow) * ROWPA + akc) * 2);
    const int brow8 = lane & 7;
    const int bg01  = (lane >> 4) & 1;
    const int bkc   = ((lane >> 3) & 1) * 8;
    const int bj01  = bg01 * 32 + hw + brow8;
    const uint32_t b01_hi = smb + GRUSM_WHI + (uint32_t)((bj01 * ROWPA + bkc) * 2);
    const uint32_t b01_lo = smb + GRUSM_WLO + (uint32_t)((bj01 * ROWPA + bkc) * 2);
    const int l15 = lane & 15;
    const int bj2 = 64 + hw + (l15 & 7);
    const int bkc2 = ((l15 >> 3) & 1) * 8;
    const uint32_t b2_hi = smb + GRUSM_WHI + (uint32_t)((bj2 * ROWPA + bkc2) * 2);
    const uint32_t b2_lo = smb + GRUSM_WLO + (uint32_t)((bj2 * ROWPA + bkc2) * 2);

    const int dr = lane >> 2;
    const int dc = (lane & 3) * 2;
    const int hcol = h0t + hw + dc;

    const float2 bh_r = *(const float2*)(bhh + 0 * HD + hcol);
    const float2 bh_z = *(const float2*)(bhh + 1 * HD + hcol);
    const float2 bh_n = *(const float2*)(bhh + 2 * HD + hcol);
    float2 gx0r = make_float2(0.f, 0.f), gx0z = gx0r, gx0n = gx0r;
    if (LAYER == 0) {
        gx0r = *(const float2*)(g_gx0 + 0 * HD + hcol);
        gx0z = *(const float2*)(g_gx0 + 1 * HD + hcol);
        gx0n = *(const float2*)(g_gx0 + 2 * HD + hcol);
    }
    __syncthreads();

    int* __restrict__ bar = &g_bar[LAYER][bj];

    for (int t = 0; t < TT; t++) {
        const float* h_in = (t == 0) ? g_h0 : ((t & 1) ? g_hA : g_hB);
        float* h_out = (t & 1) ? g_hB : g_hA;

        // ---- stage h tile straight from pre-split bf16 planes via cp.async ----
        // t=0 reads h0 seed (slot 2); t>0 reads slot written at t-1 = (t-1)&1 = (t+1)&1
        {
            const int slot = (t == 0) ? 2 : ((t + 1) & 1);
            const __nv_bfloat16* shi = g_hbf_hi[slot];
            const __nv_bfloat16* slo = g_hbf_lo[slot];
            #pragma unroll
            for (int q = 0; q < 4; q++) {
                int l = tid + q * 256;           // 1024 = 32 rows x 32 segs of 8 elems
                int row = l >> 5, seg = l & 31;
                uint32_t soff = (uint32_t)(row * ROWPA + seg * 8) * 2;
                const size_t goff = (size_t)(b0t + row) * HD + seg * 8;
                cp16(smb + GRUSM_AHI + soff, shi + goff, 16);
                cp16(smb + GRUSM_ALO + soff, slo + goff, 16);
            }
            cp_commit();
        }

        // ---- per-lane gate inputs + h_prev (overlap with cp.async) ----
        const int bA = b0t + mh * 16 + dr;
        const int bB = bA + 8;
        float2 hpA = __ldcg((const float2*)(h_in + (size_t)bA * HD + hcol));
        float2 hpB = __ldcg((const float2*)(h_in + (size_t)bB * HD + hcol));
        float2 gAr, gAz, gAn, gBr, gBz, gBn;
        if (LAYER == 1) {
            const float* pA = g_gx1 + ((size_t)bA * TT + t) * G3 + hcol;
            const float* pB = g_gx1 + ((size_t)bB * TT + t) * G3 + hcol;
            gAr = *(const float2*)(pA);  gAz = *(const float2*)(pA + HD);  gAn = *(const float2*)(pA + 2 * HD);
            gBr = *(const float2*)(pB);  gBz = *(const float2*)(pB + HD);  gBn = *(const float2*)(pB + 2 * HD);
        } else {
            gAr = gBr = gx0r; gAz = gBz = gx0z; gAn = gBn = gx0n;
        }
        asm volatile("cp.async.wait_group 0;" ::: "memory");
        __syncthreads();

        float acc0[4] = {0.f, 0.f, 0.f, 0.f};
        float acc1[4] = {0.f, 0.f, 0.f, 0.f};
        float acc2[4] = {0.f, 0.f, 0.f, 0.f};
        #pragma unroll
        for (int ks = 0; ks < 16; ks++) {
            uint32_t ah[4], al[4], w01h[4], w01l[4], w2h[2], w2l[2];
            ldm_x4(ah, aoff_hi + ks * 32);
            ldm_x4(al, aoff_lo + ks * 32);
            ldm_x4(w01h, b01_hi + ks * 32);
            ldm_x4(w01l, b01_lo + ks * 32);
            ldm_x2(w2h, b2_hi + ks * 32);
            ldm_x2(w2l, b2_lo + ks * 32);
            mma_bf16(acc0, ah, w01h);
            mma_bf16(acc0, al, w01h);
            mma_bf16(acc0, ah, w01l);
            mma_bf16(acc1, ah, w01h + 2);
            mma_bf16(acc1, al, w01h + 2);
            mma_bf16(acc1, ah, w01l + 2);
            mma_bf16(acc2, ah, w2h);
            mma_bf16(acc2, al, w2h);
            mma_bf16(acc2, ah, w2l);
        }

        #pragma unroll
        for (int rh = 0; rh < 2; rh++) {
            int b = rh ? bB : bA;
            float2 hp = rh ? hpB : hpA;
            float2 gr = rh ? gBr : gAr;
            float2 gz = rh ? gBz : gAz;
            float2 gn = rh ? gBn : gAn;
            float ar0 = rh ? acc0[2] : acc0[0], ar1 = rh ? acc0[3] : acc0[1];
            float az0 = rh ? acc1[2] : acc1[0], az1 = rh ? acc1[3] : acc1[1];
            float an0 = rh ? acc2[2] : acc2[0], an1 = rh ? acc2[3] : acc2[1];
            float r0 = sigmoidf_(gr.x + ar0 + bh_r.x);
            float r1 = sigmoidf_(gr.y + ar1 + bh_r.y);
            float u0 = sigmoidf_(gz.x + az0 + bh_z.x);
            float u1 = sigmoidf_(gz.y + az1 + bh_z.y);
            float n0 = tanhf(gn.x + r0 * (an0 + bh_n.x));
            float n1 = tanhf(gn.y + r1 * (an1 + bh_n.y));
            float hn0 = (1.f - u0) * n0 + u0 * hp.x;
            float hn1 = (1.f - u1) * n1 + u1 * hp.y;
            size_t hoff = (size_t)b * HD + hcol;
            *(float2*)(h_out + hoff) = make_float2(hn0, hn1);
            // pre-split bf16 planes for next step's staging (slot t&1)
            __nv_bfloat16 hh0, ll0, hh1, ll1;
            split_hl(hn0, hh0, ll0);
            split_hl(hn1, hh1, ll1);
            *(__nv_bfloat162*)(g_hbf_hi[t & 1] + hoff) = __halves2bfloat162(hh0, hh1);
            *(__nv_bfloat162*)(g_hbf_lo[t & 1] + hoff) = __halves2bfloat162(ll0, ll1);
            size_t p = ((size_t)b * TT + t) * HD + hcol;
            if (LAYER == 0) {
                *(__half2*)(g_out0_h + p) = __halves2half2(__float2half_rn(hn0), __float2half_rn(hn1));
            } else {
                *(float2*)(g_act + p) = make_float2(hn0, hn1);
            }
        }

        if (t < TT - 1) {
            __threadfence();
            __syncthreads();
            if (tid == 0) {
                atomicAdd(bar, 1);
                int target = 8 * (t + 1);
                while (ld_acq(bar) < target) { }
            }
            __syncthreads();
        }
    }
}

// ---------------- LayerNorm + ELU -> fp16 ----------------
__global__ __launch_bounds__(256) void ln_elu(const float* __restrict__ gamma,
                                              const float* __restrict__ beta)
{
    int warp = threadIdx.x >> 5, lane = threadIdx.x & 31;
    size_t row = (size_t)blockIdx.x * 8 + warp;
    const float* x = g_act + row * HD;
    float v[8];
    #pragma unroll
    for (int i = 0; i < 8; i++) v[i] = x[lane + 32 * i];
    float s = 0.f;
    #pragma unroll
    for (int i = 0; i < 8; i++) s += v[i];
    #pragma unroll
    for (int o = 16; o > 0; o >>= 1) s += __shfl_xor_sync(0xffffffffu, s, o);
    float mu = s * (1.0f / 256.0f);
    float q = 0.f;
    #pragma unroll
    for (int i = 0; i < 8; i++) { float dl = v[i] - mu; q += dl * dl; }
    #pragma unroll
    for (int o = 16; o > 0; o >>= 1) q += __shfl_xor_sync(0xffffffffu, q, o);
    float inv = rsqrtf(q * (1.0f / 256.0f) + 1e-5f);
    #pragma unroll
    for (int i = 0; i < 8; i++) {
        int h = lane + 32 * i;
        float y = eluf_((v[i] - mu) * inv * gamma[h] + beta[h]);
        g_act_hi[row * HD + h] = __float2half_rn(y);
    }
}

// ---------------- mma.sync fp16 GEMM, CTA 128x256, warp 64x64, NCH=8 ----------------
// MODE 0: gx1 = out0 @ W_ih1^T   MODE 1: logits = act @ W_out^T
#define ROWP 40
#define ASTG_B 0
#define BSTG_B (128 * ROWP * 2)             // 10240
#define STG_BYTES (BSTG_B + 256 * ROWP * 2) // 30720
#define GEMM_SMEM (4 * STG_BYTES)           // 122880
#define NCH 8

__device__ __forceinline__ void ld_chunkF(uint32_t smbase, int stage,
                                          const uint16_t* __restrict__ A,
                                          const uint16_t* __restrict__ B,
                                          int m0, int n0, int N, int c, int tid)
{
    if (c < NCH) {
        int k0 = c * 32;
        uint32_t stg = smbase + stage * STG_BYTES;
        #pragma unroll
        for (int q = 0; q < 2; q++) {
            int i = tid + q * 256;
            int row = i >> 2, seg = i & 3;
            uint32_t soff = (uint32_t)(row * ROWP + seg * 8) * 2;
            cp16(stg + ASTG_B + soff, A + (size_t)(m0 + row) * HD + k0 + seg * 8, 16);
        }
        #pragma unroll
        for (int q = 0; q < 4; q++) {
            int i = tid + q * 256;
            int row = i >> 2, seg = i & 3;
            uint32_t soff = (uint32_t)(row * ROWP + seg * 8) * 2;
            int n = n0 + row;
            const uint16_t* bsrc = B + (size_t)(n < N ? n : 0) * HD + k0 + seg * 8;
            cp16(stg + BSTG_B + soff, bsrc, n < N ? 16 : 0);
        }
    }
    cp_commit();
}

template<int MODE>
__global__ __launch_bounds__(256, 1) void gemm_mma(const float* __restrict__ bias,
                                                   float* __restrict__ Cext, int N)
{
    extern __shared__ char smraw[];
    const uint32_t smb = s2u(smraw);

    const int tid = threadIdx.x, wid = tid >> 5, lane = tid & 31;
    const int n0 = blockIdx.x * 256;
    const int m0 = blockIdx.y * 128;
    const int mwarp = (wid & 1) * 64;
    const int nwarp = (wid >> 1) * 64;

    const uint16_t* A0 = MODE ? (const uint16_t*)g_act_hi : (const uint16_t*)g_out0_h;
    const uint16_t* B0 = MODE ? (const uint16_t*)g_wout_h : (const uint16_t*)g_wih1_h;
    float* C = Cext ? Cext : g_gx1;

    uint32_t aoff[4], boff[4];
    {
        int arow = (lane & 15);
        int akc  = (lane >> 4) * 8;
        #pragma unroll
        for (int mf = 0; mf < 4; mf++)
            aoff[mf] = (uint32_t)(((mwarp + mf * 16 + arow) * ROWP + akc) * 2);
        int brow = (lane & 7) + ((lane >> 4) & 1) * 8;
        int bkc  = ((lane >> 3) & 1) * 8;
        #pragma unroll
        for (int nf2 = 0; nf2 < 4; nf2++)
            boff[nf2] = (uint32_t)(BSTG_B + ((nwarp + nf2 * 16 + brow) * ROWP + bkc) * 2);
    }

    const int dr = lane >> 2;
    const int dc = (lane & 3) * 2;
    float acc[4][8][4];
    #pragma unroll
    for (int nf = 0; nf < 8; nf++) {
        int n = n0 + nwarp + nf * 8 + dc;
        float b0 = (n < N) ? bias[n] : 0.f;
        float b1 = (n + 1 < N) ? bias[n + 1] : 0.f;
        #pragma unroll
        for (int mf = 0; mf < 4; mf++) {
            acc[mf][nf][0] = b0; acc[mf][nf][1] = b1;
            acc[mf][nf][2] = b0; acc[mf][nf][3] = b1;
        }
    }

    #pragma unroll
    for (int c = 0; c < 3; c++)
        ld_chunkF(smb, c, A0, B0, m0, n0, N, c, tid);

    for (int c = 0; c < NCH; c++) {
        asm volatile("cp.async.wait_group 2;" ::: "memory");
        __syncthreads();
        ld_chunkF(smb, (c + 3) & 3, A0, B0, m0, n0, N, c + 3, tid);

        uint32_t stg = smb + (c & 3) * STG_BYTES;
        #pragma unroll
        for (int kk = 0; kk < 2; kk++) {
            uint32_t af[4][4], bf[4][4];
            #pragma unroll
            for (int mf = 0; mf < 4; mf++) ldm_x4(af[mf], stg + aoff[mf] + kk * 32);
            #pragma unroll
            for (int nf2 = 0; nf2 < 4; nf2++) ldm_x4(bf[nf2], stg + boff[nf2] + kk * 32);
            #pragma unroll
            for (int mf = 0; mf < 4; mf++)
                #pragma unroll
                for (int nf = 0; nf < 8; nf++)
                    mma_f16(acc[mf][nf], af[mf], &bf[nf >> 1][(nf & 1) * 2]);
        }
        __syncthreads();
    }

    #pragma unroll
    for (int mf = 0; mf < 4; mf++) {
        int m = m0 + mwarp + mf * 16 + dr;
        #pragma unroll
        for (int nf = 0; nf < 8; nf++) {
            int n = n0 + nwarp + nf * 8 + dc;
            if (n < N) {
                *(float2*)(C + (size_t)m * N + n)       = make_float2(acc[mf][nf][0], acc[mf][nf][1]);
                *(float2*)(C + (size_t)(m + 8) * N + n) = make_float2(acc[mf][nf][2], acc[mf][nf][3]);
            }
        }
    }
}

// ---------------- launch ----------------
extern "C" void kernel_launch(void* const* d_in, const int* in_sizes, int n_in,
                              void* d_out, int out_size)
{
    const float* z         = (const float*)d_in[0];
    const float* W_init    = (const float*)d_in[1];
    const float* b_init    = (const float*)d_in[2];
    const float* embedding = (const float*)d_in[3];
    const float* W_ih0     = (const float*)d_in[4];
    const float* W_hh0     = (const float*)d_in[5];
    const float* b_ih0     = (const float*)d_in[6];
    const float* b_hh0     = (const float*)d_in[7];
    const float* W_ih1     = (const float*)d_in[8];
    const float* W_hh1     = (const float*)d_in[9];
    const float* b_ih1     = (const float*)d_in[10];
    const float* b_hh1     = (const float*)d_in[11];
    const float* ln_g      = (const float*)d_in[12];
    const float* ln_b      = (const float*)d_in[13];
    const float* W_out     = (const float*)d_in[14];
    const float* b_out     = (const float*)d_in[15];
    float* out = (float*)d_out;

    (void)in_sizes; (void)n_in; (void)out_size;

    static bool attr_done = false;
    if (!attr_done) {
        cudaFuncSetAttribute(gru_layer<0>, cudaFuncAttributeMaxDynamicSharedMemorySize, GRU_SMEM);
        cudaFuncSetAttribute(gru_layer<1>, cudaFuncAttributeMaxDynamicSharedMemorySize, GRU_SMEM);
        cudaFuncSetAttribute(gemm_mma<0>, cudaFuncAttributeMaxDynamicSharedMemorySize, GEMM_SMEM);
        cudaFuncSetAttribute(gemm_mma<1>, cudaFuncAttributeMaxDynamicSharedMemorySize, GEMM_SMEM);
        attr_done = true;
    }

    zero_bar<<<1, 32>>>();
    k_h0<<<BATCH, 256>>>(z, W_init, b_init);
    k_gx0<<<3, 256>>>(embedding, W_ih0, b_ih0);
    cvt_half<<<(G3 * HD / 4 + 255) / 256, 256>>>(W_ih1, 0, G3 * HD / 4);
    cvt_half<<<(PD * HD / 4 + 255) / 256, 256>>>(W_out, 1, PD * HD / 4);

    // layer 0 recurrence (tensor-core GRU, writes fp16 out0 + bf16 h planes)
    gru_layer<0><<<dim3(8, 16), 256, GRU_SMEM>>>(W_hh0, b_hh0);

    // gx1 = out0 @ W_ih1^T + b_ih1  (32768 x 768), fp16 1-term
    gemm_mma<0><<<dim3(G3 / 256, BT / 128), 256, GEMM_SMEM>>>(b_ih1, nullptr, G3);

    // layer 1 recurrence (writes g_act fp32 + bf16 h planes)
    gru_layer<1><<<dim3(8, 16), 256, GRU_SMEM>>>(W_hh1, b_hh1);

    // LN + ELU -> fp16
    ln_elu<<<BT / 8, 256>>>(ln_g, ln_b);

    // logits = act @ W_out^T + b_out  (32768 x 10000), fp16 1-term
    gemm_mma<1><<<dim3((PD + 255) / 256, BT / 128), 256, GEMM_SMEM>>>(b_out, out, PD);
}

// round 16
// speedup vs baseline: 6.3850x; 1.0217x over previous
#include <cuda_runtime.h>
#include <cuda_bf16.h>
#include <cuda_fp16.h>
#include <math.h>
#include <stdint.h>

// Problem dims
#define BATCH 512
#define ZD    64
#define HD    256
#define TT    64
#define PD    10000
#define G3    768
#define BT    32768

// ---------------- device scratch ----------------
__device__ __align__(256) __half g_out0_h[(size_t)BT * HD];     // layer0 outputs, fp16 (gx1 A)
__device__ __align__(256) float g_act[(size_t)BT * HD];
__device__ __align__(256) __half g_act_hi[(size_t)BT * HD];     // LN+ELU outputs, fp16 (logits A)
__device__ __align__(256) __half g_gx1h[(size_t)BT * G3];       // input gates for layer1, fp16
__device__ __align__(256) float g_gx0[G3];
__device__ __align__(256) __half g_wih1_h[G3 * HD];
__device__ __align__(256) __half g_wout_h[(size_t)PD * HD];
// h planes: slots 0/1 = step ping-pong, slot 2 = h0 seed (never overwritten)
__device__ __align__(256) __nv_bfloat16 g_hbf_hi[3][BATCH * HD];
__device__ __align__(256) __nv_bfloat16 g_hbf_lo[3][BATCH * HD];
__device__ int g_bar[2][16];

// ---------------- generic helpers ----------------
__device__ __forceinline__ int ld_acq(const int* p) {
    int v;
    asm volatile("ld.global.acquire.gpu.b32 %0,[%1];" : "=r"(v) : "l"(p));
    return v;
}
__device__ __forceinline__ float sigmoidf_(float x) { return 1.0f / (1.0f + expf(-x)); }
__device__ __forceinline__ float eluf_(float x)     { return x > 0.f ? x : expm1f(x); }

__device__ __forceinline__ void split_hl(float x, __nv_bfloat16& h, __nv_bfloat16& l) {
    h = __float2bfloat16(x);
    l = __float2bfloat16(x - __bfloat162float(h));
}

__device__ __forceinline__ uint32_t s2u(const void* p) {
    uint32_t a;
    asm("{ .reg .u64 t; cvta.to.shared.u64 t, %1; cvt.u32.u64 %0, t; }" : "=r"(a) : "l"(p));
    return a;
}

// ---------------- mma.sync building blocks (sm_80-baseline) ----------------
__device__ __forceinline__ void cp16(uint32_t dst, const void* src, int srcbytes) {
    asm volatile("cp.async.cg.shared.global [%0], [%1], 16, %2;"
                 :: "r"(dst), "l"(src), "r"(srcbytes) : "memory");
}
__device__ __forceinline__ void cp_commit() {
    asm volatile("cp.async.commit_group;" ::: "memory");
}
__device__ __forceinline__ void ldm_x4(uint32_t* r, uint32_t addr) {
    asm volatile("ldmatrix.sync.aligned.m8n8.x4.shared.b16 {%0,%1,%2,%3}, [%4];"
                 : "=r"(r[0]), "=r"(r[1]), "=r"(r[2]), "=r"(r[3]) : "r"(addr));
}
__device__ __forceinline__ void ldm_x2(uint32_t* r, uint32_t addr) {
    asm volatile("ldmatrix.sync.aligned.m8n8.x2.shared.b16 {%0,%1}, [%2];"
                 : "=r"(r[0]), "=r"(r[1]) : "r"(addr));
}
__device__ __forceinline__ void mma_bf16(float* d, const uint32_t* a, const uint32_t* b) {
    asm volatile("mma.sync.aligned.m16n8k16.row.col.f32.bf16.bf16.f32 "
                 "{%0,%1,%2,%3}, {%4,%5,%6,%7}, {%8,%9}, {%0,%1,%2,%3};"
                 : "+f"(d[0]), "+f"(d[1]), "+f"(d[2]), "+f"(d[3])
                 : "r"(a[0]), "r"(a[1]), "r"(a[2]), "r"(a[3]), "r"(b[0]), "r"(b[1]));
}
__device__ __forceinline__ void mma_f16(float* d, const uint32_t* a, const uint32_t* b) {
    asm volatile("mma.sync.aligned.m16n8k16.row.col.f32.f16.f16.f32 "
                 "{%0,%1,%2,%3}, {%4,%5,%6,%7}, {%8,%9}, {%0,%1,%2,%3};"
                 : "+f"(d[0]), "+f"(d[1]), "+f"(d[2]), "+f"(d[3])
                 : "r"(a[0]), "r"(a[1]), "r"(a[2]), "r"(a[3]), "r"(b[0]), "r"(b[1]));
}

// ---------------- init kernels ----------------
__global__ void zero_bar() {
    if (threadIdx.x < 32) ((int*)g_bar)[threadIdx.x] = 0;
}

// h0 = ELU(z @ W_init^T + b_init) -> bf16 hi/lo planes slot 2
__global__ __launch_bounds__(256) void k_h0(const float* __restrict__ z,
                                            const float* __restrict__ Wi,
                                            const float* __restrict__ bi)
{
    __shared__ float zs[ZD];
    int b = blockIdx.x;
    int h = threadIdx.x;
    if (threadIdx.x < ZD) zs[threadIdx.x] = z[(size_t)b * ZD + threadIdx.x];
    __syncthreads();
    float s = bi[h];
    const float* wr = Wi + (size_t)h * ZD;
    #pragma unroll 16
    for (int k = 0; k < ZD; k++) s += zs[k] * wr[k];
    float hv = eluf_(s);
    __nv_bfloat16 hh, ll;
    split_hl(hv, hh, ll);
    g_hbf_hi[2][(size_t)b * HD + h] = hh;
    g_hbf_lo[2][(size_t)b * HD + h] = ll;
}

__global__ __launch_bounds__(256) void k_gx0(const float* __restrict__ emb,
                                             const float* __restrict__ Wih0,
                                             const float* __restrict__ bih0)
{
    __shared__ float es[HD];
    es[threadIdx.x] = emb[threadIdx.x];
    __syncthreads();
    int j = blockIdx.x * 256 + threadIdx.x;
    float s = bih0[j];
    const float* wr = Wih0 + (size_t)j * HD;
    #pragma unroll 16
    for (int k = 0; k < HD; k++) s += es[k] * wr[k];
    g_gx0[j] = s;
}

// fp16 converter. dsel: 0 -> wih1, 1 -> wout
__global__ __launch_bounds__(256) void cvt_half(const float* __restrict__ src, int dsel, int n4)
{
    __half* dst = dsel ? g_wout_h : g_wih1_h;
    int i = blockIdx.x * 256 + threadIdx.x;
    if (i < n4) {
        float4 v = ((const float4*)src)[i];
        ((__half2*)dst)[2 * i]     = __halves2half2(__float2half_rn(v.x), __float2half_rn(v.y));
        ((__half2*)dst)[2 * i + 1] = __halves2half2(__float2half_rn(v.z), __float2half_rn(v.w));
    }
}

// ---------------- persistent GRU layer (tensor-core) ----------------
#define ROWPA 264
#define GRUSM_WHI 0
#define GRUSM_WLO (96 * ROWPA * 2)
#define GRUSM_AHI (2 * 96 * ROWPA * 2)
#define GRUSM_ALO (2 * 96 * ROWPA * 2 + 32 * ROWPA * 2)
#define GRU_SMEM  (2 * 96 * ROWPA * 2 + 2 * 32 * ROWPA * 2)   // 135168 B

template<int LAYER>
__global__ __launch_bounds__(256, 1) void gru_layer(const float* __restrict__ Whh,
                                                    const float* __restrict__ bhh)
{
    extern __shared__ char smraw[];
    const uint32_t smb = s2u(smraw);

    const int tid = threadIdx.x, wid = tid >> 5, lane = tid & 31;
    const int h0t = blockIdx.x * 32;
    const int bj  = blockIdx.y;
    const int b0t = bj * 32;

    // stage Whh slice as bf16 hi/lo, layout [j=g*32+hloc][k]
    #pragma unroll
    for (int q = 0; q < 24; q++) {
        int l = tid + q * 256;
        int j = l >> 6, kq = l & 63;
        int g = j >> 5, hloc = j & 31;
        float4 v = *(const float4*)(Whh + (size_t)(g * HD + h0t + hloc) * HD + 4 * kq);
        __nv_bfloat16 h0, h1, h2, h3, l0, l1, l2, l3;
        split_hl(v.x, h0, l0); split_hl(v.y, h1, l1);
        split_hl(v.z, h2, l2); split_hl(v.w, h3, l3);
        char* dh = smraw + GRUSM_WHI + ((size_t)j * ROWPA + 4 * kq) * 2;
        char* dl = smraw + GRUSM_WLO + ((size_t)j * ROWPA + 4 * kq) * 2;
        ((__nv_bfloat162*)dh)[0] = __halves2bfloat162(h0, h1);
        ((__nv_bfloat162*)dh)[1] = __halves2bfloat162(h2, h3);
        ((__nv_bfloat162*)dl)[0] = __halves2bfloat162(l0, l1);
        ((__nv_bfloat162*)dl)[1] = __halves2bfloat162(l2, l3);
    }

    const int mh = wid & 1;
    const int hw = (wid >> 1) * 8;
    const int arow = lane & 15, akc = (lane >> 4) * 8;
    const uint32_t aoff_hi = smb + GRUSM_AHI + (uint32_t)(((mh * 16 + arow) * ROWPA + akc) * 2);
    const uint32_t aoff_lo = smb + GRUSM_ALO + (uint32_t)(((mh * 16 + arow) * ROWPA + akc) * 2);
    const int brow8 = lane & 7;
    const int bg01  = (lane >> 4) & 1;
    const int bkc   = ((lane >> 3) & 1) * 8;
    const int bj01  = bg01 * 32 + hw + brow8;
    const uint32_t b01_hi = smb + GRUSM_WHI + (uint32_t)((bj01 * ROWPA + bkc) * 2);
    const uint32_t b01_lo = smb + GRUSM_WLO + (uint32_t)((bj01 * ROWPA + bkc) * 2);
    const int l15 = lane & 15;
    const int bj2 = 64 + hw + (l15 & 7);
    const int bkc2 = ((l15 >> 3) & 1) * 8;
    const uint32_t b2_hi = smb + GRUSM_WHI + (uint32_t)((bj2 * ROWPA + bkc2) * 2);
    const uint32_t b2_lo = smb + GRUSM_WLO + (uint32_t)((bj2 * ROWPA + bkc2) * 2);

    const int dr = lane >> 2;
    const int dc = (lane & 3) * 2;
    const int hcol = h0t + hw + dc;

    const float2 bh_r = *(const float2*)(bhh + 0 * HD + hcol);
    const float2 bh_z = *(const float2*)(bhh + 1 * HD + hcol);
    const float2 bh_n = *(const float2*)(bhh + 2 * HD + hcol);
    float2 gx0r = make_float2(0.f, 0.f), gx0z = gx0r, gx0n = gx0r;
    if (LAYER == 0) {
        gx0r = *(const float2*)(g_gx0 + 0 * HD + hcol);
        gx0z = *(const float2*)(g_gx0 + 1 * HD + hcol);
        gx0n = *(const float2*)(g_gx0 + 2 * HD + hcol);
    }
    __syncthreads();

    int* __restrict__ bar = &g_bar[LAYER][bj];
    const int bA = b0t + mh * 16 + dr;
    const int bB = bA + 8;

    for (int t = 0; t < TT; t++) {
        const int slotP = (t == 0) ? 2 : ((t + 1) & 1);

        // ---- stage h tile from pre-split bf16 planes via cp.async ----
        {
            const __nv_bfloat16* shi = g_hbf_hi[slotP];
            const __nv_bfloat16* slo = g_hbf_lo[slotP];
            #pragma unroll
            for (int q = 0; q < 4; q++) {
                int l = tid + q * 256;           // 1024 = 32 rows x 32 segs of 8 elems
                int row = l >> 5, seg = l & 31;
                uint32_t soff = (uint32_t)(row * ROWPA + seg * 8) * 2;
                const size_t goff = (size_t)(b0t + row) * HD + seg * 8;
                cp16(smb + GRUSM_AHI + soff, shi + goff, 16);
                cp16(smb + GRUSM_ALO + soff, slo + goff, 16);
            }
            cp_commit();
        }

        // ---- per-lane gate inputs + h_prev (reconstructed hi+lo) ----
        float2 hpA, hpB;
        {
            __nv_bfloat162 ahi = *(const __nv_bfloat162*)(g_hbf_hi[slotP] + (size_t)bA * HD + hcol);
            __nv_bfloat162 alo = *(const __nv_bfloat162*)(g_hbf_lo[slotP] + (size_t)bA * HD + hcol);
            __nv_bfloat162 bhi = *(const __nv_bfloat162*)(g_hbf_hi[slotP] + (size_t)bB * HD + hcol);
            __nv_bfloat162 blo = *(const __nv_bfloat162*)(g_hbf_lo[slotP] + (size_t)bB * HD + hcol);
            hpA = make_float2(__bfloat162float(ahi.x) + __bfloat162float(alo.x),
                              __bfloat162float(ahi.y) + __bfloat162float(alo.y));
            hpB = make_float2(__bfloat162float(bhi.x) + __bfloat162float(blo.x),
                              __bfloat162float(bhi.y) + __bfloat162float(blo.y));
        }
        float2 gAr, gAz, gAn, gBr, gBz, gBn;
        if (LAYER == 1) {
            const __half* pA = g_gx1h + ((size_t)bA * TT + t) * G3 + hcol;
            const __half* pB = g_gx1h + ((size_t)bB * TT + t) * G3 + hcol;
            gAr = __half22float2(*(const __half2*)(pA));
            gAz = __half22float2(*(const __half2*)(pA + HD));
            gAn = __half22float2(*(const __half2*)(pA + 2 * HD));
            gBr = __half22float2(*(const __half2*)(pB));
            gBz = __half22float2(*(const __half2*)(pB + HD));
            gBn = __half22float2(*(const __half2*)(pB + 2 * HD));
        } else {
            gAr = gBr = gx0r; gAz = gBz = gx0z; gAn = gBn = gx0n;
        }
        asm volatile("cp.async.wait_group 0;" ::: "memory");
        __syncthreads();

        float acc0[4] = {0.f, 0.f, 0.f, 0.f};
        float acc1[4] = {0.f, 0.f, 0.f, 0.f};
        float acc2[4] = {0.f, 0.f, 0.f, 0.f};
        #pragma unroll
        for (int ks = 0; ks < 16; ks++) {
            uint32_t ah[4], al[4], w01h[4], w01l[4], w2h[2], w2l[2];
            ldm_x4(ah, aoff_hi + ks * 32);
            ldm_x4(al, aoff_lo + ks * 32);
            ldm_x4(w01h, b01_hi + ks * 32);
            ldm_x4(w01l, b01_lo + ks * 32);
            ldm_x2(w2h, b2_hi + ks * 32);
            ldm_x2(w2l, b2_lo + ks * 32);
            mma_bf16(acc0, ah, w01h);
            mma_bf16(acc0, al, w01h);
            mma_bf16(acc0, ah, w01l);
            mma_bf16(acc1, ah, w01h + 2);
            mma_bf16(acc1, al, w01h + 2);
            mma_bf16(acc1, ah, w01l + 2);
            mma_bf16(acc2, ah, w2h);
            mma_bf16(acc2, al, w2h);
            mma_bf16(acc2, ah, w2l);
        }

        // ---- gate math; store planes first (peer-visible), then barrier-arrive,
        //      then the out0/act stores overlap the peer skew ----
        float hnv[2][2];
        #pragma unroll
        for (int rh = 0; rh < 2; rh++) {
            int b = rh ? bB : bA;
            float2 hp = rh ? hpB : hpA;
            float2 gr = rh ? gBr : gAr;
            float2 gz = rh ? gBz : gAz;
            float2 gn = rh ? gBn : gAn;
            float ar0 = rh ? acc0[2] : acc0[0], ar1 = rh ? acc0[3] : acc0[1];
            float az0 = rh ? acc1[2] : acc1[0], az1 = rh ? acc1[3] : acc1[1];
            float an0 = rh ? acc2[2] : acc2[0], an1 = rh ? acc2[3] : acc2[1];
            float r0 = sigmoidf_(gr.x + ar0 + bh_r.x);
            float r1 = sigmoidf_(gr.y + ar1 + bh_r.y);
            float u0 = sigmoidf_(gz.x + az0 + bh_z.x);
            float u1 = sigmoidf_(gz.y + az1 + bh_z.y);
            float n0 = tanhf(gn.x + r0 * (an0 + bh_n.x));
            float n1 = tanhf(gn.y + r1 * (an1 + bh_n.y));
            float hn0 = (1.f - u0) * n0 + u0 * hp.x;
            float hn1 = (1.f - u1) * n1 + u1 * hp.y;
            hnv[rh][0] = hn0; hnv[rh][1] = hn1;
            size_t hoff = (size_t)b * HD + hcol;
            __nv_bfloat16 hh0, ll0, hh1, ll1;
            split_hl(hn0, hh0, ll0);
            split_hl(hn1, hh1, ll1);
            *(__nv_bfloat162*)(g_hbf_hi[t & 1] + hoff) = __halves2bfloat162(hh0, hh1);
            *(__nv_bfloat162*)(g_hbf_lo[t & 1] + hoff) = __halves2bfloat162(ll0, ll1);
        }

        if (t < TT - 1) {
            __threadfence();
            __syncthreads();
            if (tid == 0) atomicAdd(bar, 1);
        }

        // layer outputs (consumed by later kernels only)
        #pragma unroll
        for (int rh = 0; rh < 2; rh++) {
            int b = rh ? bB : bA;
            size_t p = ((size_t)b * TT + t) * HD + hcol;
            if (LAYER == 0) {
                *(__half2*)(g_out0_h + p) = __halves2half2(__float2half_rn(hnv[rh][0]),
                                                           __float2half_rn(hnv[rh][1]));
            } else {
                *(float2*)(g_act + p) = make_float2(hnv[rh][0], hnv[rh][1]);
            }
        }

        if (t < TT - 1) {
            if (tid == 0) {
                int target = 8 * (t + 1);
                while (ld_acq(bar) < target) { }
            }
            __syncthreads();
        }
    }
}

// ---------------- LayerNorm + ELU -> fp16 ----------------
__global__ __launch_bounds__(256) void ln_elu(const float* __restrict__ gamma,
                                              const float* __restrict__ beta)
{
    int warp = threadIdx.x >> 5, lane = threadIdx.x & 31;
    size_t row = (size_t)blockIdx.x * 8 + warp;
    const float* x = g_act + row * HD;
    float v[8];
    #pragma unroll
    for (int i = 0; i < 8; i++) v[i] = x[lane + 32 * i];
    float s = 0.f;
    #pragma unroll
    for (int i = 0; i < 8; i++) s += v[i];
    #pragma unroll
    for (int o = 16; o > 0; o >>= 1) s += __shfl_xor_sync(0xffffffffu, s, o);
    float mu = s * (1.0f / 256.0f);
    float q = 0.f;
    #pragma unroll
    for (int i = 0; i < 8; i++) { float dl = v[i] - mu; q += dl * dl; }
    #pragma unroll
    for (int o = 16; o > 0; o >>= 1) q += __shfl_xor_sync(0xffffffffu, q, o);
    float inv = rsqrtf(q * (1.0f / 256.0f) + 1e-5f);
    #pragma unroll
    for (int i = 0; i < 8; i++) {
        int h = lane + 32 * i;
        float y = eluf_((v[i] - mu) * inv * gamma[h] + beta[h]);
        g_act_hi[row * HD + h] = __float2half_rn(y);
    }
}

// ---------------- mma.sync fp16 GEMM, CTA 128x256, warp 64x64, NCH=8 ----------------
// MODE 0: gx1 = out0 @ W_ih1^T (stores fp16)   MODE 1: logits = act @ W_out^T (stores fp32)
#define ROWP 40
#define ASTG_B 0
#define BSTG_B (128 * ROWP * 2)             // 10240
#define STG_BYTES (BSTG_B + 256 * ROWP * 2) // 30720
#define GEMM_SMEM (4 * STG_BYTES)           // 122880
#define NCH 8

__device__ __forceinline__ void ld_chunkF(uint32_t smbase, int stage,
                                          const uint16_t* __restrict__ A,
                                          const uint16_t* __restrict__ B,
                                          int m0, int n0, int N, int c, int tid)
{
    if (c < NCH) {
        int k0 = c * 32;
        uint32_t stg = smbase + stage * STG_BYTES;
        #pragma unroll
        for (int q = 0; q < 2; q++) {
            int i = tid + q * 256;
            int row = i >> 2, seg = i & 3;
            uint32_t soff = (uint32_t)(row * ROWP + seg * 8) * 2;
            cp16(stg + ASTG_B + soff, A + (size_t)(m0 + row) * HD + k0 + seg * 8, 16);
        }
        #pragma unroll
        for (int q = 0; q < 4; q++) {
            int i = tid + q * 256;
            int row = i >> 2, seg = i & 3;
            uint32_t soff = (uint32_t)(row * ROWP + seg * 8) * 2;
            int n = n0 + row;
            const uint16_t* bsrc = B + (size_t)(n < N ? n : 0) * HD + k0 + seg * 8;
            cp16(stg + BSTG_B + soff, bsrc, n < N ? 16 : 0);
        }
    }
    cp_commit();
}

template<int MODE>
__global__ __launch_bounds__(256, 1) void gemm_mma(const float* __restrict__ bias,
                                                   float* __restrict__ Cext, int N)
{
    extern __shared__ char smraw[];
    const uint32_t smb = s2u(smraw);

    const int tid = threadIdx.x, wid = tid >> 5, lane = tid & 31;
    const int n0 = blockIdx.x * 256;
    const int m0 = blockIdx.y * 128;
    const int mwarp = (wid & 1) * 64;
    const int nwarp = (wid >> 1) * 64;

    const uint16_t* A0 = MODE ? (const uint16_t*)g_act_hi : (const uint16_t*)g_out0_h;
    const uint16_t* B0 = MODE ? (const uint16_t*)g_wout_h : (const uint16_t*)g_wih1_h;

    uint32_t aoff[4], boff[4];
    {
        int arow = (lane & 15);
        int akc  = (lane >> 4) * 8;
        #pragma unroll
        for (int mf = 0; mf < 4; mf++)
            aoff[mf] = (uint32_t)(((mwarp + mf * 16 + arow) * ROWP + akc) * 2);
        int brow = (lane & 7) + ((lane >> 4) & 1) * 8;
        int bkc  = ((lane >> 3) & 1) * 8;
        #pragma unroll
        for (int nf2 = 0; nf2 < 4; nf2++)
            boff[nf2] = (uint32_t)(BSTG_B + ((nwarp + nf2 * 16 + brow) * ROWP + bkc) * 2);
    }

    const int dr = lane >> 2;
    const int dc = (lane & 3) * 2;
    float acc[4][8][4];
    #pragma unroll
    for (int nf = 0; nf < 8; nf++) {
        int n = n0 + nwarp + nf * 8 + dc;
        float b0 = (n < N) ? bias[n] : 0.f;
        float b1 = (n + 1 < N) ? bias[n + 1] : 0.f;
        #pragma unroll
        for (int mf = 0; mf < 4; mf++) {
            acc[mf][nf][0] = b0; acc[mf][nf][1] = b1;
            acc[mf][nf][2] = b0; acc[mf][nf][3] = b1;
        }
    }

    #pragma unroll
    for (int c = 0; c < 3; c++)
        ld_chunkF(smb, c, A0, B0, m0, n0, N, c, tid);

    for (int c = 0; c < NCH; c++) {
        asm volatile("cp.async.wait_group 2;" ::: "memory");
        __syncthreads();
        ld_chunkF(smb, (c + 3) & 3, A0, B0, m0, n0, N, c + 3, tid);

        uint32_t stg = smb + (c & 3) * STG_BYTES;
        #pragma unroll
        for (int kk = 0; kk < 2; kk++) {
            uint32_t af[4][4], bf[4][4];
            #pragma unroll
            for (int mf = 0; mf < 4; mf++) ldm_x4(af[mf], stg + aoff[mf] + kk * 32);
            #pragma unroll
            for (int nf2 = 0; nf2 < 4; nf2++) ldm_x4(bf[nf2], stg + boff[nf2] + kk * 32);
            #pragma unroll
            for (int mf = 0; mf < 4; mf++)
                #pragma unroll
                for (int nf = 0; nf < 8; nf++)
                    mma_f16(acc[mf][nf], af[mf], &bf[nf >> 1][(nf & 1) * 2]);
        }
        __syncthreads();
    }

    #pragma unroll
    for (int mf = 0; mf < 4; mf++) {
        int m = m0 + mwarp + mf * 16 + dr;
        #pragma unroll
        for (int nf = 0; nf < 8; nf++) {
            int n = n0 + nwarp + nf * 8 + dc;
            if (n < N) {
                if (MODE == 0) {
                    *(__half2*)(g_gx1h + (size_t)m * N + n) =
                        __halves2half2(__float2half_rn(acc[mf][nf][0]), __float2half_rn(acc[mf][nf][1]));
                    *(__half2*)(g_gx1h + (size_t)(m + 8) * N + n) =
                        __halves2half2(__float2half_rn(acc[mf][nf][2]), __float2half_rn(acc[mf][nf][3]));
                } else {
                    *(float2*)(Cext + (size_t)m * N + n)       = make_float2(acc[mf][nf][0], acc[mf][nf][1]);
                    *(float2*)(Cext + (size_t)(m + 8) * N + n) = make_float2(acc[mf][nf][2], acc[mf][nf][3]);
                }
            }
        }
    }
}

// ---------------- launch ----------------
extern "C" void kernel_launch(void* const* d_in, const int* in_sizes, int n_in,
                              void* d_out, int out_size)
{
    const float* z         = (const float*)d_in[0];
    const float* W_init    = (const float*)d_in[1];
    const float* b_init    = (const float*)d_in[2];
    const float* embedding = (const float*)d_in[3];
    const float* W_ih0     = (const float*)d_in[4];
    const float* W_hh0     = (const float*)d_in[5];
    const float* b_ih0     = (const float*)d_in[6];
    const float* b_hh0     = (const float*)d_in[7];
    const float* W_ih1     = (const float*)d_in[8];
    const float* W_hh1     = (const float*)d_in[9];
    const float* b_ih1     = (const float*)d_in[10];
    const float* b_hh1     = (const float*)d_in[11];
    const float* ln_g      = (const float*)d_in[12];
    const float* ln_b      = (const float*)d_in[13];
    const float* W_out     = (const float*)d_in[14];
    const float* b_out     = (const float*)d_in[15];
    float* out = (float*)d_out;

    (void)in_sizes; (void)n_in; (void)out_size;

    static bool attr_done = false;
    if (!attr_done) {
        cudaFuncSetAttribute(gru_layer<0>, cudaFuncAttributeMaxDynamicSharedMemorySize, GRU_SMEM);
        cudaFuncSetAttribute(gru_layer<1>, cudaFuncAttributeMaxDynamicSharedMemorySize, GRU_SMEM);
        cudaFuncSetAttribute(gemm_mma<0>, cudaFuncAttributeMaxDynamicSharedMemorySize, GEMM_SMEM);
        cudaFuncSetAttribute(gemm_mma<1>, cudaFuncAttributeMaxDynamicSharedMemorySize, GEMM_SMEM);
        attr_done = true;
    }

    zero_bar<<<1, 32>>>();
    k_h0<<<BATCH, 256>>>(z, W_init, b_init);
    k_gx0<<<3, 256>>>(embedding, W_ih0, b_ih0);
    cvt_half<<<(G3 * HD / 4 + 255) / 256, 256>>>(W_ih1, 0, G3 * HD / 4);
    cvt_half<<<(PD * HD / 4 + 255) / 256, 256>>>(W_out, 1, PD * HD / 4);

    // layer 0 recurrence (tensor-core GRU, writes fp16 out0 + bf16 h planes)
    gru_layer<0><<<dim3(8, 16), 256, GRU_SMEM>>>(W_hh0, b_hh0);

    // gx1 = out0 @ W_ih1^T + b_ih1  (32768 x 768), fp16, stores fp16
    gemm_mma<0><<<dim3(G3 / 256, BT / 128), 256, GEMM_SMEM>>>(b_ih1, nullptr, G3);

    // layer 1 recurrence (writes g_act fp32 + bf16 h planes)
    gru_layer<1><<<dim3(8, 16), 256, GRU_SMEM>>>(W_hh1, b_hh1);

    // LN + ELU -> fp16
    ln_elu<<<BT / 8, 256>>>(ln_g, ln_b);

    // logits = act @ W_out^T + b_out  (32768 x 10000), fp16, stores fp32
    gemm_mma<1><<<dim3((PD + 255) / 256, BT / 128), 256, GEMM_SMEM>>>(b_out, out, PD);
}